// round 1
// baseline (speedup 1.0000x reference)
#include <cuda_runtime.h>
#include <cuda_bf16.h>
#include <math.h>

// Problem constants
#define BZ 4
#define NN 3136
#define CC 256
#define HH 8
#define HD 32
#define PL 196
#define IMH 56
#define IMW 56
#define KTAB 2048

// ---------------- scratch (device globals; no allocation allowed) -------------
__device__ float g_q   [BZ * NN * CC];      // q GEMM out (b,n,c)
__device__ float g_qn  [BZ * HH * NN * HD]; // q_norm   (b,h,n,d)
__device__ float g_qs  [BZ * HH * NN * HD]; // q_scaled (b,h,n,d)
__device__ float g_kv  [BZ * NN * 512];     // kv GEMM out; k part normalized in place
__device__ float g_xsr [BZ * NN * CC];      // gelu(sr(x)) (b,n,c)
__device__ float g_xpl [BZ * PL * CC];      // pooled + layernormed
__device__ float g_kvp [BZ * PL * 512];     // pooled kv; k part normalized in place
__device__ float g_tab [KTAB * HH];         // CPB table output
__device__ float g_att [BZ * NN * CC];      // attention output (b,n,c)

// ---------------- generic fp32 GEMM: C[M,N] = A[M,K] @ W[N,K]^T + bias --------
// act: 0 = none, 1 = exact GELU
__global__ __launch_bounds__(256) void gemm_kernel(
    const float* __restrict__ A, const float* __restrict__ W,
    const float* __restrict__ bias, float* __restrict__ C,
    int M, int N, int K, int act)
{
    __shared__ __align__(16) float As[16][68];
    __shared__ __align__(16) float Bs[16][68];

    const int tx = threadIdx.x & 15;   // output col quad
    const int ty = threadIdx.x >> 4;   // output row quad
    const int m0 = blockIdx.y * 64;
    const int n0 = blockIdx.x * 64;

    const int lc  = threadIdx.x & 15;  // k within chunk
    const int lr4 = threadIdx.x >> 4;  // row group (0..15)

    float acc[4][4] = {};

    for (int k0 = 0; k0 < K; k0 += 16) {
        #pragma unroll
        for (int s = 0; s < 4; s++) {
            int r = lr4 * 4 + s;
            int mrow = m0 + r;
            As[lc][r] = (mrow < M) ? A[(size_t)mrow * K + k0 + lc] : 0.f;
            Bs[lc][r] = W[(size_t)(n0 + r) * K + k0 + lc];
        }
        __syncthreads();
        #pragma unroll
        for (int kk = 0; kk < 16; kk++) {
            float4 a4 = *(const float4*)&As[kk][ty * 4];
            float4 b4 = *(const float4*)&Bs[kk][tx * 4];
            float av[4] = {a4.x, a4.y, a4.z, a4.w};
            float bv[4] = {b4.x, b4.y, b4.z, b4.w};
            #pragma unroll
            for (int i = 0; i < 4; i++)
                #pragma unroll
                for (int j = 0; j < 4; j++)
                    acc[i][j] = fmaf(av[i], bv[j], acc[i][j]);
        }
        __syncthreads();
    }

    #pragma unroll
    for (int i = 0; i < 4; i++) {
        int m = m0 + ty * 4 + i;
        if (m >= M) continue;
        #pragma unroll
        for (int j = 0; j < 4; j++) {
            int nn = n0 + tx * 4 + j;
            float v = acc[i][j] + bias[nn];
            if (act == 1) v = 0.5f * v * (1.f + erff(v * 0.70710678118654752f));
            C[(size_t)m * N + nn] = v;
        }
    }
}

// ---------------- q post: l2-normalize per (b,h,n), add embedding, scale ------
__global__ __launch_bounds__(256) void qpost_kernel(
    const float* __restrict__ q, const float* __restrict__ qe,
    const float* __restrict__ temp, const float* __restrict__ sls,
    float* __restrict__ qn, float* __restrict__ qs)
{
    int idx = blockIdx.x * blockDim.x + threadIdx.x;
    if (idx >= BZ * NN * HH) return;
    int h  = idx & 7;
    int bn = idx >> 3;
    int n  = bn % NN;
    int b  = bn / NN;

    const float* src = q + (size_t)bn * CC + h * HD;
    float v[HD];
    float ss = 0.f;
    #pragma unroll
    for (int d4 = 0; d4 < HD / 4; d4++) {
        float4 t = ((const float4*)src)[d4];
        v[d4*4+0]=t.x; v[d4*4+1]=t.y; v[d4*4+2]=t.z; v[d4*4+3]=t.w;
        ss += t.x*t.x + t.y*t.y + t.z*t.z + t.w*t.w;
    }
    float inv = 1.f / fmaxf(sqrtf(ss), 1e-12f);
    float sp  = log1pf(expf(temp[h]));
    float scale = sp * sls[n];

    size_t dst = (((size_t)(b * HH + h)) * NN + n) * HD;
    #pragma unroll
    for (int d = 0; d < HD; d++) {
        float nv = v[d] * inv;
        qn[dst + d] = nv;
        qs[dst + d] = (nv + qe[h * HD + d]) * scale;
    }
}

// ---------------- normalize k part of kv rows (stride 512) in place ----------
__global__ __launch_bounds__(256) void knorm_kernel(float* __restrict__ kv, int rows)
{
    int idx = blockIdx.x * blockDim.x + threadIdx.x;
    if (idx >= rows * HH) return;
    int h = idx & 7;
    int r = idx >> 3;
    float* p = kv + (size_t)r * 512 + h * HD;
    float ss = 0.f;
    float v[HD];
    #pragma unroll
    for (int d4 = 0; d4 < HD / 4; d4++) {
        float4 t = ((const float4*)p)[d4];
        v[d4*4+0]=t.x; v[d4*4+1]=t.y; v[d4*4+2]=t.z; v[d4*4+3]=t.w;
        ss += t.x*t.x + t.y*t.y + t.z*t.z + t.w*t.w;
    }
    float inv = 1.f / fmaxf(sqrtf(ss), 1e-12f);
    #pragma unroll
    for (int d = 0; d < HD; d++) p[d] = v[d] * inv;
}

// ---------------- 4x4 average pool + layernorm over C ------------------------
__global__ __launch_bounds__(256) void pool_ln_kernel(
    const float* __restrict__ xsr, const float* __restrict__ gam,
    const float* __restrict__ bet, float* __restrict__ xpool)
{
    int bp = blockIdx.x;          // b*196 + p
    int b = bp / PL, p = bp % PL;
    int ph = p / 14, pw = p % 14;
    int c = threadIdx.x;

    float s = 0.f;
    #pragma unroll
    for (int i = 0; i < 4; i++)
        #pragma unroll
        for (int j = 0; j < 4; j++) {
            int n = (ph * 4 + i) * IMW + pw * 4 + j;
            s += xsr[((size_t)b * NN + n) * CC + c];
        }
    s *= (1.f / 16.f);

    __shared__ float r1[256], r2[256];
    r1[c] = s;
    r2[c] = s * s;
    __syncthreads();
    for (int st = 128; st > 0; st >>= 1) {
        if (c < st) { r1[c] += r1[c + st]; r2[c] += r2[c + st]; }
        __syncthreads();
    }
    float mean = r1[0] * (1.f / 256.f);
    float var  = r2[0] * (1.f / 256.f) - mean * mean;
    float invs = rsqrtf(var + 1e-5f);
    xpool[(size_t)bp * CC + c] = (s - mean) * invs * gam[c] + bet[c];
}

// ---------------- CPB table: tab[t,h] = relu(rct[t]@w1^T+b1) @ w2^T + b2 ------
__global__ __launch_bounds__(256) void tab_kernel(
    const float* __restrict__ rct, const float* __restrict__ w1,
    const float* __restrict__ b1, const float* __restrict__ w2,
    const float* __restrict__ b2, float* __restrict__ tab)
{
    int t = blockIdx.x;
    __shared__ float sh[512];
    float c0 = rct[t * 2], c1 = rct[t * 2 + 1];
    for (int j = threadIdx.x; j < 512; j += 256)
        sh[j] = fmaxf(0.f, c0 * w1[j * 2] + c1 * w1[j * 2 + 1] + b1[j]);
    __syncthreads();
    int w = threadIdx.x >> 5, lane = threadIdx.x & 31;  // warp w handles head w
    float s = 0.f;
    for (int j = lane; j < 512; j += 32) s += sh[j] * w2[w * 512 + j];
    #pragma unroll
    for (int o = 16; o > 0; o >>= 1) s += __shfl_xor_sync(0xffffffffu, s, o);
    if (lane == 0) tab[t * 8 + w] = s + b2[w];
}

// ---------------- fused attention: local(9) + pooled(196) softmax + outputs ---
// grid: (NN/8, HH, BZ); block: 256 threads, warp w handles row n0+w
__global__ __launch_bounds__(256) void attn_kernel(
    const float* __restrict__ qs, const float* __restrict__ qn,
    const float* __restrict__ kv, const float* __restrict__ kvp,
    const float* __restrict__ tab, const int* __restrict__ rpi,
    const float* __restrict__ rpb, const float* __restrict__ ltok,
    const float* __restrict__ lbias, float* __restrict__ out)
{
    extern __shared__ float sm[];
    float* sK  = sm;                 // 196*33
    float* sV  = sK + PL * 33;       // 196*33
    float* sP  = sV + PL * 33;       // 8*224
    float* sQs = sP + 8 * 224;       // 8*32
    float* sQn = sQs + 256;          // 8*32

    const int b = blockIdx.z, h = blockIdx.y;
    const int n0 = blockIdx.x * 8;
    const int tid = threadIdx.x;

    // stage pooled K/V for this (b,h)
    for (int i = tid; i < PL * 32; i += 256) {
        int m = i >> 5, d = i & 31;
        const float* row = kvp + ((size_t)(b * PL + m)) * 512 + h * HD;
        sK[m * 33 + d] = row[d];
        sV[m * 33 + d] = row[256 + d];
    }
    // stage q rows
    {
        int i = tid >> 5, d = tid & 31;
        size_t base = (((size_t)(b * HH + h)) * NN + n0 + i) * HD + d;
        sQs[i * 32 + d] = qs[base];
        sQn[i * 32 + d] = qn[base];
    }
    __syncthreads();

    const int w = tid >> 5, lane = tid & 31;
    const int n = n0 + w;
    const int r = n / IMW, cc = n % IMW;
    float* P = sP + w * 224;
    const float* Q  = sQs + w * 32;
    const float* Qn = sQn + w * 32;

    // local logits (lanes 0..8)
    if (lane < 9) {
        int di = lane / 3 - 1, dj = lane % 3 - 1;
        int rr = r + di, c2 = cc + dj;
        bool valid = (rr >= 0 && rr < IMH && c2 >= 0 && c2 < IMW);
        float a;
        if (valid) {
            int nb = rr * IMW + c2;
            const float4* kr = (const float4*)(kv + ((size_t)(b * NN + nb)) * 512 + h * HD);
            float s2 = 0.f;
            #pragma unroll
            for (int d4 = 0; d4 < 8; d4++) {
                float4 t = kr[d4];
                s2 += Q[d4*4+0]*t.x + Q[d4*4+1]*t.y + Q[d4*4+2]*t.z + Q[d4*4+3]*t.w;
            }
            a = s2 + rpb[h * 9 + lane];
        } else {
            a = __int_as_float(0xff800000);  // -inf
        }
        P[lane] = a;
    }

    // pooled logits
    const int* rp = rpi + (size_t)n * PL;
    for (int m = lane; m < PL; m += 32) {
        const float* kr = sK + m * 33;
        float s2 = 0.f;
        #pragma unroll
        for (int d = 0; d < 32; d++) s2 += Q[d] * kr[d];
        P[9 + m] = s2 + tab[rp[m] * 8 + h];
    }
    __syncwarp();

    // softmax over 205
    float mx = -3.4e38f;
    for (int j = lane; j < 205; j += 32) mx = fmaxf(mx, P[j]);
    #pragma unroll
    for (int o = 16; o > 0; o >>= 1) mx = fmaxf(mx, __shfl_xor_sync(0xffffffffu, mx, o));
    float sum = 0.f;
    for (int j = lane; j < 205; j += 32) {
        float e = __expf(P[j] - mx);
        P[j] = e;
        sum += e;
    }
    #pragma unroll
    for (int o = 16; o > 0; o >>= 1) sum += __shfl_xor_sync(0xffffffffu, sum, o);
    float inv = 1.f / sum;
    for (int j = lane; j < 205; j += 32) P[j] *= inv;
    __syncwarp();

    // w_loc = q_norm @ learnable_tokens + learnable_bias + a_loc (lanes 0..8)
    if (lane < 9) {
        float s2 = 0.f;
        #pragma unroll
        for (int d = 0; d < 32; d++) s2 += Qn[d] * ltok[(h * 32 + d) * 9 + lane];
        P[lane] = s2 + lbias[h * 9 + lane] + P[lane];
    }
    __syncwarp();

    // outputs: lane = head-dim d
    float acc = 0.f;
    #pragma unroll
    for (int l2 = 0; l2 < 9; l2++) {
        int di = l2 / 3 - 1, dj = l2 % 3 - 1;
        int rr = r + di, c2 = cc + dj;
        if (rr >= 0 && rr < IMH && c2 >= 0 && c2 < IMW) {
            int nb = rr * IMW + c2;
            acc += P[l2] * kv[((size_t)(b * NN + nb)) * 512 + 256 + h * HD + lane];
        }
    }
    for (int m = 0; m < PL; m++)
        acc += P[9 + m] * sV[m * 33 + lane];

    out[((size_t)(b * NN) + n) * CC + h * HD + lane] = acc;
}

// -----------------------------------------------------------------------------
extern "C" void kernel_launch(void* const* d_in, const int* in_sizes, int n_in,
                              void* d_out, int out_size)
{
    const float* x      = (const float*)d_in[0];
    const int*   rpi    = (const int*)  d_in[3];
    const float* rct    = (const float*)d_in[4];
    const float* sls    = (const float*)d_in[5];
    const float* q_w    = (const float*)d_in[7];
    const float* q_b    = (const float*)d_in[8];
    const float* kv_w   = (const float*)d_in[9];
    const float* kv_b   = (const float*)d_in[10];
    const float* sr_w   = (const float*)d_in[11];
    const float* sr_b   = (const float*)d_in[12];
    const float* norm_g = (const float*)d_in[13];
    const float* norm_b = (const float*)d_in[14];
    const float* cpb1_w = (const float*)d_in[15];
    const float* cpb1_b = (const float*)d_in[16];
    const float* cpb2_w = (const float*)d_in[17];
    const float* cpb2_b = (const float*)d_in[18];
    const float* temp   = (const float*)d_in[19];
    const float* qe     = (const float*)d_in[20];
    const float* rpb    = (const float*)d_in[21];
    const float* ltok   = (const float*)d_in[22];
    const float* lbias  = (const float*)d_in[23];
    const float* proj_w = (const float*)d_in[24];
    const float* proj_b = (const float*)d_in[25];
    float* out = (float*)d_out;

    float *p_q, *p_qn, *p_qs, *p_kv, *p_xsr, *p_xpl, *p_kvp, *p_tab, *p_att;
    cudaGetSymbolAddress((void**)&p_q,   g_q);
    cudaGetSymbolAddress((void**)&p_qn,  g_qn);
    cudaGetSymbolAddress((void**)&p_qs,  g_qs);
    cudaGetSymbolAddress((void**)&p_kv,  g_kv);
    cudaGetSymbolAddress((void**)&p_xsr, g_xsr);
    cudaGetSymbolAddress((void**)&p_xpl, g_xpl);
    cudaGetSymbolAddress((void**)&p_kvp, g_kvp);
    cudaGetSymbolAddress((void**)&p_tab, g_tab);
    cudaGetSymbolAddress((void**)&p_att, g_att);

    const int M = BZ * NN;  // 12544

    // main GEMMs
    gemm_kernel<<<dim3(4, 196), 256>>>(x, q_w,  q_b,  p_q,   M, 256, 256, 0);
    gemm_kernel<<<dim3(8, 196), 256>>>(x, kv_w, kv_b, p_kv,  M, 512, 256, 0);
    gemm_kernel<<<dim3(4, 196), 256>>>(x, sr_w, sr_b, p_xsr, M, 256, 256, 1);

    // q post-processing + k normalization
    qpost_kernel<<<(BZ * NN * HH + 255) / 256, 256>>>(p_q, qe, temp, sls, p_qn, p_qs);
    knorm_kernel<<<(BZ * NN * HH + 255) / 256, 256>>>(p_kv, BZ * NN);

    // pooled path
    pool_ln_kernel<<<BZ * PL, 256>>>(p_xsr, norm_g, norm_b, p_xpl);
    gemm_kernel<<<dim3(8, 13), 256>>>(p_xpl, kv_w, kv_b, p_kvp, BZ * PL, 512, 256, 0);
    knorm_kernel<<<(BZ * PL * HH + 255) / 256, 256>>>(p_kvp, BZ * PL);

    // CPB bias table
    tab_kernel<<<KTAB, 256>>>(rct, cpb1_w, cpb1_b, cpb2_w, cpb2_b, p_tab);

    // fused attention
    size_t shmem = (size_t)(PL * 33 * 2 + 8 * 224 + 512) * sizeof(float);  // 60960 B
    cudaFuncSetAttribute(attn_kernel, cudaFuncAttributeMaxDynamicSharedMemorySize, 65536);
    attn_kernel<<<dim3(NN / 8, HH, BZ), 256, shmem>>>(
        p_qs, p_qn, p_kv, p_kvp, p_tab, rpi, rpb, ltok, lbias, p_att);

    // output projection
    gemm_kernel<<<dim3(4, 196), 256>>>(p_att, proj_w, proj_b, out, M, 256, 256, 0);
}

// round 2
// speedup vs baseline: 1.2496x; 1.2496x over previous
#include <cuda_runtime.h>
#include <cuda_bf16.h>
#include <math.h>

// Problem constants
#define BZ 4
#define NN 3136
#define CC 256
#define HH 8
#define HD 32
#define PL 196
#define IMH 56
#define IMW 56
#define KTAB 2048

// ---------------- scratch (device globals; no allocation allowed) -------------
__device__ float g_q   [BZ * NN * CC];      // q GEMM out (b,n,c)
__device__ float g_kv  [BZ * NN * 512];     // kv GEMM out; k half normalized in epilogue
__device__ float g_xsr [BZ * NN * CC];      // gelu(sr(x)) (b,n,c)
__device__ float g_xpl [BZ * PL * CC];      // pooled + layernormed
__device__ float g_kvp [BZ * PL * 512];     // pooled kv; k half normalized in epilogue
__device__ float g_tab [KTAB * HH];         // CPB table output
__device__ float g_att [BZ * NN * CC];      // attention output (b,n,c)

// ---------------- packed f32x2 helpers ----------------------------------------
__device__ __forceinline__ unsigned long long pk2(float x) {
    unsigned long long r;
    asm("mov.b64 %0, {%1, %1};" : "=l"(r) : "f"(x));
    return r;
}
__device__ __forceinline__ void ffma2(unsigned long long& d, unsigned long long a,
                                      unsigned long long b) {
    asm("fma.rn.f32x2 %0, %1, %2, %0;" : "+l"(d) : "l"(a), "l"(b));
}
__device__ __forceinline__ float2 upk(unsigned long long v) {
    float2 f;
    asm("mov.b64 {%0, %1}, %2;" : "=f"(f.x), "=f"(f.y) : "l"(v));
    return f;
}

// ---------------- fp32 GEMM (FFMA2): C[M,N] = A[M,K] @ W[N,K]^T + bias --------
// act: 0 = none, 1 = exact GELU, 2 = l2-normalize 32-col head groups (k half,
//      applied when the tile lies in cols < 256)
__global__ __launch_bounds__(256) void gemm_kernel(
    const float* __restrict__ A, const float* __restrict__ W,
    const float* __restrict__ bias, float* __restrict__ C,
    int M, int N, int K, int act)
{
    __shared__ __align__(16) float As[16][68];
    __shared__ __align__(16) float Bs[16][68];

    const int tid = threadIdx.x;
    const int tx = tid & 15;           // output col quad
    const int ty = tid >> 4;           // output row quad
    const int m0 = blockIdx.y * 64;
    const int n0 = blockIdx.x * 64;

    // loader mapping: each thread loads one float4 of A and one of W per chunk
    const int lrow = tid >> 2;         // 0..63
    const int lkq  = (tid & 3) * 4;    // k offset 0,4,8,12

    unsigned long long acc[4][2];      // [row][col-pair] packed f32x2
    #pragma unroll
    for (int i = 0; i < 4; i++) { acc[i][0] = 0ull; acc[i][1] = 0ull; }

    for (int k0 = 0; k0 < K; k0 += 16) {
        int mrow = m0 + lrow;
        float4 av = make_float4(0.f, 0.f, 0.f, 0.f);
        if (mrow < M) av = *(const float4*)&A[(size_t)mrow * K + k0 + lkq];
        float4 wv = *(const float4*)&W[(size_t)(n0 + lrow) * K + k0 + lkq];
        As[lkq + 0][lrow] = av.x; As[lkq + 1][lrow] = av.y;
        As[lkq + 2][lrow] = av.z; As[lkq + 3][lrow] = av.w;
        Bs[lkq + 0][lrow] = wv.x; Bs[lkq + 1][lrow] = wv.y;
        Bs[lkq + 2][lrow] = wv.z; Bs[lkq + 3][lrow] = wv.w;
        __syncthreads();

        #pragma unroll
        for (int kk = 0; kk < 16; kk++) {
            float4 a4 = *(const float4*)&As[kk][ty * 4];
            ulonglong2 b2 = *(const ulonglong2*)&Bs[kk][tx * 4];
            unsigned long long a0 = pk2(a4.x), a1 = pk2(a4.y),
                               a2 = pk2(a4.z), a3 = pk2(a4.w);
            ffma2(acc[0][0], a0, b2.x); ffma2(acc[0][1], a0, b2.y);
            ffma2(acc[1][0], a1, b2.x); ffma2(acc[1][1], a1, b2.y);
            ffma2(acc[2][0], a2, b2.x); ffma2(acc[2][1], a2, b2.y);
            ffma2(acc[3][0], a3, b2.x); ffma2(acc[3][1], a3, b2.y);
        }
        __syncthreads();
    }

    // epilogue
    float v[4][4];
    float b0 = bias[n0 + tx * 4 + 0], b1 = bias[n0 + tx * 4 + 1];
    float b2f = bias[n0 + tx * 4 + 2], b3 = bias[n0 + tx * 4 + 3];
    #pragma unroll
    for (int i = 0; i < 4; i++) {
        float2 p0 = upk(acc[i][0]);
        float2 p1 = upk(acc[i][1]);
        v[i][0] = p0.x + b0; v[i][1] = p0.y + b1;
        v[i][2] = p1.x + b2f; v[i][3] = p1.y + b3;
    }

    if (act == 2 && n0 < 256) {
        // l2-normalize each 32-col head group per row; group = 8 adjacent lanes
        #pragma unroll
        for (int i = 0; i < 4; i++) {
            float ss = v[i][0]*v[i][0] + v[i][1]*v[i][1]
                     + v[i][2]*v[i][2] + v[i][3]*v[i][3];
            ss += __shfl_xor_sync(0xffffffffu, ss, 1);
            ss += __shfl_xor_sync(0xffffffffu, ss, 2);
            ss += __shfl_xor_sync(0xffffffffu, ss, 4);
            float inv = 1.f / fmaxf(sqrtf(ss), 1e-12f);
            v[i][0] *= inv; v[i][1] *= inv; v[i][2] *= inv; v[i][3] *= inv;
        }
    } else if (act == 1) {
        #pragma unroll
        for (int i = 0; i < 4; i++)
            #pragma unroll
            for (int j = 0; j < 4; j++)
                v[i][j] = 0.5f * v[i][j] *
                          (1.f + erff(v[i][j] * 0.70710678118654752f));
    }

    #pragma unroll
    for (int i = 0; i < 4; i++) {
        int m = m0 + ty * 4 + i;
        if (m >= M) continue;
        float4 o = make_float4(v[i][0], v[i][1], v[i][2], v[i][3]);
        *(float4*)&C[(size_t)m * N + n0 + tx * 4] = o;
    }
}

// ---------------- 4x4 average pool + layernorm over C ------------------------
__global__ __launch_bounds__(256) void pool_ln_kernel(
    const float* __restrict__ xsr, const float* __restrict__ gam,
    const float* __restrict__ bet, float* __restrict__ xpool)
{
    int bp = blockIdx.x;          // b*196 + p
    int b = bp / PL, p = bp % PL;
    int ph = p / 14, pw = p % 14;
    int c = threadIdx.x;

    float s = 0.f;
    #pragma unroll
    for (int i = 0; i < 4; i++)
        #pragma unroll
        for (int j = 0; j < 4; j++) {
            int n = (ph * 4 + i) * IMW + pw * 4 + j;
            s += xsr[((size_t)b * NN + n) * CC + c];
        }
    s *= (1.f / 16.f);

    __shared__ float r1[256], r2[256];
    r1[c] = s;
    r2[c] = s * s;
    __syncthreads();
    for (int st = 128; st > 0; st >>= 1) {
        if (c < st) { r1[c] += r1[c + st]; r2[c] += r2[c + st]; }
        __syncthreads();
    }
    float mean = r1[0] * (1.f / 256.f);
    float var  = r2[0] * (1.f / 256.f) - mean * mean;
    float invs = rsqrtf(var + 1e-5f);
    xpool[(size_t)bp * CC + c] = (s - mean) * invs * gam[c] + bet[c];
}

// ---------------- CPB table: tab[t,h] = relu(rct[t]@w1^T+b1) @ w2^T + b2 ------
__global__ __launch_bounds__(256) void tab_kernel(
    const float* __restrict__ rct, const float* __restrict__ w1,
    const float* __restrict__ b1, const float* __restrict__ w2,
    const float* __restrict__ b2, float* __restrict__ tab)
{
    int t = blockIdx.x;
    __shared__ float sh[512];
    float c0 = rct[t * 2], c1 = rct[t * 2 + 1];
    for (int j = threadIdx.x; j < 512; j += 256)
        sh[j] = fmaxf(0.f, c0 * w1[j * 2] + c1 * w1[j * 2 + 1] + b1[j]);
    __syncthreads();
    int w = threadIdx.x >> 5, lane = threadIdx.x & 31;  // warp w handles head w
    float s = 0.f;
    for (int j = lane; j < 512; j += 32) s += sh[j] * w2[w * 512 + j];
    #pragma unroll
    for (int o = 16; o > 0; o >>= 1) s += __shfl_xor_sync(0xffffffffu, s, o);
    if (lane == 0) tab[t * 8 + w] = s + b2[w];
}

// ---------------- fused attention: q-norm + local(9) + pooled(196) softmax ----
// grid: (NN/16, HH, BZ); block: 512 threads, warp w handles row n0+w
__global__ __launch_bounds__(512) void attn_kernel(
    const float* __restrict__ q, const float* __restrict__ qe,
    const float* __restrict__ temp, const float* __restrict__ sls,
    const float* __restrict__ kv, const float* __restrict__ kvp,
    const float* __restrict__ tab, const int* __restrict__ rpi,
    const float* __restrict__ rpb, const float* __restrict__ ltok,
    const float* __restrict__ lbias, float* __restrict__ out)
{
    extern __shared__ float sm[];
    float* sK  = sm;                 // 196*33
    float* sV  = sK + PL * 33;       // 196*33
    float* sP  = sV + PL * 33;       // 16*224
    float* sQs = sP + 16 * 224;      // 16*32
    float* sQn = sQs + 512;          // 16*32

    const int b = blockIdx.z, h = blockIdx.y;
    const int n0 = blockIdx.x * 16;
    const int tid = threadIdx.x;

    // stage pooled K/V for this (b,h) with float4 loads
    for (int i = tid; i < PL * 8; i += 512) {
        int m = i >> 3, q4 = i & 7;
        const float* rowb = kvp + ((size_t)(b * PL + m)) * 512 + h * HD;
        float4 kk4 = *(const float4*)(rowb + q4 * 4);
        float4 vv4 = *(const float4*)(rowb + 256 + q4 * 4);
        int base = m * 33 + q4 * 4;
        sK[base + 0] = kk4.x; sK[base + 1] = kk4.y;
        sK[base + 2] = kk4.z; sK[base + 3] = kk4.w;
        sV[base + 0] = vv4.x; sV[base + 1] = vv4.y;
        sV[base + 2] = vv4.z; sV[base + 3] = vv4.w;
    }

    const int w = tid >> 5, lane = tid & 31;
    const int n = n0 + w;

    // fused q post-processing: l2-norm + embedding + temperature/seq scaling
    {
        float val = q[((size_t)(b * NN + n)) * CC + h * HD + lane];
        float ss = val * val;
        #pragma unroll
        for (int o = 16; o > 0; o >>= 1) ss += __shfl_xor_sync(0xffffffffu, ss, o);
        float inv = 1.f / fmaxf(sqrtf(ss), 1e-12f);
        float qnv = val * inv;
        float sp = log1pf(expf(temp[h]));
        float qsv = (qnv + qe[h * HD + lane]) * sp * sls[n];
        sQs[w * 32 + lane] = qsv;
        sQn[w * 32 + lane] = qnv;
    }
    __syncthreads();

    const int r = n / IMW, cc = n % IMW;
    float* P = sP + w * 224;
    const float* Q  = sQs + w * 32;
    const float* Qn = sQn + w * 32;

    // local logits (lanes 0..8)
    if (lane < 9) {
        int di = lane / 3 - 1, dj = lane % 3 - 1;
        int rr = r + di, c2 = cc + dj;
        bool valid = (rr >= 0 && rr < IMH && c2 >= 0 && c2 < IMW);
        float a;
        if (valid) {
            int nb = rr * IMW + c2;
            const float4* kr = (const float4*)(kv + ((size_t)(b * NN + nb)) * 512 + h * HD);
            float s2 = 0.f;
            #pragma unroll
            for (int d4 = 0; d4 < 8; d4++) {
                float4 t = kr[d4];
                s2 += Q[d4*4+0]*t.x + Q[d4*4+1]*t.y + Q[d4*4+2]*t.z + Q[d4*4+3]*t.w;
            }
            a = s2 + rpb[h * 9 + lane];
        } else {
            a = __int_as_float(0xff800000);  // -inf
        }
        P[lane] = a;
    }

    // pooled logits
    const int* rp = rpi + (size_t)n * PL;
    for (int m = lane; m < PL; m += 32) {
        const float* kr = sK + m * 33;
        float s2 = 0.f;
        #pragma unroll
        for (int d = 0; d < 32; d++) s2 += Q[d] * kr[d];
        P[9 + m] = s2 + tab[rp[m] * 8 + h];
    }
    __syncwarp();

    // softmax over 205
    float mx = -3.4e38f;
    for (int j = lane; j < 205; j += 32) mx = fmaxf(mx, P[j]);
    #pragma unroll
    for (int o = 16; o > 0; o >>= 1) mx = fmaxf(mx, __shfl_xor_sync(0xffffffffu, mx, o));
    float sum = 0.f;
    for (int j = lane; j < 205; j += 32) {
        float e = __expf(P[j] - mx);
        P[j] = e;
        sum += e;
    }
    #pragma unroll
    for (int o = 16; o > 0; o >>= 1) sum += __shfl_xor_sync(0xffffffffu, sum, o);
    float inv = 1.f / sum;
    for (int j = lane; j < 205; j += 32) P[j] *= inv;
    __syncwarp();

    // w_loc = q_norm @ learnable_tokens + learnable_bias + a_loc (lanes 0..8)
    if (lane < 9) {
        float s2 = 0.f;
        #pragma unroll
        for (int d = 0; d < 32; d++) s2 += Qn[d] * ltok[(h * 32 + d) * 9 + lane];
        P[lane] = s2 + lbias[h * 9 + lane] + P[lane];
    }
    __syncwarp();

    // outputs: lane = head-dim d
    float acc = 0.f;
    #pragma unroll
    for (int l2 = 0; l2 < 9; l2++) {
        int di = l2 / 3 - 1, dj = l2 % 3 - 1;
        int rr = r + di, c2 = cc + dj;
        if (rr >= 0 && rr < IMH && c2 >= 0 && c2 < IMW) {
            int nb = rr * IMW + c2;
            acc += P[l2] * kv[((size_t)(b * NN + nb)) * 512 + 256 + h * HD + lane];
        }
    }
    for (int m = 0; m < PL; m++)
        acc += P[9 + m] * sV[m * 33 + lane];

    out[((size_t)(b * NN) + n) * CC + h * HD + lane] = acc;
}

// -----------------------------------------------------------------------------
extern "C" void kernel_launch(void* const* d_in, const int* in_sizes, int n_in,
                              void* d_out, int out_size)
{
    const float* x      = (const float*)d_in[0];
    const int*   rpi    = (const int*)  d_in[3];
    const float* rct    = (const float*)d_in[4];
    const float* sls    = (const float*)d_in[5];
    const float* q_w    = (const float*)d_in[7];
    const float* q_b    = (const float*)d_in[8];
    const float* kv_w   = (const float*)d_in[9];
    const float* kv_b   = (const float*)d_in[10];
    const float* sr_w   = (const float*)d_in[11];
    const float* sr_b   = (const float*)d_in[12];
    const float* norm_g = (const float*)d_in[13];
    const float* norm_b = (const float*)d_in[14];
    const float* cpb1_w = (const float*)d_in[15];
    const float* cpb1_b = (const float*)d_in[16];
    const float* cpb2_w = (const float*)d_in[17];
    const float* cpb2_b = (const float*)d_in[18];
    const float* temp   = (const float*)d_in[19];
    const float* qe     = (const float*)d_in[20];
    const float* rpb    = (const float*)d_in[21];
    const float* ltok   = (const float*)d_in[22];
    const float* lbias  = (const float*)d_in[23];
    const float* proj_w = (const float*)d_in[24];
    const float* proj_b = (const float*)d_in[25];
    float* out = (float*)d_out;

    float *p_q, *p_kv, *p_xsr, *p_xpl, *p_kvp, *p_tab, *p_att;
    cudaGetSymbolAddress((void**)&p_q,   g_q);
    cudaGetSymbolAddress((void**)&p_kv,  g_kv);
    cudaGetSymbolAddress((void**)&p_xsr, g_xsr);
    cudaGetSymbolAddress((void**)&p_xpl, g_xpl);
    cudaGetSymbolAddress((void**)&p_kvp, g_kvp);
    cudaGetSymbolAddress((void**)&p_tab, g_tab);
    cudaGetSymbolAddress((void**)&p_att, g_att);

    const int M = BZ * NN;  // 12544

    // main GEMMs (kv: k-half l2-norm fused in epilogue; sr: GELU fused)
    gemm_kernel<<<dim3(4, 196), 256>>>(x, q_w,  q_b,  p_q,   M, 256, 256, 0);
    gemm_kernel<<<dim3(8, 196), 256>>>(x, kv_w, kv_b, p_kv,  M, 512, 256, 2);
    gemm_kernel<<<dim3(4, 196), 256>>>(x, sr_w, sr_b, p_xsr, M, 256, 256, 1);

    // pooled path
    pool_ln_kernel<<<BZ * PL, 256>>>(p_xsr, norm_g, norm_b, p_xpl);
    gemm_kernel<<<dim3(8, 13), 256>>>(p_xpl, kv_w, kv_b, p_kvp, BZ * PL, 512, 256, 2);

    // CPB bias table
    tab_kernel<<<KTAB, 256>>>(rct, cpb1_w, cpb1_b, cpb2_w, cpb2_b, p_tab);

    // fused attention (q-norm fused into staging)
    size_t shmem = (size_t)(PL * 33 * 2 + 16 * 224 + 1024) * sizeof(float);  // 70176 B
    cudaFuncSetAttribute(attn_kernel, cudaFuncAttributeMaxDynamicSharedMemorySize, 72000);
    attn_kernel<<<dim3(NN / 16, HH, BZ), 512, shmem>>>(
        p_q, qe, temp, sls, p_kv, p_kvp, p_tab, rpi, rpb, ltok, lbias, p_att);

    // output projection
    gemm_kernel<<<dim3(4, 196), 256>>>(p_att, proj_w, proj_b, out, M, 256, 256, 0);
}

// round 4
// speedup vs baseline: 1.2927x; 1.0345x over previous
#include <cuda_runtime.h>
#include <cuda_bf16.h>
#include <math.h>
#include <stdint.h>

// Problem constants
#define BZ 4
#define NN 3136
#define CC 256
#define HH 8
#define HD 32
#define PL 196
#define IMH 56
#define IMW 56
#define KTAB 2048

// ---------------- scratch (device globals; no allocation allowed) -------------
__device__ float g_q   [BZ * NN * CC];      // q GEMM out (b,n,c)
__device__ float g_kv  [BZ * NN * 512];     // kv GEMM out; k half normalized in epilogue
__device__ float g_xsr [BZ * NN * CC];      // gelu(sr(x)) (b,n,c)
__device__ float g_xpl [BZ * PL * CC];      // pooled + layernormed
__device__ float g_kvp [BZ * PL * 512];     // pooled kv; k half normalized in epilogue
__device__ float g_tab [KTAB * HH];         // CPB table output
__device__ float g_att [BZ * NN * CC];      // attention output (b,n,c)

// ---------------- tf32 helpers ------------------------------------------------
__device__ __forceinline__ float f2tf(float x) {
    uint32_t u;
    asm("cvt.rna.tf32.f32 %0, %1;" : "=r"(u) : "f"(x));
    return __uint_as_float(u);
}
__device__ __forceinline__ void mma_tf32(float* d, float a0, float a1, float a2,
                                         float a3, float b0, float b1) {
    uint32_t ua0 = __float_as_uint(a0), ua1 = __float_as_uint(a1);
    uint32_t ua2 = __float_as_uint(a2), ua3 = __float_as_uint(a3);
    uint32_t ub0 = __float_as_uint(b0), ub1 = __float_as_uint(b1);
    asm volatile(
        "mma.sync.aligned.m16n8k8.row.col.f32.tf32.tf32.f32 "
        "{%0,%1,%2,%3},{%4,%5,%6,%7},{%8,%9},{%0,%1,%2,%3};"
        : "+f"(d[0]), "+f"(d[1]), "+f"(d[2]), "+f"(d[3])
        : "r"(ua0), "r"(ua1), "r"(ua2), "r"(ua3), "r"(ub0), "r"(ub1));
}

// ---------------- 3xTF32 tensor-core GEMM: C = A @ W^T + bias -----------------
// Tile 128x64xK, BK=16, 256 threads = 8 warps (4x2), warp tile 32x32.
// Operands split hi/lo (hi=tf32(x), lo=tf32(x-hi)); acc += hi*hi + lo*hi + hi*lo.
// smem k-permuted layout: within a 16-wide chunk, original col c stored at
// pos p = (c>>2) + 4*(c&3); row stride 20 floats (conflict-free STS & LDS.128).
// act: 0 = none, 1 = exact GELU, 2 = l2-normalize 32-col head groups (cols<256)
__global__ __launch_bounds__(256) void gemm_tf32(
    const float* __restrict__ A, const float* __restrict__ W,
    const float* __restrict__ bias, float* __restrict__ C,
    int M, int N, int K, int act)
{
    __shared__ __align__(16) float AsH[128 * 20];
    __shared__ __align__(16) float AsL[128 * 20];
    __shared__ __align__(16) float BsH[64 * 20];
    __shared__ __align__(16) float BsL[64 * 20];

    const int tid  = threadIdx.x;
    const int lane = tid & 31, wid = tid >> 5;
    const int gid  = lane >> 2, tig = lane & 3;
    const int warpM = wid & 3, warpN = wid >> 2;
    const int m0 = blockIdx.y * 128, n0 = blockIdx.x * 64;

    const int aRow = tid >> 2;   // 0..63 (and +64 for second)
    const int jq   = tid & 3;    // k-quad index

    float acc[2][4][4];
    #pragma unroll
    for (int mt = 0; mt < 2; mt++)
        #pragma unroll
        for (int nt = 0; nt < 4; nt++)
            #pragma unroll
            for (int i = 0; i < 4; i++) acc[mt][nt][i] = 0.f;

    float4 ra0, ra1, rb;
    const float4 z4 = make_float4(0.f, 0.f, 0.f, 0.f);

    // prefetch chunk 0
    {
        int r0 = m0 + aRow, r1 = r0 + 64;
        ra0 = (r0 < M) ? *(const float4*)&A[(size_t)r0 * K + jq * 4] : z4;
        ra1 = (r1 < M) ? *(const float4*)&A[(size_t)r1 * K + jq * 4] : z4;
        rb  = *(const float4*)&W[(size_t)(n0 + aRow) * K + jq * 4];
    }

    for (int k0 = 0; k0 < K; k0 += 16) {
        __syncthreads();
        // permuted STS with hi/lo tf32 split
        {
            float* pAH = &AsH[aRow * 20 + jq];
            float* pAL = &AsL[aRow * 20 + jq];
            float h;
            h = f2tf(ra0.x); pAH[0]  = h; pAL[0]  = f2tf(ra0.x - h);
            h = f2tf(ra0.y); pAH[4]  = h; pAL[4]  = f2tf(ra0.y - h);
            h = f2tf(ra0.z); pAH[8]  = h; pAL[8]  = f2tf(ra0.z - h);
            h = f2tf(ra0.w); pAH[12] = h; pAL[12] = f2tf(ra0.w - h);
            pAH += 64 * 20; pAL += 64 * 20;
            h = f2tf(ra1.x); pAH[0]  = h; pAL[0]  = f2tf(ra1.x - h);
            h = f2tf(ra1.y); pAH[4]  = h; pAL[4]  = f2tf(ra1.y - h);
            h = f2tf(ra1.z); pAH[8]  = h; pAL[8]  = f2tf(ra1.z - h);
            h = f2tf(ra1.w); pAH[12] = h; pAL[12] = f2tf(ra1.w - h);
            float* pBH = &BsH[aRow * 20 + jq];
            float* pBL = &BsL[aRow * 20 + jq];
            h = f2tf(rb.x); pBH[0]  = h; pBL[0]  = f2tf(rb.x - h);
            h = f2tf(rb.y); pBH[4]  = h; pBL[4]  = f2tf(rb.y - h);
            h = f2tf(rb.z); pBH[8]  = h; pBL[8]  = f2tf(rb.z - h);
            h = f2tf(rb.w); pBH[12] = h; pBL[12] = f2tf(rb.w - h);
        }
        __syncthreads();

        // prefetch next chunk
        if (k0 + 16 < K) {
            int r0 = m0 + aRow, r1 = r0 + 64;
            int kk = k0 + 16 + jq * 4;
            ra0 = (r0 < M) ? *(const float4*)&A[(size_t)r0 * K + kk] : z4;
            ra1 = (r1 < M) ? *(const float4*)&A[(size_t)r1 * K + kk] : z4;
            rb  = *(const float4*)&W[(size_t)(n0 + aRow) * K + kk];
        }

        // fragments + mma (3xTF32: HH, LH, HL)
        const int q4 = tig * 4;
        float4 aloH[2], ahiH[2], aloL[2], ahiL[2], bqH[4], bqL[4];
        #pragma unroll
        for (int mt = 0; mt < 2; mt++) {
            int rb0 = (warpM * 32 + mt * 16 + gid) * 20 + q4;
            aloH[mt] = *(const float4*)&AsH[rb0];
            ahiH[mt] = *(const float4*)&AsH[rb0 + 8 * 20];
            aloL[mt] = *(const float4*)&AsL[rb0];
            ahiL[mt] = *(const float4*)&AsL[rb0 + 8 * 20];
        }
        #pragma unroll
        for (int nt = 0; nt < 4; nt++) {
            int cb0 = (warpN * 32 + nt * 8 + gid) * 20 + q4;
            bqH[nt] = *(const float4*)&BsH[cb0];
            bqL[nt] = *(const float4*)&BsL[cb0];
        }

        #pragma unroll
        for (int mt = 0; mt < 2; mt++)
            #pragma unroll
            for (int nt = 0; nt < 4; nt++) {
                float* d = acc[mt][nt];
                // k 0-7
                mma_tf32(d, aloH[mt].x, ahiH[mt].x, aloH[mt].y, ahiH[mt].y,
                         bqH[nt].x, bqH[nt].y);
                mma_tf32(d, aloL[mt].x, ahiL[mt].x, aloL[mt].y, ahiL[mt].y,
                         bqH[nt].x, bqH[nt].y);
                mma_tf32(d, aloH[mt].x, ahiH[mt].x, aloH[mt].y, ahiH[mt].y,
                         bqL[nt].x, bqL[nt].y);
                // k 8-15
                mma_tf32(d, aloH[mt].z, ahiH[mt].z, aloH[mt].w, ahiH[mt].w,
                         bqH[nt].z, bqH[nt].w);
                mma_tf32(d, aloL[mt].z, ahiL[mt].z, aloL[mt].w, ahiL[mt].w,
                         bqH[nt].z, bqH[nt].w);
                mma_tf32(d, aloH[mt].z, ahiH[mt].z, aloH[mt].w, ahiH[mt].w,
                         bqL[nt].z, bqL[nt].w);
            }
    }

    // ---------------- epilogue ----------------
    const bool donorm = (act == 2) && (n0 + warpN * 32) < 256;
    #pragma unroll
    for (int mt = 0; mt < 2; mt++) {
        int r0 = m0 + warpM * 32 + mt * 16 + gid;
        int r1 = r0 + 8;
        float v0[4][2], v1[4][2];
        #pragma unroll
        for (int nt = 0; nt < 4; nt++) {
            int cb = n0 + warpN * 32 + nt * 8 + 2 * tig;
            float b0 = bias[cb], b1 = bias[cb + 1];
            v0[nt][0] = acc[mt][nt][0] + b0; v0[nt][1] = acc[mt][nt][1] + b1;
            v1[nt][0] = acc[mt][nt][2] + b0; v1[nt][1] = acc[mt][nt][3] + b1;
        }
        if (act == 1) {
            #pragma unroll
            for (int nt = 0; nt < 4; nt++)
                #pragma unroll
                for (int i = 0; i < 2; i++) {
                    v0[nt][i] = 0.5f * v0[nt][i] *
                                (1.f + erff(v0[nt][i] * 0.70710678118654752f));
                    v1[nt][i] = 0.5f * v1[nt][i] *
                                (1.f + erff(v1[nt][i] * 0.70710678118654752f));
                }
        } else if (donorm) {
            float ss0 = 0.f, ss1 = 0.f;
            #pragma unroll
            for (int nt = 0; nt < 4; nt++) {
                ss0 += v0[nt][0] * v0[nt][0] + v0[nt][1] * v0[nt][1];
                ss1 += v1[nt][0] * v1[nt][0] + v1[nt][1] * v1[nt][1];
            }
            ss0 += __shfl_xor_sync(0xffffffffu, ss0, 1);
            ss0 += __shfl_xor_sync(0xffffffffu, ss0, 2);
            ss1 += __shfl_xor_sync(0xffffffffu, ss1, 1);
            ss1 += __shfl_xor_sync(0xffffffffu, ss1, 2);
            float inv0 = 1.f / fmaxf(sqrtf(ss0), 1e-12f);
            float inv1 = 1.f / fmaxf(sqrtf(ss1), 1e-12f);
            #pragma unroll
            for (int nt = 0; nt < 4; nt++) {
                v0[nt][0] *= inv0; v0[nt][1] *= inv0;
                v1[nt][0] *= inv1; v1[nt][1] *= inv1;
            }
        }
        #pragma unroll
        for (int nt = 0; nt < 4; nt++) {
            int cb = n0 + warpN * 32 + nt * 8 + 2 * tig;
            if (r0 < M)
                *(float2*)&C[(size_t)r0 * N + cb] = make_float2(v0[nt][0], v0[nt][1]);
            if (r1 < M)
                *(float2*)&C[(size_t)r1 * N + cb] = make_float2(v1[nt][0], v1[nt][1]);
        }
    }
}

// ---------------- 4x4 average pool + layernorm over C ------------------------
__global__ __launch_bounds__(256) void pool_ln_kernel(
    const float* __restrict__ xsr, const float* __restrict__ gam,
    const float* __restrict__ bet, float* __restrict__ xpool)
{
    int bp = blockIdx.x;          // b*196 + p
    int b = bp / PL, p = bp % PL;
    int ph = p / 14, pw = p % 14;
    int c = threadIdx.x;

    float s = 0.f;
    #pragma unroll
    for (int i = 0; i < 4; i++)
        #pragma unroll
        for (int j = 0; j < 4; j++) {
            int n = (ph * 4 + i) * IMW + pw * 4 + j;
            s += xsr[((size_t)b * NN + n) * CC + c];
        }
    s *= (1.f / 16.f);

    __shared__ float r1[256], r2[256];
    r1[c] = s;
    r2[c] = s * s;
    __syncthreads();
    for (int st = 128; st > 0; st >>= 1) {
        if (c < st) { r1[c] += r1[c + st]; r2[c] += r2[c + st]; }
        __syncthreads();
    }
    float mean = r1[0] * (1.f / 256.f);
    float var  = r2[0] * (1.f / 256.f) - mean * mean;
    float invs = rsqrtf(var + 1e-5f);
    xpool[(size_t)bp * CC + c] = (s - mean) * invs * gam[c] + bet[c];
}

// ---------------- CPB table: tab[t,h] = relu(rct[t]@w1^T+b1) @ w2^T + b2 ------
__global__ __launch_bounds__(256) void tab_kernel(
    const float* __restrict__ rct, const float* __restrict__ w1,
    const float* __restrict__ b1, const float* __restrict__ w2,
    const float* __restrict__ b2, float* __restrict__ tab)
{
    int t = blockIdx.x;
    __shared__ float sh[512];
    float c0 = rct[t * 2], c1 = rct[t * 2 + 1];
    for (int j = threadIdx.x; j < 512; j += 256)
        sh[j] = fmaxf(0.f, c0 * w1[j * 2] + c1 * w1[j * 2 + 1] + b1[j]);
    __syncthreads();
    int w = threadIdx.x >> 5, lane = threadIdx.x & 31;  // warp w handles head w
    float s = 0.f;
    for (int j = lane; j < 512; j += 32) s += sh[j] * w2[w * 512 + j];
    #pragma unroll
    for (int o = 16; o > 0; o >>= 1) s += __shfl_xor_sync(0xffffffffu, s, o);
    if (lane == 0) tab[t * 8 + w] = s + b2[w];
}

// ---------------- fused attention: q-norm + local(9) + pooled(196) softmax ----
// grid: (NN/16, HH, BZ); block: 512 threads, warp w handles row n0+w
__global__ __launch_bounds__(512) void attn_kernel(
    const float* __restrict__ q, const float* __restrict__ qe,
    const float* __restrict__ temp, const float* __restrict__ sls,
    const float* __restrict__ kv, const float* __restrict__ kvp,
    const float* __restrict__ tab, const int* __restrict__ rpi,
    const float* __restrict__ rpb, const float* __restrict__ ltok,
    const float* __restrict__ lbias, float* __restrict__ out)
{
    extern __shared__ float sm[];
    float* sK  = sm;                 // 196*33
    float* sV  = sK + PL * 33;       // 196*33
    float* sP  = sV + PL * 33;       // 16*224
    float* sQs = sP + 16 * 224;      // 16*32
    float* sQn = sQs + 512;          // 16*32

    const int b = blockIdx.z, h = blockIdx.y;
    const int n0 = blockIdx.x * 16;
    const int tid = threadIdx.x;

    // stage pooled K/V for this (b,h) with float4 loads
    for (int i = tid; i < PL * 8; i += 512) {
        int m = i >> 3, q4 = i & 7;
        const float* rowb = kvp + ((size_t)(b * PL + m)) * 512 + h * HD;
        float4 kk4 = *(const float4*)(rowb + q4 * 4);
        float4 vv4 = *(const float4*)(rowb + 256 + q4 * 4);
        int base = m * 33 + q4 * 4;
        sK[base + 0] = kk4.x; sK[base + 1] = kk4.y;
        sK[base + 2] = kk4.z; sK[base + 3] = kk4.w;
        sV[base + 0] = vv4.x; sV[base + 1] = vv4.y;
        sV[base + 2] = vv4.z; sV[base + 3] = vv4.w;
    }

    const int w = tid >> 5, lane = tid & 31;
    const int n = n0 + w;

    // fused q post-processing: l2-norm + embedding + temperature/seq scaling
    {
        float val = q[((size_t)(b * NN + n)) * CC + h * HD + lane];
        float ss = val * val;
        #pragma unroll
        for (int o = 16; o > 0; o >>= 1) ss += __shfl_xor_sync(0xffffffffu, ss, o);
        float inv = 1.f / fmaxf(sqrtf(ss), 1e-12f);
        float qnv = val * inv;
        float sp = log1pf(expf(temp[h]));
        float qsv = (qnv + qe[h * HD + lane]) * sp * sls[n];
        sQs[w * 32 + lane] = qsv;
        sQn[w * 32 + lane] = qnv;
    }
    __syncthreads();

    const int r = n / IMW, cc = n % IMW;
    float* P = sP + w * 224;
    const float* Q  = sQs + w * 32;
    const float* Qn = sQn + w * 32;

    // local logits (lanes 0..8)
    if (lane < 9) {
        int di = lane / 3 - 1, dj = lane % 3 - 1;
        int rr = r + di, c2 = cc + dj;
        bool valid = (rr >= 0 && rr < IMH && c2 >= 0 && c2 < IMW);
        float a;
        if (valid) {
            int nb = rr * IMW + c2;
            const float4* kr = (const float4*)(kv + ((size_t)(b * NN + nb)) * 512 + h * HD);
            float s2 = 0.f;
            #pragma unroll
            for (int d4 = 0; d4 < 8; d4++) {
                float4 t = kr[d4];
                s2 += Q[d4*4+0]*t.x + Q[d4*4+1]*t.y + Q[d4*4+2]*t.z + Q[d4*4+3]*t.w;
            }
            a = s2 + rpb[h * 9 + lane];
        } else {
            a = __int_as_float(0xff800000);  // -inf
        }
        P[lane] = a;
    }

    // pooled logits
    const int* rp = rpi + (size_t)n * PL;
    for (int m = lane; m < PL; m += 32) {
        const float* kr = sK + m * 33;
        float s2 = 0.f;
        #pragma unroll
        for (int d = 0; d < 32; d++) s2 += Q[d] * kr[d];
        P[9 + m] = s2 + tab[rp[m] * 8 + h];
    }
    __syncwarp();

    // softmax over 205
    float mx = -3.4e38f;
    for (int j = lane; j < 205; j += 32) mx = fmaxf(mx, P[j]);
    #pragma unroll
    for (int o = 16; o > 0; o >>= 1) mx = fmaxf(mx, __shfl_xor_sync(0xffffffffu, mx, o));
    float sum = 0.f;
    for (int j = lane; j < 205; j += 32) {
        float e = __expf(P[j] - mx);
        P[j] = e;
        sum += e;
    }
    #pragma unroll
    for (int o = 16; o > 0; o >>= 1) sum += __shfl_xor_sync(0xffffffffu, sum, o);
    float inv = 1.f / sum;
    for (int j = lane; j < 205; j += 32) P[j] *= inv;
    __syncwarp();

    // w_loc = q_norm @ learnable_tokens + learnable_bias + a_loc (lanes 0..8)
    if (lane < 9) {
        float s2 = 0.f;
        #pragma unroll
        for (int d = 0; d < 32; d++) s2 += Qn[d] * ltok[(h * 32 + d) * 9 + lane];
        P[lane] = s2 + lbias[h * 9 + lane] + P[lane];
    }
    __syncwarp();

    // outputs: lane = head-dim d
    float acc = 0.f;
    #pragma unroll
    for (int l2 = 0; l2 < 9; l2++) {
        int di = l2 / 3 - 1, dj = l2 % 3 - 1;
        int rr = r + di, c2 = cc + dj;
        if (rr >= 0 && rr < IMH && c2 >= 0 && c2 < IMW) {
            int nb = rr * IMW + c2;
            acc += P[l2] * kv[((size_t)(b * NN + nb)) * 512 + 256 + h * HD + lane];
        }
    }
    for (int m = 0; m < PL; m++)
        acc += P[9 + m] * sV[m * 33 + lane];

    out[((size_t)(b * NN) + n) * CC + h * HD + lane] = acc;
}

// -----------------------------------------------------------------------------
extern "C" void kernel_launch(void* const* d_in, const int* in_sizes, int n_in,
                              void* d_out, int out_size)
{
    const float* x      = (const float*)d_in[0];
    const int*   rpi    = (const int*)  d_in[3];
    const float* rct    = (const float*)d_in[4];
    const float* sls    = (const float*)d_in[5];
    const float* q_w    = (const float*)d_in[7];
    const float* q_b    = (const float*)d_in[8];
    const float* kv_w   = (const float*)d_in[9];
    const float* kv_b   = (const float*)d_in[10];
    const float* sr_w   = (const float*)d_in[11];
    const float* sr_b   = (const float*)d_in[12];
    const float* norm_g = (const float*)d_in[13];
    const float* norm_b = (const float*)d_in[14];
    const float* cpb1_w = (const float*)d_in[15];
    const float* cpb1_b = (const float*)d_in[16];
    const float* cpb2_w = (const float*)d_in[17];
    const float* cpb2_b = (const float*)d_in[18];
    const float* temp   = (const float*)d_in[19];
    const float* qe     = (const float*)d_in[20];
    const float* rpb    = (const float*)d_in[21];
    const float* ltok   = (const float*)d_in[22];
    const float* lbias  = (const float*)d_in[23];
    const float* proj_w = (const float*)d_in[24];
    const float* proj_b = (const float*)d_in[25];
    float* out = (float*)d_out;

    float *p_q, *p_kv, *p_xsr, *p_xpl, *p_kvp, *p_tab, *p_att;
    cudaGetSymbolAddress((void**)&p_q,   g_q);
    cudaGetSymbolAddress((void**)&p_kv,  g_kv);
    cudaGetSymbolAddress((void**)&p_xsr, g_xsr);
    cudaGetSymbolAddress((void**)&p_xpl, g_xpl);
    cudaGetSymbolAddress((void**)&p_kvp, g_kvp);
    cudaGetSymbolAddress((void**)&p_tab, g_tab);
    cudaGetSymbolAddress((void**)&p_att, g_att);

    const int M = BZ * NN;  // 12544, = 98 * 128

    // main GEMMs on tensor cores, 3xTF32 (kv: k-half l2-norm; sr: GELU fused)
    gemm_tf32<<<dim3(4, 98), 256>>>(x, q_w,  q_b,  p_q,   M, 256, 256, 0);
    gemm_tf32<<<dim3(8, 98), 256>>>(x, kv_w, kv_b, p_kv,  M, 512, 256, 2);
    gemm_tf32<<<dim3(4, 98), 256>>>(x, sr_w, sr_b, p_xsr, M, 256, 256, 1);

    // pooled path
    pool_ln_kernel<<<BZ * PL, 256>>>(p_xsr, norm_g, norm_b, p_xpl);
    gemm_tf32<<<dim3(8, 7), 256>>>(p_xpl, kv_w, kv_b, p_kvp, BZ * PL, 512, 256, 2);

    // CPB bias table
    tab_kernel<<<KTAB, 256>>>(rct, cpb1_w, cpb1_b, cpb2_w, cpb2_b, p_tab);

    // fused attention (q-norm fused into staging)
    size_t shmem = (size_t)(PL * 33 * 2 + 16 * 224 + 1024) * sizeof(float);  // 70176 B
    cudaFuncSetAttribute(attn_kernel, cudaFuncAttributeMaxDynamicSharedMemorySize, 72000);
    attn_kernel<<<dim3(NN / 16, HH, BZ), 512, shmem>>>(
        p_q, qe, temp, sls, p_kv, p_kvp, p_tab, rpi, rpb, ltok, lbias, p_att);

    // output projection
    gemm_tf32<<<dim3(4, 98), 256>>>(p_att, proj_w, proj_b, out, M, 256, 256, 0);
}

// round 6
// speedup vs baseline: 1.6487x; 1.2754x over previous
#include <cuda_runtime.h>
#include <cuda_bf16.h>
#include <math.h>
#include <stdint.h>

// Problem constants
#define BZ 4
#define NN 3136
#define CC 256
#define HH 8
#define HD 32
#define PL 196
#define IMH 56
#define IMW 56
#define KTAB 2048

// ---------------- scratch (device globals; no allocation allowed) -------------
__device__ float g_q   [BZ * NN * CC];
__device__ float g_kv  [BZ * NN * 512];
__device__ float g_xsr [BZ * NN * CC];
__device__ float g_xpl [BZ * PL * CC];
__device__ float g_kvp [BZ * PL * 512];
__device__ float g_tab [KTAB * HH];
__device__ float g_att [BZ * NN * CC];
// bf16 hi/lo split inputs
__device__ __nv_bfloat16 g_xh  [BZ * NN * CC];
__device__ __nv_bfloat16 g_xl  [BZ * NN * CC];
__device__ __nv_bfloat16 g_xph [BZ * PL * CC];
__device__ __nv_bfloat16 g_xpL [BZ * PL * CC];
__device__ __nv_bfloat16 g_ath [BZ * NN * CC];
__device__ __nv_bfloat16 g_atl [BZ * NN * CC];

// ---------------- helpers ------------------------------------------------------
__device__ __forceinline__ uint32_t smem_u32(const void* p) {
    uint32_t a;
    asm("{ .reg .u64 t; cvta.to.shared.u64 t, %1; cvt.u32.u64 %0, t; }"
        : "=r"(a) : "l"(p));
    return a;
}
__device__ __forceinline__ void split4(float4 v, uint2& hi, uint2& lo) {
    float h0 = __bfloat162float(__float2bfloat16_rn(v.x));
    float h1 = __bfloat162float(__float2bfloat16_rn(v.y));
    float h2 = __bfloat162float(__float2bfloat16_rn(v.z));
    float h3 = __bfloat162float(__float2bfloat16_rn(v.w));
    __nv_bfloat162 ph0 = __floats2bfloat162_rn(h0, h1);
    __nv_bfloat162 ph1 = __floats2bfloat162_rn(h2, h3);
    __nv_bfloat162 pl0 = __floats2bfloat162_rn(v.x - h0, v.y - h1);
    __nv_bfloat162 pl1 = __floats2bfloat162_rn(v.z - h2, v.w - h3);
    hi.x = *(uint32_t*)&ph0; hi.y = *(uint32_t*)&ph1;
    lo.x = *(uint32_t*)&pl0; lo.y = *(uint32_t*)&pl1;
}
__device__ __forceinline__ void ldsm4(uint32_t* r, uint32_t addr) {
    asm volatile("ldmatrix.sync.aligned.m8n8.x4.shared.b16 {%0,%1,%2,%3}, [%4];"
                 : "=r"(r[0]), "=r"(r[1]), "=r"(r[2]), "=r"(r[3]) : "r"(addr));
}
__device__ __forceinline__ void mma_bf16(float* d, const uint32_t* a,
                                         uint32_t b0, uint32_t b1) {
    asm volatile(
        "mma.sync.aligned.m16n8k16.row.col.f32.bf16.bf16.f32 "
        "{%0,%1,%2,%3},{%4,%5,%6,%7},{%8,%9},{%0,%1,%2,%3};"
        : "+f"(d[0]), "+f"(d[1]), "+f"(d[2]), "+f"(d[3])
        : "r"(a[0]), "r"(a[1]), "r"(a[2]), "r"(a[3]), "r"(b0), "r"(b1));
}

// ---------------- split: fp32 -> bf16 hi/lo -----------------------------------
__global__ __launch_bounds__(256) void split_kernel(
    const float* __restrict__ src, __nv_bfloat16* __restrict__ hi,
    __nv_bfloat16* __restrict__ lo, int n4)
{
    int i = blockIdx.x * 256 + threadIdx.x;
    if (i >= n4) return;
    float4 v = ((const float4*)src)[i];
    uint2 h, l;
    split4(v, h, l);
    ((uint2*)hi)[i] = h;
    ((uint2*)lo)[i] = l;
}

// ---------------- bf16 3-pass compensated GEMM --------------------------------
// C[M,N] = A[M,256] @ W[N,256]^T + bias ; A pre-split bf16 hi/lo, W fp32.
// Tile 128x64, BK=64 (4 chunks). 8 warps (warpM 0-3 x warpN 0-1), warp 32x32.
// smem: A chunk hi/lo (SW128, 128B rows), B full-K hi/lo (512B rows, SW128/blk).
// act: 0 none, 1 exact GELU, 2 l2-norm 32-col head groups when global col < 256
#define A_H 0
#define A_L 16384
#define B_H 32768
#define B_L 65536
#define SMEM_GEMM 98304

__global__ __launch_bounds__(256) void gemm_bf16(
    const __nv_bfloat16* __restrict__ Ah, const __nv_bfloat16* __restrict__ Al,
    const float* __restrict__ W, const float* __restrict__ bias,
    float* __restrict__ C, int M, int N, int act)
{
    extern __shared__ __align__(1024) char smem[];
    const uint32_t sb = smem_u32(smem);
    const int tid = threadIdx.x;
    const int lane = tid & 31, wid = tid >> 5;
    const int gid = lane >> 2, tig = lane & 3;
    const int warpM = wid & 3, warpN = wid >> 2;
    const int m0 = blockIdx.y * 128, n0 = blockIdx.x * 64;

    // ---- stage B (64 rows x K=256) fp32 -> bf16 hi/lo, swizzled ----
    #pragma unroll
    for (int it = 0; it < 16; it++) {
        int idx = tid + it * 256;
        int n = idx >> 6, c4 = idx & 63;
        float4 wv = *(const float4*)&W[(size_t)(n0 + n) * 256 + c4 * 4];
        uint2 hi, lo;
        split4(wv, hi, lo);
        uint32_t off = n * 512 + ((c4 >> 4) << 7) +
                       (((((c4 >> 1) & 7) ^ (n & 7))) << 4) + ((c4 & 1) << 3);
        *(uint2*)(smem + B_H + off) = hi;
        *(uint2*)(smem + B_L + off) = lo;
    }

    float acc[2][4][4];
    #pragma unroll
    for (int mt = 0; mt < 2; mt++)
        #pragma unroll
        for (int nt = 0; nt < 4; nt++)
            #pragma unroll
            for (int i = 0; i < 4; i++) acc[mt][nt][i] = 0.f;

    const uint4 z16 = make_uint4(0, 0, 0, 0);
    uint4 pah[4], pal[4];
    // prefetch A chunk 0
    #pragma unroll
    for (int it = 0; it < 4; it++) {
        int idx = tid + it * 256;
        int row = idx >> 3, seg = idx & 7;
        int gr = m0 + row;
        pah[it] = (gr < M) ? *(const uint4*)&Ah[(size_t)gr * 256 + seg * 8] : z16;
        pal[it] = (gr < M) ? *(const uint4*)&Al[(size_t)gr * 256 + seg * 8] : z16;
    }

    // lane mapping for ldmatrix
    const int a_row_in = ((lane >> 3) & 1) * 8 + (lane & 7);
    const int a_kseg   = (lane >> 4) & 1;
    const int b_row_in = ((lane >> 4) & 1) * 8 + (lane & 7);
    const int b_kseg   = (lane >> 3) & 1;

    for (int ch = 0; ch < 4; ch++) {
        __syncthreads();
        #pragma unroll
        for (int it = 0; it < 4; it++) {
            int idx = tid + it * 256;
            int row = idx >> 3, seg = idx & 7;
            uint32_t off = row * 128 + ((seg ^ (row & 7)) << 4);
            *(uint4*)(smem + A_H + off) = pah[it];
            *(uint4*)(smem + A_L + off) = pal[it];
        }
        __syncthreads();

        if (ch < 3) {
            #pragma unroll
            for (int it = 0; it < 4; it++) {
                int idx = tid + it * 256;
                int row = idx >> 3, seg = idx & 7;
                int gr = m0 + row;
                size_t gb = (size_t)gr * 256 + (ch + 1) * 64 + seg * 8;
                pah[it] = (gr < M) ? *(const uint4*)&Ah[gb] : z16;
                pal[it] = (gr < M) ? *(const uint4*)&Al[gb] : z16;
            }
        }

        #pragma unroll
        for (int s = 0; s < 4; s++) {
            uint32_t ah[2][4], al[2][4], bh[2][4], bl[2][4];
            #pragma unroll
            for (int mt = 0; mt < 2; mt++) {
                int r = warpM * 32 + mt * 16 + a_row_in;
                uint32_t off = r * 128 + (((s * 2 + a_kseg) ^ (r & 7)) << 4);
                ldsm4(ah[mt], sb + A_H + off);
                ldsm4(al[mt], sb + A_L + off);
            }
            #pragma unroll
            for (int np = 0; np < 2; np++) {
                int n = warpN * 32 + np * 16 + b_row_in;
                uint32_t off = n * 512 + ch * 128 +
                               (((s * 2 + b_kseg) ^ (n & 7)) << 4);
                ldsm4(bh[np], sb + B_H + off);
                ldsm4(bl[np], sb + B_L + off);
            }
            #pragma unroll
            for (int mt = 0; mt < 2; mt++)
                #pragma unroll
                for (int np = 0; np < 2; np++) {
                    float* dl = acc[mt][2 * np];
                    float* dh = acc[mt][2 * np + 1];
                    mma_bf16(dl, ah[mt], bh[np][0], bh[np][1]);
                    mma_bf16(dl, al[mt], bh[np][0], bh[np][1]);
                    mma_bf16(dl, ah[mt], bl[np][0], bl[np][1]);
                    mma_bf16(dh, ah[mt], bh[np][2], bh[np][3]);
                    mma_bf16(dh, al[mt], bh[np][2], bh[np][3]);
                    mma_bf16(dh, ah[mt], bl[np][2], bl[np][3]);
                }
        }
    }

    // ---------------- epilogue ----------------
    const bool donorm = (act == 2) && (n0 + warpN * 32) < 256;
    #pragma unroll
    for (int mt = 0; mt < 2; mt++) {
        int r0 = m0 + warpM * 32 + mt * 16 + gid;
        int r1 = r0 + 8;
        float v0[4][2], v1[4][2];
        #pragma unroll
        for (int nt = 0; nt < 4; nt++) {
            int cb = n0 + warpN * 32 + nt * 8 + 2 * tig;
            float b0 = bias[cb], b1 = bias[cb + 1];
            v0[nt][0] = acc[mt][nt][0] + b0; v0[nt][1] = acc[mt][nt][1] + b1;
            v1[nt][0] = acc[mt][nt][2] + b0; v1[nt][1] = acc[mt][nt][3] + b1;
        }
        if (act == 1) {
            #pragma unroll
            for (int nt = 0; nt < 4; nt++)
                #pragma unroll
                for (int i = 0; i < 2; i++) {
                    v0[nt][i] = 0.5f * v0[nt][i] *
                                (1.f + erff(v0[nt][i] * 0.70710678118654752f));
                    v1[nt][i] = 0.5f * v1[nt][i] *
                                (1.f + erff(v1[nt][i] * 0.70710678118654752f));
                }
        } else if (donorm) {
            float ss0 = 0.f, ss1 = 0.f;
            #pragma unroll
            for (int nt = 0; nt < 4; nt++) {
                ss0 += v0[nt][0] * v0[nt][0] + v0[nt][1] * v0[nt][1];
                ss1 += v1[nt][0] * v1[nt][0] + v1[nt][1] * v1[nt][1];
            }
            ss0 += __shfl_xor_sync(0xffffffffu, ss0, 1);
            ss0 += __shfl_xor_sync(0xffffffffu, ss0, 2);
            ss1 += __shfl_xor_sync(0xffffffffu, ss1, 1);
            ss1 += __shfl_xor_sync(0xffffffffu, ss1, 2);
            float inv0 = 1.f / fmaxf(sqrtf(ss0), 1e-12f);
            float inv1 = 1.f / fmaxf(sqrtf(ss1), 1e-12f);
            #pragma unroll
            for (int nt = 0; nt < 4; nt++) {
                v0[nt][0] *= inv0; v0[nt][1] *= inv0;
                v1[nt][0] *= inv1; v1[nt][1] *= inv1;
            }
        }
        #pragma unroll
        for (int nt = 0; nt < 4; nt++) {
            int cb = n0 + warpN * 32 + nt * 8 + 2 * tig;
            if (r0 < M)
                *(float2*)&C[(size_t)r0 * N + cb] = make_float2(v0[nt][0], v0[nt][1]);
            if (r1 < M)
                *(float2*)&C[(size_t)r1 * N + cb] = make_float2(v1[nt][0], v1[nt][1]);
        }
    }
}

// ---------------- 4x4 average pool + layernorm over C ------------------------
__global__ __launch_bounds__(256) void pool_ln_kernel(
    const float* __restrict__ xsr, const float* __restrict__ gam,
    const float* __restrict__ bet, float* __restrict__ xpool)
{
    int bp = blockIdx.x;
    int b = bp / PL, p = bp % PL;
    int ph = p / 14, pw = p % 14;
    int c = threadIdx.x;

    float s = 0.f;
    #pragma unroll
    for (int i = 0; i < 4; i++)
        #pragma unroll
        for (int j = 0; j < 4; j++) {
            int n = (ph * 4 + i) * IMW + pw * 4 + j;
            s += xsr[((size_t)b * NN + n) * CC + c];
        }
    s *= (1.f / 16.f);

    __shared__ float r1[256], r2[256];
    r1[c] = s;
    r2[c] = s * s;
    __syncthreads();
    for (int st = 128; st > 0; st >>= 1) {
        if (c < st) { r1[c] += r1[c + st]; r2[c] += r2[c + st]; }
        __syncthreads();
    }
    float mean = r1[0] * (1.f / 256.f);
    float var  = r2[0] * (1.f / 256.f) - mean * mean;
    float invs = rsqrtf(var + 1e-5f);
    xpool[(size_t)bp * CC + c] = (s - mean) * invs * gam[c] + bet[c];
}

// ---------------- CPB table ----------------------------------------------------
__global__ __launch_bounds__(256) void tab_kernel(
    const float* __restrict__ rct, const float* __restrict__ w1,
    const float* __restrict__ b1, const float* __restrict__ w2,
    const float* __restrict__ b2, float* __restrict__ tab)
{
    int t = blockIdx.x;
    __shared__ float sh[512];
    float c0 = rct[t * 2], c1 = rct[t * 2 + 1];
    for (int j = threadIdx.x; j < 512; j += 256)
        sh[j] = fmaxf(0.f, c0 * w1[j * 2] + c1 * w1[j * 2 + 1] + b1[j]);
    __syncthreads();
    int w = threadIdx.x >> 5, lane = threadIdx.x & 31;
    float s = 0.f;
    for (int j = lane; j < 512; j += 32) s += sh[j] * w2[w * 512 + j];
    #pragma unroll
    for (int o = 16; o > 0; o >>= 1) s += __shfl_xor_sync(0xffffffffu, s, o);
    if (lane == 0) tab[t * 8 + w] = s + b2[w];
}

// ---------------- fused attention ---------------------------------------------
__global__ __launch_bounds__(512) void attn_kernel(
    const float* __restrict__ q, const float* __restrict__ qe,
    const float* __restrict__ temp, const float* __restrict__ sls,
    const float* __restrict__ kv, const float* __restrict__ kvp,
    const float* __restrict__ tab, const int* __restrict__ rpi,
    const float* __restrict__ rpb, const float* __restrict__ ltok,
    const float* __restrict__ lbias, float* __restrict__ out)
{
    extern __shared__ float sm[];
    float* sK  = sm;
    float* sV  = sK + PL * 33;
    float* sP  = sV + PL * 33;
    float* sQs = sP + 16 * 224;
    float* sQn = sQs + 512;

    const int b = blockIdx.z, h = blockIdx.y;
    const int n0 = blockIdx.x * 16;
    const int tid = threadIdx.x;

    for (int i = tid; i < PL * 8; i += 512) {
        int m = i >> 3, q4 = i & 7;
        const float* rowb = kvp + ((size_t)(b * PL + m)) * 512 + h * HD;
        float4 kk4 = *(const float4*)(rowb + q4 * 4);
        float4 vv4 = *(const float4*)(rowb + 256 + q4 * 4);
        int base = m * 33 + q4 * 4;
        sK[base + 0] = kk4.x; sK[base + 1] = kk4.y;
        sK[base + 2] = kk4.z; sK[base + 3] = kk4.w;
        sV[base + 0] = vv4.x; sV[base + 1] = vv4.y;
        sV[base + 2] = vv4.z; sV[base + 3] = vv4.w;
    }

    const int w = tid >> 5, lane = tid & 31;
    const int n = n0 + w;

    {
        float val = q[((size_t)(b * NN + n)) * CC + h * HD + lane];
        float ss = val * val;
        #pragma unroll
        for (int o = 16; o > 0; o >>= 1) ss += __shfl_xor_sync(0xffffffffu, ss, o);
        float inv = 1.f / fmaxf(sqrtf(ss), 1e-12f);
        float qnv = val * inv;
        float sp = log1pf(expf(temp[h]));
        float qsv = (qnv + qe[h * HD + lane]) * sp * sls[n];
        sQs[w * 32 + lane] = qsv;
        sQn[w * 32 + lane] = qnv;
    }
    __syncthreads();

    const int r = n / IMW, cc = n % IMW;
    float* P = sP + w * 224;
    const float* Q  = sQs + w * 32;
    const float* Qn = sQn + w * 32;

    if (lane < 9) {
        int di = lane / 3 - 1, dj = lane % 3 - 1;
        int rr = r + di, c2 = cc + dj;
        bool valid = (rr >= 0 && rr < IMH && c2 >= 0 && c2 < IMW);
        float a;
        if (valid) {
            int nb = rr * IMW + c2;
            const float4* kr = (const float4*)(kv + ((size_t)(b * NN + nb)) * 512 + h * HD);
            float s2 = 0.f;
            #pragma unroll
            for (int d4 = 0; d4 < 8; d4++) {
                float4 t = kr[d4];
                s2 += Q[d4*4+0]*t.x + Q[d4*4+1]*t.y + Q[d4*4+2]*t.z + Q[d4*4+3]*t.w;
            }
            a = s2 + rpb[h * 9 + lane];
        } else {
            a = __int_as_float(0xff800000);
        }
        P[lane] = a;
    }

    const int* rp = rpi + (size_t)n * PL;
    for (int m = lane; m < PL; m += 32) {
        const float* kr = sK + m * 33;
        float s2 = 0.f;
        #pragma unroll
        for (int d = 0; d < 32; d++) s2 += Q[d] * kr[d];
        P[9 + m] = s2 + tab[rp[m] * 8 + h];
    }
    __syncwarp();

    float mx = -3.4e38f;
    for (int j = lane; j < 205; j += 32) mx = fmaxf(mx, P[j]);
    #pragma unroll
    for (int o = 16; o > 0; o >>= 1) mx = fmaxf(mx, __shfl_xor_sync(0xffffffffu, mx, o));
    float sum = 0.f;
    for (int j = lane; j < 205; j += 32) {
        float e = __expf(P[j] - mx);
        P[j] = e;
        sum += e;
    }
    #pragma unroll
    for (int o = 16; o > 0; o >>= 1) sum += __shfl_xor_sync(0xffffffffu, sum, o);
    float inv = 1.f / sum;
    for (int j = lane; j < 205; j += 32) P[j] *= inv;
    __syncwarp();

    if (lane < 9) {
        float s2 = 0.f;
        #pragma unroll
        for (int d = 0; d < 32; d++) s2 += Qn[d] * ltok[(h * 32 + d) * 9 + lane];
        P[lane] = s2 + lbias[h * 9 + lane] + P[lane];
    }
    __syncwarp();

    float acc = 0.f;
    #pragma unroll
    for (int l2 = 0; l2 < 9; l2++) {
        int di = l2 / 3 - 1, dj = l2 % 3 - 1;
        int rr = r + di, c2 = cc + dj;
        if (rr >= 0 && rr < IMH && c2 >= 0 && c2 < IMW) {
            int nb = rr * IMW + c2;
            acc += P[l2] * kv[((size_t)(b * NN + nb)) * 512 + 256 + h * HD + lane];
        }
    }
    for (int m = 0; m < PL; m++)
        acc += P[9 + m] * sV[m * 33 + lane];

    out[((size_t)(b * NN) + n) * CC + h * HD + lane] = acc;
}

// -----------------------------------------------------------------------------
extern "C" void kernel_launch(void* const* d_in, const int* in_sizes, int n_in,
                              void* d_out, int out_size)
{
    const float* x      = (const float*)d_in[0];
    const int*   rpi    = (const int*)  d_in[3];
    const float* rct    = (const float*)d_in[4];
    const float* sls    = (const float*)d_in[5];
    const float* q_w    = (const float*)d_in[7];
    const float* q_b    = (const float*)d_in[8];
    const float* kv_w   = (const float*)d_in[9];
    const float* kv_b   = (const float*)d_in[10];
    const float* sr_w   = (const float*)d_in[11];
    const float* sr_b   = (const float*)d_in[12];
    const float* norm_g = (const float*)d_in[13];
    const float* norm_b = (const float*)d_in[14];
    const float* cpb1_w = (const float*)d_in[15];
    const float* cpb1_b = (const float*)d_in[16];
    const float* cpb2_w = (const float*)d_in[17];
    const float* cpb2_b = (const float*)d_in[18];
    const float* temp   = (const float*)d_in[19];
    const float* qe     = (const float*)d_in[20];
    const float* rpb    = (const float*)d_in[21];
    const float* ltok   = (const float*)d_in[22];
    const float* lbias  = (const float*)d_in[23];
    const float* proj_w = (const float*)d_in[24];
    const float* proj_b = (const float*)d_in[25];
    float* out = (float*)d_out;

    float *p_q, *p_kv, *p_xsr, *p_xpl, *p_kvp, *p_tab, *p_att;
    __nv_bfloat16 *p_xh, *p_xl, *p_xph, *p_xpL, *p_ath, *p_atl;
    cudaGetSymbolAddress((void**)&p_q,   g_q);
    cudaGetSymbolAddress((void**)&p_kv,  g_kv);
    cudaGetSymbolAddress((void**)&p_xsr, g_xsr);
    cudaGetSymbolAddress((void**)&p_xpl, g_xpl);
    cudaGetSymbolAddress((void**)&p_kvp, g_kvp);
    cudaGetSymbolAddress((void**)&p_tab, g_tab);
    cudaGetSymbolAddress((void**)&p_att, g_att);
    cudaGetSymbolAddress((void**)&p_xh,  g_xh);
    cudaGetSymbolAddress((void**)&p_xl,  g_xl);
    cudaGetSymbolAddress((void**)&p_xph, g_xph);
    cudaGetSymbolAddress((void**)&p_xpL, g_xpL);
    cudaGetSymbolAddress((void**)&p_ath, g_ath);
    cudaGetSymbolAddress((void**)&p_atl, g_atl);

    const int M = BZ * NN;  // 12544 = 98 * 128
    const int MP = BZ * PL; // 784

    cudaFuncSetAttribute(gemm_bf16, cudaFuncAttributeMaxDynamicSharedMemorySize,
                         SMEM_GEMM);

    // split x -> bf16 hi/lo (shared by q, kv, sr GEMMs)
    split_kernel<<<(M * CC / 4 + 255) / 256, 256>>>(x, p_xh, p_xl, M * CC / 4);

    // main GEMMs (bf16 tensor cores, 3-pass compensated)
    gemm_bf16<<<dim3(4, 98), 256, SMEM_GEMM>>>(p_xh, p_xl, q_w,  q_b,  p_q,   M, 256, 0);
    gemm_bf16<<<dim3(8, 98), 256, SMEM_GEMM>>>(p_xh, p_xl, kv_w, kv_b, p_kv,  M, 512, 2);
    gemm_bf16<<<dim3(4, 98), 256, SMEM_GEMM>>>(p_xh, p_xl, sr_w, sr_b, p_xsr, M, 256, 1);

    // pooled path
    pool_ln_kernel<<<BZ * PL, 256>>>(p_xsr, norm_g, norm_b, p_xpl);
    split_kernel<<<(MP * CC / 4 + 255) / 256, 256>>>(p_xpl, p_xph, p_xpL, MP * CC / 4);
    gemm_bf16<<<dim3(8, 7), 256, SMEM_GEMM>>>(p_xph, p_xpL, kv_w, kv_b, p_kvp, MP, 512, 2);

    // CPB bias table
    tab_kernel<<<KTAB, 256>>>(rct, cpb1_w, cpb1_b, cpb2_w, cpb2_b, p_tab);

    // fused attention
    size_t shmem = (size_t)(PL * 33 * 2 + 16 * 224 + 1024) * sizeof(float);
    cudaFuncSetAttribute(attn_kernel, cudaFuncAttributeMaxDynamicSharedMemorySize, 72000);
    attn_kernel<<<dim3(NN / 16, HH, BZ), 512, shmem>>>(
        p_q, qe, temp, sls, p_kv, p_kvp, p_tab, rpi, rpb, ltok, lbias, p_att);

    // output projection
    split_kernel<<<(M * CC / 4 + 255) / 256, 256>>>(p_att, p_ath, p_atl, M * CC / 4);
    gemm_bf16<<<dim3(4, 98), 256, SMEM_GEMM>>>(p_ath, p_atl, proj_w, proj_b, out, M, 256, 0);
}

// round 7
// speedup vs baseline: 1.9290x; 1.1700x over previous
#include <cuda_runtime.h>
#include <cuda_bf16.h>
#include <math.h>
#include <stdint.h>

// Problem constants
#define BZ 4
#define NN 3136
#define CC 256
#define HH 8
#define HD 32
#define PL 196
#define IMH 56
#define IMW 56
#define KTAB 2048

// ---------------- scratch (device globals; no allocation allowed) -------------
__device__ float g_q   [BZ * NN * CC];
__device__ float g_kv  [BZ * NN * 512];
__device__ float g_xsr [BZ * NN * CC];
__device__ float g_xpl [BZ * PL * CC];
__device__ float g_kvp [BZ * PL * 512];
__device__ float g_tab [KTAB * HH];
__device__ float g_att [BZ * NN * CC];
// bf16 hi/lo split inputs
__device__ __nv_bfloat16 g_xh  [BZ * NN * CC];
__device__ __nv_bfloat16 g_xl  [BZ * NN * CC];
__device__ __nv_bfloat16 g_xph [BZ * PL * CC];
__device__ __nv_bfloat16 g_xpL [BZ * PL * CC];
__device__ __nv_bfloat16 g_ath [BZ * NN * CC];
__device__ __nv_bfloat16 g_atl [BZ * NN * CC];

// ---------------- helpers ------------------------------------------------------
__device__ __forceinline__ uint32_t smem_u32(const void* p) {
    uint32_t a;
    asm("{ .reg .u64 t; cvta.to.shared.u64 t, %1; cvt.u32.u64 %0, t; }"
        : "=r"(a) : "l"(p));
    return a;
}
__device__ __forceinline__ void split4(float4 v, uint2& hi, uint2& lo) {
    float h0 = __bfloat162float(__float2bfloat16_rn(v.x));
    float h1 = __bfloat162float(__float2bfloat16_rn(v.y));
    float h2 = __bfloat162float(__float2bfloat16_rn(v.z));
    float h3 = __bfloat162float(__float2bfloat16_rn(v.w));
    __nv_bfloat162 ph0 = __floats2bfloat162_rn(h0, h1);
    __nv_bfloat162 ph1 = __floats2bfloat162_rn(h2, h3);
    __nv_bfloat162 pl0 = __floats2bfloat162_rn(v.x - h0, v.y - h1);
    __nv_bfloat162 pl1 = __floats2bfloat162_rn(v.z - h2, v.w - h3);
    hi.x = *(uint32_t*)&ph0; hi.y = *(uint32_t*)&ph1;
    lo.x = *(uint32_t*)&pl0; lo.y = *(uint32_t*)&pl1;
}
__device__ __forceinline__ void ldsm4(uint32_t* r, uint32_t addr) {
    asm volatile("ldmatrix.sync.aligned.m8n8.x4.shared.b16 {%0,%1,%2,%3}, [%4];"
                 : "=r"(r[0]), "=r"(r[1]), "=r"(r[2]), "=r"(r[3]) : "r"(addr));
}
__device__ __forceinline__ void mma_bf16(float* d, const uint32_t* a,
                                         uint32_t b0, uint32_t b1) {
    asm volatile(
        "mma.sync.aligned.m16n8k16.row.col.f32.bf16.bf16.f32 "
        "{%0,%1,%2,%3},{%4,%5,%6,%7},{%8,%9},{%0,%1,%2,%3};"
        : "+f"(d[0]), "+f"(d[1]), "+f"(d[2]), "+f"(d[3])
        : "r"(a[0]), "r"(a[1]), "r"(a[2]), "r"(a[3]), "r"(b0), "r"(b1));
}

// ---------------- split: fp32 -> bf16 hi/lo -----------------------------------
__global__ __launch_bounds__(256) void split_kernel(
    const float* __restrict__ src, __nv_bfloat16* __restrict__ hi,
    __nv_bfloat16* __restrict__ lo, int n4)
{
    int i = blockIdx.x * 256 + threadIdx.x;
    if (i >= n4) return;
    float4 v = ((const float4*)src)[i];
    uint2 h, l;
    split4(v, h, l);
    ((uint2*)hi)[i] = h;
    ((uint2*)lo)[i] = l;
}

// ---------------- bf16 3-pass compensated GEMM (unchanged from R6) ------------
#define A_H 0
#define A_L 16384
#define B_H 32768
#define B_L 65536
#define SMEM_GEMM 98304

__global__ __launch_bounds__(256) void gemm_bf16(
    const __nv_bfloat16* __restrict__ Ah, const __nv_bfloat16* __restrict__ Al,
    const float* __restrict__ W, const float* __restrict__ bias,
    float* __restrict__ C, int M, int N, int act)
{
    extern __shared__ __align__(1024) char smem[];
    const uint32_t sb = smem_u32(smem);
    const int tid = threadIdx.x;
    const int lane = tid & 31, wid = tid >> 5;
    const int gid = lane >> 2, tig = lane & 3;
    const int warpM = wid & 3, warpN = wid >> 2;
    const int m0 = blockIdx.y * 128, n0 = blockIdx.x * 64;

    #pragma unroll
    for (int it = 0; it < 16; it++) {
        int idx = tid + it * 256;
        int n = idx >> 6, c4 = idx & 63;
        float4 wv = *(const float4*)&W[(size_t)(n0 + n) * 256 + c4 * 4];
        uint2 hi, lo;
        split4(wv, hi, lo);
        uint32_t off = n * 512 + ((c4 >> 4) << 7) +
                       (((((c4 >> 1) & 7) ^ (n & 7))) << 4) + ((c4 & 1) << 3);
        *(uint2*)(smem + B_H + off) = hi;
        *(uint2*)(smem + B_L + off) = lo;
    }

    float acc[2][4][4];
    #pragma unroll
    for (int mt = 0; mt < 2; mt++)
        #pragma unroll
        for (int nt = 0; nt < 4; nt++)
            #pragma unroll
            for (int i = 0; i < 4; i++) acc[mt][nt][i] = 0.f;

    const uint4 z16 = make_uint4(0, 0, 0, 0);
    uint4 pah[4], pal[4];
    #pragma unroll
    for (int it = 0; it < 4; it++) {
        int idx = tid + it * 256;
        int row = idx >> 3, seg = idx & 7;
        int gr = m0 + row;
        pah[it] = (gr < M) ? *(const uint4*)&Ah[(size_t)gr * 256 + seg * 8] : z16;
        pal[it] = (gr < M) ? *(const uint4*)&Al[(size_t)gr * 256 + seg * 8] : z16;
    }

    const int a_row_in = ((lane >> 3) & 1) * 8 + (lane & 7);
    const int a_kseg   = (lane >> 4) & 1;
    const int b_row_in = ((lane >> 4) & 1) * 8 + (lane & 7);
    const int b_kseg   = (lane >> 3) & 1;

    for (int ch = 0; ch < 4; ch++) {
        __syncthreads();
        #pragma unroll
        for (int it = 0; it < 4; it++) {
            int idx = tid + it * 256;
            int row = idx >> 3, seg = idx & 7;
            uint32_t off = row * 128 + ((seg ^ (row & 7)) << 4);
            *(uint4*)(smem + A_H + off) = pah[it];
            *(uint4*)(smem + A_L + off) = pal[it];
        }
        __syncthreads();

        if (ch < 3) {
            #pragma unroll
            for (int it = 0; it < 4; it++) {
                int idx = tid + it * 256;
                int row = idx >> 3, seg = idx & 7;
                int gr = m0 + row;
                size_t gb = (size_t)gr * 256 + (ch + 1) * 64 + seg * 8;
                pah[it] = (gr < M) ? *(const uint4*)&Ah[gb] : z16;
                pal[it] = (gr < M) ? *(const uint4*)&Al[gb] : z16;
            }
        }

        #pragma unroll
        for (int s = 0; s < 4; s++) {
            uint32_t ah[2][4], al[2][4], bh[2][4], bl[2][4];
            #pragma unroll
            for (int mt = 0; mt < 2; mt++) {
                int r = warpM * 32 + mt * 16 + a_row_in;
                uint32_t off = r * 128 + (((s * 2 + a_kseg) ^ (r & 7)) << 4);
                ldsm4(ah[mt], sb + A_H + off);
                ldsm4(al[mt], sb + A_L + off);
            }
            #pragma unroll
            for (int np = 0; np < 2; np++) {
                int n = warpN * 32 + np * 16 + b_row_in;
                uint32_t off = n * 512 + ch * 128 +
                               (((s * 2 + b_kseg) ^ (n & 7)) << 4);
                ldsm4(bh[np], sb + B_H + off);
                ldsm4(bl[np], sb + B_L + off);
            }
            #pragma unroll
            for (int mt = 0; mt < 2; mt++)
                #pragma unroll
                for (int np = 0; np < 2; np++) {
                    float* dl = acc[mt][2 * np];
                    float* dh = acc[mt][2 * np + 1];
                    mma_bf16(dl, ah[mt], bh[np][0], bh[np][1]);
                    mma_bf16(dl, al[mt], bh[np][0], bh[np][1]);
                    mma_bf16(dl, ah[mt], bl[np][0], bl[np][1]);
                    mma_bf16(dh, ah[mt], bh[np][2], bh[np][3]);
                    mma_bf16(dh, al[mt], bh[np][2], bh[np][3]);
                    mma_bf16(dh, ah[mt], bl[np][2], bl[np][3]);
                }
        }
    }

    const bool donorm = (act == 2) && (n0 + warpN * 32) < 256;
    #pragma unroll
    for (int mt = 0; mt < 2; mt++) {
        int r0 = m0 + warpM * 32 + mt * 16 + gid;
        int r1 = r0 + 8;
        float v0[4][2], v1[4][2];
        #pragma unroll
        for (int nt = 0; nt < 4; nt++) {
            int cb = n0 + warpN * 32 + nt * 8 + 2 * tig;
            float b0 = bias[cb], b1 = bias[cb + 1];
            v0[nt][0] = acc[mt][nt][0] + b0; v0[nt][1] = acc[mt][nt][1] + b1;
            v1[nt][0] = acc[mt][nt][2] + b0; v1[nt][1] = acc[mt][nt][3] + b1;
        }
        if (act == 1) {
            #pragma unroll
            for (int nt = 0; nt < 4; nt++)
                #pragma unroll
                for (int i = 0; i < 2; i++) {
                    v0[nt][i] = 0.5f * v0[nt][i] *
                                (1.f + erff(v0[nt][i] * 0.70710678118654752f));
                    v1[nt][i] = 0.5f * v1[nt][i] *
                                (1.f + erff(v1[nt][i] * 0.70710678118654752f));
                }
        } else if (donorm) {
            float ss0 = 0.f, ss1 = 0.f;
            #pragma unroll
            for (int nt = 0; nt < 4; nt++) {
                ss0 += v0[nt][0] * v0[nt][0] + v0[nt][1] * v0[nt][1];
                ss1 += v1[nt][0] * v1[nt][0] + v1[nt][1] * v1[nt][1];
            }
            ss0 += __shfl_xor_sync(0xffffffffu, ss0, 1);
            ss0 += __shfl_xor_sync(0xffffffffu, ss0, 2);
            ss1 += __shfl_xor_sync(0xffffffffu, ss1, 1);
            ss1 += __shfl_xor_sync(0xffffffffu, ss1, 2);
            float inv0 = 1.f / fmaxf(sqrtf(ss0), 1e-12f);
            float inv1 = 1.f / fmaxf(sqrtf(ss1), 1e-12f);
            #pragma unroll
            for (int nt = 0; nt < 4; nt++) {
                v0[nt][0] *= inv0; v0[nt][1] *= inv0;
                v1[nt][0] *= inv1; v1[nt][1] *= inv1;
            }
        }
        #pragma unroll
        for (int nt = 0; nt < 4; nt++) {
            int cb = n0 + warpN * 32 + nt * 8 + 2 * tig;
            if (r0 < M)
                *(float2*)&C[(size_t)r0 * N + cb] = make_float2(v0[nt][0], v0[nt][1]);
            if (r1 < M)
                *(float2*)&C[(size_t)r1 * N + cb] = make_float2(v1[nt][0], v1[nt][1]);
        }
    }
}

// ---------------- 4x4 average pool + layernorm over C ------------------------
__global__ __launch_bounds__(256) void pool_ln_kernel(
    const float* __restrict__ xsr, const float* __restrict__ gam,
    const float* __restrict__ bet, float* __restrict__ xpool)
{
    int bp = blockIdx.x;
    int b = bp / PL, p = bp % PL;
    int ph = p / 14, pw = p % 14;
    int c = threadIdx.x;

    float s = 0.f;
    #pragma unroll
    for (int i = 0; i < 4; i++)
        #pragma unroll
        for (int j = 0; j < 4; j++) {
            int n = (ph * 4 + i) * IMW + pw * 4 + j;
            s += xsr[((size_t)b * NN + n) * CC + c];
        }
    s *= (1.f / 16.f);

    __shared__ float r1[256], r2[256];
    r1[c] = s;
    r2[c] = s * s;
    __syncthreads();
    for (int st = 128; st > 0; st >>= 1) {
        if (c < st) { r1[c] += r1[c + st]; r2[c] += r2[c + st]; }
        __syncthreads();
    }
    float mean = r1[0] * (1.f / 256.f);
    float var  = r2[0] * (1.f / 256.f) - mean * mean;
    float invs = rsqrtf(var + 1e-5f);
    xpool[(size_t)bp * CC + c] = (s - mean) * invs * gam[c] + bet[c];
}

// ---------------- CPB table ----------------------------------------------------
__global__ __launch_bounds__(256) void tab_kernel(
    const float* __restrict__ rct, const float* __restrict__ w1,
    const float* __restrict__ b1, const float* __restrict__ w2,
    const float* __restrict__ b2, float* __restrict__ tab)
{
    int t = blockIdx.x;
    __shared__ float sh[512];
    float c0 = rct[t * 2], c1 = rct[t * 2 + 1];
    for (int j = threadIdx.x; j < 512; j += 256)
        sh[j] = fmaxf(0.f, c0 * w1[j * 2] + c1 * w1[j * 2 + 1] + b1[j]);
    __syncthreads();
    int w = threadIdx.x >> 5, lane = threadIdx.x & 31;
    float s = 0.f;
    for (int j = lane; j < 512; j += 32) s += sh[j] * w2[w * 512 + j];
    #pragma unroll
    for (int o = 16; o > 0; o >>= 1) s += __shfl_xor_sync(0xffffffffu, s, o);
    if (lane == 0) tab[t * 8 + w] = s + b2[w];
}

// ---------------- MMA attention ------------------------------------------------
// grid (49, 8, 4); 256 threads; 64 query rows per block; one (b,h) per block.
// smem byte offsets:
#define SP_OFF   0        // logits fp32 [64][228]  (later probs bf16 hi@col0, lo@col232 of 456)
#define SKH_OFF  58368    // K_pool hi bf16 [224][40]
#define SKL_OFF  76288    // K_pool lo
#define SVTH_OFF 94208    // V^T hi bf16 [32][216]
#define SVTL_OFF 108032   // V^T lo
#define SQH_OFF  121856   // q_scaled hi bf16 [64][40]
#define SQL_OFF  126976   // q_scaled lo
#define SQS_OFF  132096   // q_scaled fp32 [64][33]  (reused as output accum sO)
#define SQN_OFF  140544   // q_norm fp32 [64][33]
#define SLOC_OFF 148992   // local weights [64][12]
#define SMEM_ATTN 152064

__global__ __launch_bounds__(256) void attn_mma(
    const float* __restrict__ q, const float* __restrict__ qe,
    const float* __restrict__ temp, const float* __restrict__ sls,
    const float* __restrict__ kv, const float* __restrict__ kvp,
    const float* __restrict__ tab, const int* __restrict__ rpi,
    const float* __restrict__ rpb, const float* __restrict__ ltok,
    const float* __restrict__ lbias, float* __restrict__ out)
{
    extern __shared__ __align__(1024) char smem[];
    const uint32_t sb = smem_u32(smem);
    float* sP   = (float*)(smem + SP_OFF);
    float* sQs  = (float*)(smem + SQS_OFF);
    float* sQn  = (float*)(smem + SQN_OFF);
    float* sLoc = (float*)(smem + SLOC_OFF);

    const int b = blockIdx.z, h = blockIdx.y;
    const int n0 = blockIdx.x * 64;
    const int tid = threadIdx.x, lane = tid & 31, wid = tid >> 5;
    const int gid = lane >> 2, tig = lane & 3;

    // ---- stage K_pool (196 rows + zero pad to 224), bf16 hi/lo, stride 40 ----
    for (int i = tid; i < 224 * 8; i += 256) {
        int m = i >> 3, c = i & 7;
        uint2 hi = make_uint2(0, 0), lo = make_uint2(0, 0);
        if (m < PL) {
            float4 k4 = *(const float4*)&kvp[((size_t)(b * PL + m)) * 512 + h * HD + c * 4];
            split4(k4, hi, lo);
        }
        *(uint2*)(smem + SKH_OFF + m * 80 + c * 8) = hi;
        *(uint2*)(smem + SKL_OFF + m * 80 + c * 8) = lo;
    }
    // ---- stage V^T bf16 hi/lo [d=32][k=216], stride 216 bf16 = 432 B ----
    for (int i = tid; i < PL * 8; i += 256) {
        int m = i >> 3, c = i & 7;
        float4 v4 = *(const float4*)&kvp[((size_t)(b * PL + m)) * 512 + 256 + h * HD + c * 4];
        float vv[4] = {v4.x, v4.y, v4.z, v4.w};
        #pragma unroll
        for (int j = 0; j < 4; j++) {
            int d = c * 4 + j;
            __nv_bfloat16 hb = __float2bfloat16_rn(vv[j]);
            *(__nv_bfloat16*)(smem + SVTH_OFF + d * 432 + m * 2) = hb;
            *(__nv_bfloat16*)(smem + SVTL_OFF + d * 432 + m * 2) =
                __float2bfloat16_rn(vv[j] - __bfloat162float(hb));
        }
    }
    // zero V^T pad cols 196..215
    for (int i = tid; i < 32 * 20; i += 256) {
        int d = i / 20, kk = 196 + i % 20;
        *(__nv_bfloat16*)(smem + SVTH_OFF + d * 432 + kk * 2) = __float2bfloat16(0.f);
        *(__nv_bfloat16*)(smem + SVTL_OFF + d * 432 + kk * 2) = __float2bfloat16(0.f);
    }
    // ---- stage q: norm + scale, fp32 & bf16 hi/lo ----
    {
        float sp = log1pf(expf(temp[h]));
        float qev = qe[h * HD + lane];
        for (int i = 0; i < 8; i++) {
            int row = wid * 8 + i;
            int n = n0 + row;
            float val = q[((size_t)(b * NN + n)) * CC + h * HD + lane];
            float ss = val * val;
            #pragma unroll
            for (int o = 16; o > 0; o >>= 1) ss += __shfl_xor_sync(0xffffffffu, ss, o);
            float inv = 1.f / fmaxf(sqrtf(ss), 1e-12f);
            float qnv = val * inv;
            float qsv = (qnv + qev) * sp * sls[n];
            sQs[row * 33 + lane] = qsv;
            sQn[row * 33 + lane] = qnv;
            __nv_bfloat16 hb = __float2bfloat16_rn(qsv);
            *(__nv_bfloat16*)(smem + SQH_OFF + row * 80 + lane * 2) = hb;
            *(__nv_bfloat16*)(smem + SQL_OFF + row * 80 + lane * 2) =
                __float2bfloat16_rn(qsv - __bfloat162float(hb));
        }
    }
    __syncthreads();

    const int warpM = wid & 3, warpN = wid >> 2;
    const int a_row = ((lane >> 3) & 1) * 8 + (lane & 7);
    const int a_ks  = (lane >> 4) & 1;
    const int b_row = ((lane >> 4) & 1) * 8 + (lane & 7);
    const int b_ks  = (lane >> 3) & 1;

    // ---- phase 1: pooled logits = Qs @ K^T via 3-pass bf16 MMA ----
    {
        float acc[7][2][4];
        #pragma unroll
        for (int nt = 0; nt < 7; nt++)
            #pragma unroll
            for (int np = 0; np < 2; np++)
                #pragma unroll
                for (int i = 0; i < 4; i++) acc[nt][np][i] = 0.f;

        #pragma unroll
        for (int s = 0; s < 2; s++) {
            uint32_t ah[4], al[4];
            {
                int r = warpM * 16 + a_row;
                uint32_t off = SQH_OFF + r * 80 + (s * 2 + a_ks) * 16;
                ldsm4(ah, sb + off);
                ldsm4(al, sb + off + (SQL_OFF - SQH_OFF));
            }
            #pragma unroll
            for (int nt = 0; nt < 7; nt++) {
                int nr = warpN * 112 + nt * 16 + b_row;
                uint32_t off = SKH_OFF + nr * 80 + (s * 2 + b_ks) * 16;
                uint32_t bh[4], bl[4];
                ldsm4(bh, sb + off);
                ldsm4(bl, sb + off + (SKL_OFF - SKH_OFF));
                #pragma unroll
                for (int np = 0; np < 2; np++) {
                    float* d = acc[nt][np];
                    mma_bf16(d, ah, bh[np * 2], bh[np * 2 + 1]);
                    mma_bf16(d, al, bh[np * 2], bh[np * 2 + 1]);
                    mma_bf16(d, ah, bl[np * 2], bl[np * 2 + 1]);
                }
            }
        }
        int r0 = warpM * 16 + gid;
        #pragma unroll
        for (int nt = 0; nt < 7; nt++)
            #pragma unroll
            for (int np = 0; np < 2; np++) {
                int colb = warpN * 112 + nt * 16 + np * 8 + 2 * tig;
                *(float2*)&sP[r0 * 228 + colb] =
                    make_float2(acc[nt][np][0], acc[nt][np][1]);
                *(float2*)&sP[(r0 + 8) * 228 + colb] =
                    make_float2(acc[nt][np][2], acc[nt][np][3]);
            }
    }
    __syncthreads();

    // ---- phase 2: scalar per-row — local logits, bias gather, softmax -------
    for (int i = 0; i < 8; i++) {
        int row = wid * 8 + i;
        int n = n0 + row;
        int rr = n / IMW, cc2 = n % IMW;
        float* Pr = &sP[row * 228];
        const float* Qs = &sQs[row * 33];
        const int* rp = rpi + (size_t)n * PL;

        float aloc = -3.4e38f;
        if (lane < 9) {
            int di = lane / 3 - 1, dj = lane % 3 - 1;
            int r2 = rr + di, c3 = cc2 + dj;
            if (r2 >= 0 && r2 < IMH && c3 >= 0 && c3 < IMW) {
                int nb = r2 * IMW + c3;
                const float4* kr =
                    (const float4*)(kv + ((size_t)(b * NN + nb)) * 512 + h * HD);
                float s2 = 0.f;
                #pragma unroll
                for (int d4 = 0; d4 < 8; d4++) {
                    float4 t = kr[d4];
                    s2 += Qs[d4*4+0]*t.x + Qs[d4*4+1]*t.y
                        + Qs[d4*4+2]*t.z + Qs[d4*4+3]*t.w;
                }
                aloc = s2 + rpb[h * 9 + lane];
            }
        }

        float e[7];
        float mx = -3.4e38f;
        #pragma unroll
        for (int t = 0; t < 7; t++) {
            int j = lane + 32 * t;
            if (j < PL) {
                float v = Pr[j] + tab[rp[j] * 8 + h];
                e[t] = v;
                mx = fmaxf(mx, v);
            } else e[t] = -3.4e38f;
        }
        if (lane < 9) mx = fmaxf(mx, aloc);
        #pragma unroll
        for (int o = 16; o > 0; o >>= 1)
            mx = fmaxf(mx, __shfl_xor_sync(0xffffffffu, mx, o));

        float sum = 0.f;
        #pragma unroll
        for (int t = 0; t < 7; t++) {
            int j = lane + 32 * t;
            if (j < PL) { e[t] = __expf(e[t] - mx); sum += e[t]; }
        }
        float el = 0.f;
        if (lane < 9) { el = __expf(aloc - mx); sum += el; }
        #pragma unroll
        for (int o = 16; o > 0; o >>= 1) sum += __shfl_xor_sync(0xffffffffu, sum, o);
        float inv = 1.f / sum;

        // write probs bf16 hi/lo in place (reads already in regs)
        __nv_bfloat16* Ph = (__nv_bfloat16*)Pr;        // cols 0..215
        __nv_bfloat16* Pl2 = Ph + 232;                  // 16B-aligned lo block
        #pragma unroll
        for (int t = 0; t < 7; t++) {
            int j = lane + 32 * t;
            if (j < PL) {
                float p = e[t] * inv;
                __nv_bfloat16 hb = __float2bfloat16_rn(p);
                Ph[j] = hb;
                Pl2[j] = __float2bfloat16_rn(p - __bfloat162float(hb));
            }
        }
        if (lane < 12) {
            Ph[PL + lane] = __float2bfloat16(0.f);
            Pl2[PL + lane] = __float2bfloat16(0.f);
        }
        if (lane < 9) {
            const float* Qn = &sQn[row * 33];
            float s2 = 0.f;
            #pragma unroll
            for (int d = 0; d < 32; d++)
                s2 += Qn[d] * ltok[(h * 32 + d) * 9 + lane];
            sLoc[row * 12 + lane] = s2 + lbias[h * 9 + lane] + el * inv;
        }
    }
    __syncthreads();

    // ---- phase 3: pooled output = P @ V via 3-pass bf16 MMA ----
    {
        float acc[2][4];
        #pragma unroll
        for (int np = 0; np < 2; np++)
            #pragma unroll
            for (int i = 0; i < 4; i++) acc[np][i] = 0.f;

        #pragma unroll
        for (int kt = 0; kt < 13; kt++) {
            uint32_t ah[4], al[4], bh[4], bl[4];
            int r = warpM * 16 + a_row;
            uint32_t offA = SP_OFF + r * 912 + (kt * 2 + a_ks) * 16;
            ldsm4(ah, sb + offA);
            ldsm4(al, sb + offA + 464);
            int nr = warpN * 16 + b_row;
            uint32_t offB = SVTH_OFF + nr * 432 + (kt * 2 + b_ks) * 16;
            ldsm4(bh, sb + offB);
            ldsm4(bl, sb + offB + (SVTL_OFF - SVTH_OFF));
            #pragma unroll
            for (int np = 0; np < 2; np++) {
                float* d = acc[np];
                mma_bf16(d, ah, bh[np * 2], bh[np * 2 + 1]);
                mma_bf16(d, al, bh[np * 2], bh[np * 2 + 1]);
                mma_bf16(d, ah, bl[np * 2], bl[np * 2 + 1]);
            }
        }
        float* sO = sQs;  // reuse (q_scaled fp32 no longer needed)
        int r0 = warpM * 16 + gid;
        #pragma unroll
        for (int np = 0; np < 2; np++) {
            int colb = warpN * 16 + np * 8 + 2 * tig;
            sO[r0 * 33 + colb]       = acc[np][0];
            sO[r0 * 33 + colb + 1]   = acc[np][1];
            sO[(r0+8) * 33 + colb]     = acc[np][2];
            sO[(r0+8) * 33 + colb + 1] = acc[np][3];
        }
    }
    __syncthreads();

    // ---- phase 4: add local-V contribution and store ----
    for (int i = 0; i < 8; i++) {
        int row = wid * 8 + i;
        int n = n0 + row;
        int rr = n / IMW, cc2 = n % IMW;
        float o = sQs[row * 33 + lane];
        #pragma unroll
        for (int l = 0; l < 9; l++) {
            int r2 = rr + l / 3 - 1, c3 = cc2 + l % 3 - 1;
            if (r2 >= 0 && r2 < IMH && c3 >= 0 && c3 < IMW) {
                int nb = r2 * IMW + c3;
                o += sLoc[row * 12 + l] *
                     kv[((size_t)(b * NN + nb)) * 512 + 256 + h * HD + lane];
            }
        }
        out[((size_t)(b * NN) + n) * CC + h * HD + lane] = o;
    }
}

// -----------------------------------------------------------------------------
extern "C" void kernel_launch(void* const* d_in, const int* in_sizes, int n_in,
                              void* d_out, int out_size)
{
    const float* x      = (const float*)d_in[0];
    const int*   rpi    = (const int*)  d_in[3];
    const float* rct    = (const float*)d_in[4];
    const float* sls    = (const float*)d_in[5];
    const float* q_w    = (const float*)d_in[7];
    const float* q_b    = (const float*)d_in[8];
    const float* kv_w   = (const float*)d_in[9];
    const float* kv_b   = (const float*)d_in[10];
    const float* sr_w   = (const float*)d_in[11];
    const float* sr_b   = (const float*)d_in[12];
    const float* norm_g = (const float*)d_in[13];
    const float* norm_b = (const float*)d_in[14];
    const float* cpb1_w = (const float*)d_in[15];
    const float* cpb1_b = (const float*)d_in[16];
    const float* cpb2_w = (const float*)d_in[17];
    const float* cpb2_b = (const float*)d_in[18];
    const float* temp   = (const float*)d_in[19];
    const float* qe     = (const float*)d_in[20];
    const float* rpb    = (const float*)d_in[21];
    const float* ltok   = (const float*)d_in[22];
    const float* lbias  = (const float*)d_in[23];
    const float* proj_w = (const float*)d_in[24];
    const float* proj_b = (const float*)d_in[25];
    float* out = (float*)d_out;

    float *p_q, *p_kv, *p_xsr, *p_xpl, *p_kvp, *p_tab, *p_att;
    __nv_bfloat16 *p_xh, *p_xl, *p_xph, *p_xpL, *p_ath, *p_atl;
    cudaGetSymbolAddress((void**)&p_q,   g_q);
    cudaGetSymbolAddress((void**)&p_kv,  g_kv);
    cudaGetSymbolAddress((void**)&p_xsr, g_xsr);
    cudaGetSymbolAddress((void**)&p_xpl, g_xpl);
    cudaGetSymbolAddress((void**)&p_kvp, g_kvp);
    cudaGetSymbolAddress((void**)&p_tab, g_tab);
    cudaGetSymbolAddress((void**)&p_att, g_att);
    cudaGetSymbolAddress((void**)&p_xh,  g_xh);
    cudaGetSymbolAddress((void**)&p_xl,  g_xl);
    cudaGetSymbolAddress((void**)&p_xph, g_xph);
    cudaGetSymbolAddress((void**)&p_xpL, g_xpL);
    cudaGetSymbolAddress((void**)&p_ath, g_ath);
    cudaGetSymbolAddress((void**)&p_atl, g_atl);

    const int M = BZ * NN;  // 12544 = 98 * 128
    const int MP = BZ * PL; // 784

    cudaFuncSetAttribute(gemm_bf16, cudaFuncAttributeMaxDynamicSharedMemorySize,
                         SMEM_GEMM);
    cudaFuncSetAttribute(attn_mma, cudaFuncAttributeMaxDynamicSharedMemorySize,
                         SMEM_ATTN);

    // split x -> bf16 hi/lo (shared by q, kv, sr GEMMs)
    split_kernel<<<(M * CC / 4 + 255) / 256, 256>>>(x, p_xh, p_xl, M * CC / 4);

    // main GEMMs
    gemm_bf16<<<dim3(4, 98), 256, SMEM_GEMM>>>(p_xh, p_xl, q_w,  q_b,  p_q,   M, 256, 0);
    gemm_bf16<<<dim3(8, 98), 256, SMEM_GEMM>>>(p_xh, p_xl, kv_w, kv_b, p_kv,  M, 512, 2);
    gemm_bf16<<<dim3(4, 98), 256, SMEM_GEMM>>>(p_xh, p_xl, sr_w, sr_b, p_xsr, M, 256, 1);

    // pooled path
    pool_ln_kernel<<<BZ * PL, 256>>>(p_xsr, norm_g, norm_b, p_xpl);
    split_kernel<<<(MP * CC / 4 + 255) / 256, 256>>>(p_xpl, p_xph, p_xpL, MP * CC / 4);
    gemm_bf16<<<dim3(8, 7), 256, SMEM_GEMM>>>(p_xph, p_xpL, kv_w, kv_b, p_kvp, MP, 512, 2);

    // CPB bias table
    tab_kernel<<<KTAB, 256>>>(rct, cpb1_w, cpb1_b, cpb2_w, cpb2_b, p_tab);

    // MMA attention
    attn_mma<<<dim3(NN / 64, HH, BZ), 256, SMEM_ATTN>>>(
        p_q, qe, temp, sls, p_kv, p_kvp, p_tab, rpi, rpb, ltok, lbias, p_att);

    // output projection
    split_kernel<<<(M * CC / 4 + 255) / 256, 256>>>(p_att, p_ath, p_atl, M * CC / 4);
    gemm_bf16<<<dim3(4, 98), 256, SMEM_GEMM>>>(p_ath, p_atl, proj_w, proj_b, out, M, 256, 0);
}

// round 10
// speedup vs baseline: 2.0287x; 1.0517x over previous
#include <cuda_runtime.h>
#include <cuda_bf16.h>
#include <math.h>
#include <stdint.h>

// Problem constants
#define BZ 4
#define NN 3136
#define CC 256
#define HH 8
#define HD 32
#define PL 196
#define IMH 56
#define IMW 56
#define KTAB 2048

// ---------------- scratch (device globals; no allocation allowed) -------------
__device__ float g_q   [BZ * NN * CC];
__device__ float g_kv  [BZ * NN * 512];
__device__ float g_xsr [BZ * NN * CC];
__device__ float g_xpl [BZ * PL * CC];
__device__ float g_kvp [BZ * PL * 512];
__device__ float g_tab [KTAB * HH];
// bf16 hi/lo split inputs
__device__ __nv_bfloat16 g_xh  [BZ * NN * CC];
__device__ __nv_bfloat16 g_xl  [BZ * NN * CC];
__device__ __nv_bfloat16 g_xph [BZ * PL * CC];
__device__ __nv_bfloat16 g_xpL [BZ * PL * CC];
__device__ __nv_bfloat16 g_ath [BZ * NN * CC];
__device__ __nv_bfloat16 g_atl [BZ * NN * CC];

// ---------------- helpers ------------------------------------------------------
__device__ __forceinline__ uint32_t smem_u32(const void* p) {
    uint32_t a;
    asm("{ .reg .u64 t; cvta.to.shared.u64 t, %1; cvt.u32.u64 %0, t; }"
        : "=r"(a) : "l"(p));
    return a;
}
__device__ __forceinline__ void split4(float4 v, uint2& hi, uint2& lo) {
    float h0 = __bfloat162float(__float2bfloat16_rn(v.x));
    float h1 = __bfloat162float(__float2bfloat16_rn(v.y));
    float h2 = __bfloat162float(__float2bfloat16_rn(v.z));
    float h3 = __bfloat162float(__float2bfloat16_rn(v.w));
    __nv_bfloat162 ph0 = __floats2bfloat162_rn(h0, h1);
    __nv_bfloat162 ph1 = __floats2bfloat162_rn(h2, h3);
    __nv_bfloat162 pl0 = __floats2bfloat162_rn(v.x - h0, v.y - h1);
    __nv_bfloat162 pl1 = __floats2bfloat162_rn(v.z - h2, v.w - h3);
    hi.x = *(uint32_t*)&ph0; hi.y = *(uint32_t*)&ph1;
    lo.x = *(uint32_t*)&pl0; lo.y = *(uint32_t*)&pl1;
}
__device__ __forceinline__ void ldsm4(uint32_t* r, uint32_t addr) {
    asm volatile("ldmatrix.sync.aligned.m8n8.x4.shared.b16 {%0,%1,%2,%3}, [%4];"
                 : "=r"(r[0]), "=r"(r[1]), "=r"(r[2]), "=r"(r[3]) : "r"(addr));
}
__device__ __forceinline__ void mma_bf16(float* d, const uint32_t* a,
                                         uint32_t b0, uint32_t b1) {
    asm volatile(
        "mma.sync.aligned.m16n8k16.row.col.f32.bf16.bf16.f32 "
        "{%0,%1,%2,%3},{%4,%5,%6,%7},{%8,%9},{%0,%1,%2,%3};"
        : "+f"(d[0]), "+f"(d[1]), "+f"(d[2]), "+f"(d[3])
        : "r"(a[0]), "r"(a[1]), "r"(a[2]), "r"(a[3]), "r"(b0), "r"(b1));
}

// ---------------- split: fp32 -> bf16 hi/lo -----------------------------------
__global__ __launch_bounds__(256) void split_kernel(
    const float* __restrict__ src, __nv_bfloat16* __restrict__ hi,
    __nv_bfloat16* __restrict__ lo, int n4)
{
    int i = blockIdx.x * 256 + threadIdx.x;
    if (i >= n4) return;
    float4 v = ((const float4*)src)[i];
    uint2 h, l;
    split4(v, h, l);
    ((uint2*)hi)[i] = h;
    ((uint2*)lo)[i] = l;
}

// ---------------- bf16 3-pass GEMM core (device function) ----------------------
#define A_H 0
#define A_L 16384
#define B_H 32768
#define B_L 65536
#define SMEM_GEMM 98304

__device__ __forceinline__ void gemm_body(
    char* smem, const __nv_bfloat16* __restrict__ Ah,
    const __nv_bfloat16* __restrict__ Al, const float* __restrict__ W,
    const float* __restrict__ bias, float* __restrict__ C,
    int M, int N, int act, int m0, int n0)
{
    const uint32_t sb = smem_u32(smem);
    const int tid = threadIdx.x;
    const int lane = tid & 31, wid = tid >> 5;
    const int gid = lane >> 2, tig = lane & 3;
    const int warpM = wid & 3, warpN = wid >> 2;

    #pragma unroll
    for (int it = 0; it < 16; it++) {
        int idx = tid + it * 256;
        int n = idx >> 6, c4 = idx & 63;
        float4 wv = *(const float4*)&W[(size_t)(n0 + n) * 256 + c4 * 4];
        uint2 hi, lo;
        split4(wv, hi, lo);
        uint32_t off = n * 512 + ((c4 >> 4) << 7) +
                       (((((c4 >> 1) & 7) ^ (n & 7))) << 4) + ((c4 & 1) << 3);
        *(uint2*)(smem + B_H + off) = hi;
        *(uint2*)(smem + B_L + off) = lo;
    }

    float acc[2][4][4];
    #pragma unroll
    for (int mt = 0; mt < 2; mt++)
        #pragma unroll
        for (int nt = 0; nt < 4; nt++)
            #pragma unroll
            for (int i = 0; i < 4; i++) acc[mt][nt][i] = 0.f;

    const uint4 z16 = make_uint4(0, 0, 0, 0);
    uint4 pah[4], pal[4];
    #pragma unroll
    for (int it = 0; it < 4; it++) {
        int idx = tid + it * 256;
        int row = idx >> 3, seg = idx & 7;
        int gr = m0 + row;
        pah[it] = (gr < M) ? *(const uint4*)&Ah[(size_t)gr * 256 + seg * 8] : z16;
        pal[it] = (gr < M) ? *(const uint4*)&Al[(size_t)gr * 256 + seg * 8] : z16;
    }

    const int a_row_in = ((lane >> 3) & 1) * 8 + (lane & 7);
    const int a_kseg   = (lane >> 4) & 1;
    const int b_row_in = ((lane >> 4) & 1) * 8 + (lane & 7);
    const int b_kseg   = (lane >> 3) & 1;

    for (int ch = 0; ch < 4; ch++) {
        __syncthreads();
        #pragma unroll
        for (int it = 0; it < 4; it++) {
            int idx = tid + it * 256;
            int row = idx >> 3, seg = idx & 7;
            uint32_t off = row * 128 + ((seg ^ (row & 7)) << 4);
            *(uint4*)(smem + A_H + off) = pah[it];
            *(uint4*)(smem + A_L + off) = pal[it];
        }
        __syncthreads();

        if (ch < 3) {
            #pragma unroll
            for (int it = 0; it < 4; it++) {
                int idx = tid + it * 256;
                int row = idx >> 3, seg = idx & 7;
                int gr = m0 + row;
                size_t gb = (size_t)gr * 256 + (ch + 1) * 64 + seg * 8;
                pah[it] = (gr < M) ? *(const uint4*)&Ah[gb] : z16;
                pal[it] = (gr < M) ? *(const uint4*)&Al[gb] : z16;
            }
        }

        #pragma unroll
        for (int s = 0; s < 4; s++) {
            uint32_t ah[2][4], al[2][4], bh[2][4], bl[2][4];
            #pragma unroll
            for (int mt = 0; mt < 2; mt++) {
                int r = warpM * 32 + mt * 16 + a_row_in;
                uint32_t off = r * 128 + (((s * 2 + a_kseg) ^ (r & 7)) << 4);
                ldsm4(ah[mt], sb + A_H + off);
                ldsm4(al[mt], sb + A_L + off);
            }
            #pragma unroll
            for (int np = 0; np < 2; np++) {
                int n = warpN * 32 + np * 16 + b_row_in;
                uint32_t off = n * 512 + ch * 128 +
                               (((s * 2 + b_kseg) ^ (n & 7)) << 4);
                ldsm4(bh[np], sb + B_H + off);
                ldsm4(bl[np], sb + B_L + off);
            }
            #pragma unroll
            for (int mt = 0; mt < 2; mt++)
                #pragma unroll
                for (int np = 0; np < 2; np++) {
                    float* dl = acc[mt][2 * np];
                    float* dh = acc[mt][2 * np + 1];
                    mma_bf16(dl, ah[mt], bh[np][0], bh[np][1]);
                    mma_bf16(dl, al[mt], bh[np][0], bh[np][1]);
                    mma_bf16(dl, ah[mt], bl[np][0], bl[np][1]);
                    mma_bf16(dh, ah[mt], bh[np][2], bh[np][3]);
                    mma_bf16(dh, al[mt], bh[np][2], bh[np][3]);
                    mma_bf16(dh, ah[mt], bl[np][2], bl[np][3]);
                }
        }
    }

    const bool donorm = (act == 2) && (n0 + warpN * 32) < 256;
    #pragma unroll
    for (int mt = 0; mt < 2; mt++) {
        int r0 = m0 + warpM * 32 + mt * 16 + gid;
        int r1 = r0 + 8;
        float v0[4][2], v1[4][2];
        #pragma unroll
        for (int nt = 0; nt < 4; nt++) {
            int cb = n0 + warpN * 32 + nt * 8 + 2 * tig;
            float b0 = bias[cb], b1 = bias[cb + 1];
            v0[nt][0] = acc[mt][nt][0] + b0; v0[nt][1] = acc[mt][nt][1] + b1;
            v1[nt][0] = acc[mt][nt][2] + b0; v1[nt][1] = acc[mt][nt][3] + b1;
        }
        if (act == 1) {
            #pragma unroll
            for (int nt = 0; nt < 4; nt++)
                #pragma unroll
                for (int i = 0; i < 2; i++) {
                    v0[nt][i] = 0.5f * v0[nt][i] *
                                (1.f + erff(v0[nt][i] * 0.70710678118654752f));
                    v1[nt][i] = 0.5f * v1[nt][i] *
                                (1.f + erff(v1[nt][i] * 0.70710678118654752f));
                }
        } else if (donorm) {
            float ss0 = 0.f, ss1 = 0.f;
            #pragma unroll
            for (int nt = 0; nt < 4; nt++) {
                ss0 += v0[nt][0] * v0[nt][0] + v0[nt][1] * v0[nt][1];
                ss1 += v1[nt][0] * v1[nt][0] + v1[nt][1] * v1[nt][1];
            }
            ss0 += __shfl_xor_sync(0xffffffffu, ss0, 1);
            ss0 += __shfl_xor_sync(0xffffffffu, ss0, 2);
            ss1 += __shfl_xor_sync(0xffffffffu, ss1, 1);
            ss1 += __shfl_xor_sync(0xffffffffu, ss1, 2);
            float inv0 = 1.f / fmaxf(sqrtf(ss0), 1e-12f);
            float inv1 = 1.f / fmaxf(sqrtf(ss1), 1e-12f);
            #pragma unroll
            for (int nt = 0; nt < 4; nt++) {
                v0[nt][0] *= inv0; v0[nt][1] *= inv0;
                v1[nt][0] *= inv1; v1[nt][1] *= inv1;
            }
        }
        #pragma unroll
        for (int nt = 0; nt < 4; nt++) {
            int cb = n0 + warpN * 32 + nt * 8 + 2 * tig;
            if (r0 < M)
                *(float2*)&C[(size_t)r0 * N + cb] = make_float2(v0[nt][0], v0[nt][1]);
            if (r1 < M)
                *(float2*)&C[(size_t)r1 * N + cb] = make_float2(v1[nt][0], v1[nt][1]);
        }
    }
}

// plain GEMM (proj, kvp)
__global__ __launch_bounds__(256) void gemm_bf16(
    const __nv_bfloat16* __restrict__ Ah, const __nv_bfloat16* __restrict__ Al,
    const float* __restrict__ W, const float* __restrict__ bias,
    float* __restrict__ C, int M, int N, int act)
{
    extern __shared__ __align__(1024) char smem[];
    gemm_body(smem, Ah, Al, W, bias, C, M, N, act,
              blockIdx.y * 128, blockIdx.x * 64);
}

// fused q/kv/sr GEMM: 16 column-blocks -> segments [q:0-3][kv:4-11][sr:12-15]
__global__ __launch_bounds__(256) void gemm_qkvsr(
    const __nv_bfloat16* __restrict__ Ah, const __nv_bfloat16* __restrict__ Al,
    const float* __restrict__ q_w, const float* __restrict__ q_b,
    const float* __restrict__ kv_w, const float* __restrict__ kv_b,
    const float* __restrict__ sr_w, const float* __restrict__ sr_b,
    float* __restrict__ Cq, float* __restrict__ Ckv, float* __restrict__ Cxsr,
    int M)
{
    extern __shared__ __align__(1024) char smem[];
    const int bx = blockIdx.x;
    const float *W, *bias;
    float* C;
    int N, n0, act;
    if (bx < 4)       { W = q_w;  bias = q_b;  C = Cq;   N = 256; n0 = bx * 64;        act = 0; }
    else if (bx < 12) { W = kv_w; bias = kv_b; C = Ckv;  N = 512; n0 = (bx - 4) * 64;  act = 2; }
    else              { W = sr_w; bias = sr_b; C = Cxsr; N = 256; n0 = (bx - 12) * 64; act = 1; }
    gemm_body(smem, Ah, Al, W, bias, C, M, N, act, blockIdx.y * 128, n0);
}

// ---------------- 4x4 average pool + layernorm over C ------------------------
__global__ __launch_bounds__(256) void pool_ln_kernel(
    const float* __restrict__ xsr, const float* __restrict__ gam,
    const float* __restrict__ bet, float* __restrict__ xpool)
{
    int bp = blockIdx.x;
    int b = bp / PL, p = bp % PL;
    int ph = p / 14, pw = p % 14;
    int c = threadIdx.x;

    float s = 0.f;
    #pragma unroll
    for (int i = 0; i < 4; i++)
        #pragma unroll
        for (int j = 0; j < 4; j++) {
            int n = (ph * 4 + i) * IMW + pw * 4 + j;
            s += xsr[((size_t)b * NN + n) * CC + c];
        }
    s *= (1.f / 16.f);

    __shared__ float r1[256], r2[256];
    r1[c] = s;
    r2[c] = s * s;
    __syncthreads();
    for (int st = 128; st > 0; st >>= 1) {
        if (c < st) { r1[c] += r1[c + st]; r2[c] += r2[c + st]; }
        __syncthreads();
    }
    float mean = r1[0] * (1.f / 256.f);
    float var  = r2[0] * (1.f / 256.f) - mean * mean;
    float invs = rsqrtf(var + 1e-5f);
    xpool[(size_t)bp * CC + c] = (s - mean) * invs * gam[c] + bet[c];
}

// ---------------- CPB table ----------------------------------------------------
__global__ __launch_bounds__(256) void tab_kernel(
    const float* __restrict__ rct, const float* __restrict__ w1,
    const float* __restrict__ b1, const float* __restrict__ w2,
    const float* __restrict__ b2, float* __restrict__ tab)
{
    int t = blockIdx.x;
    __shared__ float sh[512];
    float c0 = rct[t * 2], c1 = rct[t * 2 + 1];
    for (int j = threadIdx.x; j < 512; j += 256)
        sh[j] = fmaxf(0.f, c0 * w1[j * 2] + c1 * w1[j * 2 + 1] + b1[j]);
    __syncthreads();
    int w = threadIdx.x >> 5, lane = threadIdx.x & 31;
    float s = 0.f;
    for (int j = lane; j < 512; j += 32) s += sh[j] * w2[w * 512 + j];
    #pragma unroll
    for (int o = 16; o > 0; o >>= 1) s += __shfl_xor_sync(0xffffffffu, s, o);
    if (lane == 0) tab[t * 8 + w] = s + b2[w];
}

// ---------------- MMA attention ------------------------------------------------
// grid (49, 8, 4); 256 threads; 64 query rows per block; one (b,h) per block.
#define SP_OFF   0        // logits fp32 [64][228]; later probs bf16 hi@0, lo@+464B
#define SKH_OFF  58368    // K_pool hi bf16 [224][40]
#define SKL_OFF  76288
#define SVTH_OFF 94208    // V^T hi bf16 [32][216]
#define SVTL_OFF 108032
#define SQH_OFF  121856   // q_scaled hi bf16 [64][40]
#define SQL_OFF  126976
#define SQS_OFF  132096   // q_scaled fp32 [64][33] (reused as output accum)
#define SQN_OFF  140544   // q_norm fp32 [64][33]
#define SLOC_OFF 148992   // local weights [64][12]
#define SLOC2_OFF 152064  // raw local logits [64][12]
#define SMEM_ATTN 155136

__global__ __launch_bounds__(256) void attn_mma(
    const float* __restrict__ q, const float* __restrict__ qe,
    const float* __restrict__ temp, const float* __restrict__ sls,
    const float* __restrict__ kv, const float* __restrict__ kvp,
    const float* __restrict__ tab, const int* __restrict__ rpi,
    const float* __restrict__ rpb, const float* __restrict__ ltok,
    const float* __restrict__ lbias,
    __nv_bfloat16* __restrict__ oh, __nv_bfloat16* __restrict__ ol)
{
    extern __shared__ __align__(1024) char smem[];
    const uint32_t sb = smem_u32(smem);
    float* sP    = (float*)(smem + SP_OFF);
    float* sQs   = (float*)(smem + SQS_OFF);
    float* sQn   = (float*)(smem + SQN_OFF);
    float* sLoc  = (float*)(smem + SLOC_OFF);
    float* sLoc2 = (float*)(smem + SLOC2_OFF);

    const int b = blockIdx.z, h = blockIdx.y;
    const int n0 = blockIdx.x * 64;
    const int tid = threadIdx.x, lane = tid & 31, wid = tid >> 5;
    const int gid = lane >> 2, tig = lane & 3;

    // ---- stage K_pool (196 + pad to 224), bf16 hi/lo, row stride 80 B ----
    for (int i = tid; i < 224 * 8; i += 256) {
        int m = i >> 3, c = i & 7;
        uint2 hi = make_uint2(0, 0), lo = make_uint2(0, 0);
        if (m < PL) {
            float4 k4 = *(const float4*)&kvp[((size_t)(b * PL + m)) * 512 + h * HD + c * 4];
            split4(k4, hi, lo);
        }
        *(uint2*)(smem + SKH_OFF + m * 80 + c * 8) = hi;
        *(uint2*)(smem + SKL_OFF + m * 80 + c * 8) = lo;
    }
    // ---- stage V^T bf16 hi/lo [32][216] ----
    for (int i = tid; i < PL * 8; i += 256) {
        int m = i >> 3, c = i & 7;
        float4 v4 = *(const float4*)&kvp[((size_t)(b * PL + m)) * 512 + 256 + h * HD + c * 4];
        float vv[4] = {v4.x, v4.y, v4.z, v4.w};
        #pragma unroll
        for (int j = 0; j < 4; j++) {
            int d = c * 4 + j;
            __nv_bfloat16 hb = __float2bfloat16_rn(vv[j]);
            *(__nv_bfloat16*)(smem + SVTH_OFF + d * 432 + m * 2) = hb;
            *(__nv_bfloat16*)(smem + SVTL_OFF + d * 432 + m * 2) =
                __float2bfloat16_rn(vv[j] - __bfloat162float(hb));
        }
    }
    for (int i = tid; i < 32 * 20; i += 256) {
        int d = i / 20, kk = 196 + i % 20;
        *(__nv_bfloat16*)(smem + SVTH_OFF + d * 432 + kk * 2) = __float2bfloat16(0.f);
        *(__nv_bfloat16*)(smem + SVTL_OFF + d * 432 + kk * 2) = __float2bfloat16(0.f);
    }
    // ---- stage q: norm + scale ----
    {
        float sp = log1pf(expf(temp[h]));
        float qev = qe[h * HD + lane];
        for (int i = 0; i < 8; i++) {
            int row = wid * 8 + i;
            int n = n0 + row;
            float val = q[((size_t)(b * NN + n)) * CC + h * HD + lane];
            float ss = val * val;
            #pragma unroll
            for (int o = 16; o > 0; o >>= 1) ss += __shfl_xor_sync(0xffffffffu, ss, o);
            float inv = 1.f / fmaxf(sqrtf(ss), 1e-12f);
            float qnv = val * inv;
            float qsv = (qnv + qev) * sp * sls[n];
            sQs[row * 33 + lane] = qsv;
            sQn[row * 33 + lane] = qnv;
            __nv_bfloat16 hb = __float2bfloat16_rn(qsv);
            *(__nv_bfloat16*)(smem + SQH_OFF + row * 80 + lane * 2) = hb;
            *(__nv_bfloat16*)(smem + SQL_OFF + row * 80 + lane * 2) =
                __float2bfloat16_rn(qsv - __bfloat162float(hb));
        }
    }
    __syncthreads();

    const int warpM = wid & 3, warpN = wid >> 2;
    const int a_row = ((lane >> 3) & 1) * 8 + (lane & 7);
    const int a_ks  = (lane >> 4) & 1;
    const int b_row = ((lane >> 4) & 1) * 8 + (lane & 7);
    const int b_ks  = (lane >> 3) & 1;

    // ---- phase 1: pooled logits = Qs @ K^T (3-pass bf16 MMA) ----
    {
        float acc[7][2][4];
        #pragma unroll
        for (int nt = 0; nt < 7; nt++)
            #pragma unroll
            for (int np = 0; np < 2; np++)
                #pragma unroll
                for (int i = 0; i < 4; i++) acc[nt][np][i] = 0.f;

        #pragma unroll
        for (int s = 0; s < 2; s++) {
            uint32_t ah[4], al[4];
            {
                int r = warpM * 16 + a_row;
                uint32_t off = SQH_OFF + r * 80 + (s * 2 + a_ks) * 16;
                ldsm4(ah, sb + off);
                ldsm4(al, sb + off + (SQL_OFF - SQH_OFF));
            }
            #pragma unroll
            for (int nt = 0; nt < 7; nt++) {
                int nr = warpN * 112 + nt * 16 + b_row;
                uint32_t off = SKH_OFF + nr * 80 + (s * 2 + b_ks) * 16;
                uint32_t bh[4], bl[4];
                ldsm4(bh, sb + off);
                ldsm4(bl, sb + off + (SKL_OFF - SKH_OFF));
                #pragma unroll
                for (int np = 0; np < 2; np++) {
                    float* d = acc[nt][np];
                    mma_bf16(d, ah, bh[np * 2], bh[np * 2 + 1]);
                    mma_bf16(d, al, bh[np * 2], bh[np * 2 + 1]);
                    mma_bf16(d, ah, bl[np * 2], bl[np * 2 + 1]);
                }
            }
        }
        int r0 = warpM * 16 + gid;
        #pragma unroll
        for (int nt = 0; nt < 7; nt++)
            #pragma unroll
            for (int np = 0; np < 2; np++) {
                int colb = warpN * 112 + nt * 16 + np * 8 + 2 * tig;
                *(float2*)&sP[r0 * 228 + colb] =
                    make_float2(acc[nt][np][0], acc[nt][np][1]);
                *(float2*)&sP[(r0 + 8) * 228 + colb] =
                    make_float2(acc[nt][np][2], acc[nt][np][3]);
            }
    }
    __syncthreads();

    // ---- phase 1.5a: parallel CPB bias gather (high MLP) ----
    #pragma unroll 4
    for (int i = tid; i < 64 * PL; i += 256) {
        int row = i / PL;
        int j = i - row * PL;
        sP[row * 228 + j] += tab[rpi[(size_t)(n0 + row) * PL + j] * 8 + h];
    }
    // ---- phase 1.5b: parallel local logits + learnable-token dots ----
    for (int t5 = tid; t5 < 64 * 9; t5 += 256) {
        int row = t5 / 9, l = t5 - row * 9;
        int n = n0 + row;
        int rr = n / IMW, cc2 = n % IMW;
        int r2 = rr + l / 3 - 1, c3 = cc2 + l % 3 - 1;
        float aloc = -3.4e38f;
        const float* Qs = &sQs[row * 33];
        if (r2 >= 0 && r2 < IMH && c3 >= 0 && c3 < IMW) {
            int nb = r2 * IMW + c3;
            const float4* kr = (const float4*)(kv + ((size_t)(b * NN + nb)) * 512 + h * HD);
            float s2 = 0.f;
            #pragma unroll
            for (int d4 = 0; d4 < 8; d4++) {
                float4 t = kr[d4];
                s2 += Qs[d4*4+0]*t.x + Qs[d4*4+1]*t.y + Qs[d4*4+2]*t.z + Qs[d4*4+3]*t.w;
            }
            aloc = s2 + rpb[h * 9 + l];
        }
        sLoc2[row * 12 + l] = aloc;
        const float* Qn = &sQn[row * 33];
        float t2 = 0.f;
        #pragma unroll
        for (int d = 0; d < 32; d++) t2 += Qn[d] * ltok[(h * 32 + d) * 9 + l];
        sLoc[row * 12 + l] = t2 + lbias[h * 9 + l];
    }
    __syncthreads();

    // ---- phase 2: softmax per row (smem only) ----
    for (int i = 0; i < 8; i++) {
        int row = wid * 8 + i;
        float* Pr = &sP[row * 228];

        float e[7];
        float mx = -3.4e38f;
        #pragma unroll
        for (int t = 0; t < 7; t++) {
            int j = lane + 32 * t;
            if (j < PL) { e[t] = Pr[j]; mx = fmaxf(mx, e[t]); }
            else e[t] = -3.4e38f;
        }
        float aloc = (lane < 9) ? sLoc2[row * 12 + lane] : -3.4e38f;
        mx = fmaxf(mx, aloc);
        #pragma unroll
        for (int o = 16; o > 0; o >>= 1)
            mx = fmaxf(mx, __shfl_xor_sync(0xffffffffu, mx, o));

        float sum = 0.f;
        #pragma unroll
        for (int t = 0; t < 7; t++) {
            int j = lane + 32 * t;
            if (j < PL) { e[t] = __expf(e[t] - mx); sum += e[t]; }
        }
        float el = 0.f;
        if (lane < 9) { el = __expf(aloc - mx); sum += el; }
        #pragma unroll
        for (int o = 16; o > 0; o >>= 1) sum += __shfl_xor_sync(0xffffffffu, sum, o);
        float inv = 1.f / sum;

        __nv_bfloat16* Ph = (__nv_bfloat16*)Pr;
        __nv_bfloat16* Pl2 = Ph + 232;
        #pragma unroll
        for (int t = 0; t < 7; t++) {
            int j = lane + 32 * t;
            if (j < PL) {
                float p = e[t] * inv;
                __nv_bfloat16 hb = __float2bfloat16_rn(p);
                Ph[j] = hb;
                Pl2[j] = __float2bfloat16_rn(p - __bfloat162float(hb));
            }
        }
        if (lane < 12) {
            Ph[PL + lane] = __float2bfloat16(0.f);
            Pl2[PL + lane] = __float2bfloat16(0.f);
        }
        if (lane < 9) sLoc[row * 12 + lane] += el * inv;
    }
    __syncthreads();

    // ---- phase 3: pooled output = P @ V (3-pass bf16 MMA) ----
    {
        float acc[2][4];
        #pragma unroll
        for (int np = 0; np < 2; np++)
            #pragma unroll
            for (int i = 0; i < 4; i++) acc[np][i] = 0.f;

        #pragma unroll
        for (int kt = 0; kt < 13; kt++) {
            uint32_t ah[4], al[4], bh[4], bl[4];
            int r = warpM * 16 + a_row;
            uint32_t offA = SP_OFF + r * 912 + (kt * 2 + a_ks) * 16;
            ldsm4(ah, sb + offA);
            ldsm4(al, sb + offA + 464);
            int nr = warpN * 16 + b_row;
            uint32_t offB = SVTH_OFF + nr * 432 + (kt * 2 + b_ks) * 16;
            ldsm4(bh, sb + offB);
            ldsm4(bl, sb + offB + (SVTL_OFF - SVTH_OFF));
            #pragma unroll
            for (int np = 0; np < 2; np++) {
                float* d = acc[np];
                mma_bf16(d, ah, bh[np * 2], bh[np * 2 + 1]);
                mma_bf16(d, al, bh[np * 2], bh[np * 2 + 1]);
                mma_bf16(d, ah, bl[np * 2], bl[np * 2 + 1]);
            }
        }
        float* sO = sQs;
        int r0 = warpM * 16 + gid;
        #pragma unroll
        for (int np = 0; np < 2; np++) {
            int colb = warpN * 16 + np * 8 + 2 * tig;
            sO[r0 * 33 + colb]         = acc[np][0];
            sO[r0 * 33 + colb + 1]     = acc[np][1];
            sO[(r0+8) * 33 + colb]     = acc[np][2];
            sO[(r0+8) * 33 + colb + 1] = acc[np][3];
        }
    }
    __syncthreads();

    // ---- phase 4: add local-V contribution, split hi/lo, store ----
    for (int i = 0; i < 8; i++) {
        int row = wid * 8 + i;
        int n = n0 + row;
        int rr = n / IMW, cc2 = n % IMW;
        float o = sQs[row * 33 + lane];
        #pragma unroll
        for (int l = 0; l < 9; l++) {
            int r2 = rr + l / 3 - 1, c3 = cc2 + l % 3 - 1;
            if (r2 >= 0 && r2 < IMH && c3 >= 0 && c3 < IMW) {
                int nb = r2 * IMW + c3;
                o += sLoc[row * 12 + l] *
                     kv[((size_t)(b * NN + nb)) * 512 + 256 + h * HD + lane];
            }
        }
        size_t oi = ((size_t)(b * NN) + n) * CC + h * HD + lane;
        __nv_bfloat16 hb = __float2bfloat16_rn(o);
        oh[oi] = hb;
        ol[oi] = __float2bfloat16_rn(o - __bfloat162float(hb));
    }
}

// -----------------------------------------------------------------------------
extern "C" void kernel_launch(void* const* d_in, const int* in_sizes, int n_in,
                              void* d_out, int out_size)
{
    const float* x      = (const float*)d_in[0];
    const int*   rpi    = (const int*)  d_in[3];
    const float* rct    = (const float*)d_in[4];
    const float* sls    = (const float*)d_in[5];
    const float* q_w    = (const float*)d_in[7];
    const float* q_b    = (const float*)d_in[8];
    const float* kv_w   = (const float*)d_in[9];
    const float* kv_b   = (const float*)d_in[10];
    const float* sr_w   = (const float*)d_in[11];
    const float* sr_b   = (const float*)d_in[12];
    const float* norm_g = (const float*)d_in[13];
    const float* norm_b = (const float*)d_in[14];
    const float* cpb1_w = (const float*)d_in[15];
    const float* cpb1_b = (const float*)d_in[16];
    const float* cpb2_w = (const float*)d_in[17];
    const float* cpb2_b = (const float*)d_in[18];
    const float* temp   = (const float*)d_in[19];
    const float* qe     = (const float*)d_in[20];
    const float* rpb    = (const float*)d_in[21];
    const float* ltok   = (const float*)d_in[22];
    const float* lbias  = (const float*)d_in[23];
    const float* proj_w = (const float*)d_in[24];
    const float* proj_b = (const float*)d_in[25];
    float* out = (float*)d_out;

    float *p_q, *p_kv, *p_xsr, *p_xpl, *p_kvp, *p_tab;
    __nv_bfloat16 *p_xh, *p_xl, *p_xph, *p_xpL, *p_ath, *p_atl;
    cudaGetSymbolAddress((void**)&p_q,   g_q);
    cudaGetSymbolAddress((void**)&p_kv,  g_kv);
    cudaGetSymbolAddress((void**)&p_xsr, g_xsr);
    cudaGetSymbolAddress((void**)&p_xpl, g_xpl);
    cudaGetSymbolAddress((void**)&p_kvp, g_kvp);
    cudaGetSymbolAddress((void**)&p_tab, g_tab);
    cudaGetSymbolAddress((void**)&p_xh,  g_xh);
    cudaGetSymbolAddress((void**)&p_xl,  g_xl);
    cudaGetSymbolAddress((void**)&p_xph, g_xph);
    cudaGetSymbolAddress((void**)&p_xpL, g_xpL);
    cudaGetSymbolAddress((void**)&p_ath, g_ath);
    cudaGetSymbolAddress((void**)&p_atl, g_atl);

    const int M = BZ * NN;  // 12544 = 98 * 128
    const int MP = BZ * PL; // 784

    cudaFuncSetAttribute(gemm_bf16, cudaFuncAttributeMaxDynamicSharedMemorySize,
                         SMEM_GEMM);
    cudaFuncSetAttribute(gemm_qkvsr, cudaFuncAttributeMaxDynamicSharedMemorySize,
                         SMEM_GEMM);
    cudaFuncSetAttribute(attn_mma, cudaFuncAttributeMaxDynamicSharedMemorySize,
                         SMEM_ATTN);

    // split x -> bf16 hi/lo
    split_kernel<<<(M * CC / 4 + 255) / 256, 256>>>(x, p_xh, p_xl, M * CC / 4);

    // fused q + kv + sr GEMMs (one launch, 1568 blocks)
    gemm_qkvsr<<<dim3(16, 98), 256, SMEM_GEMM>>>(
        p_xh, p_xl, q_w, q_b, kv_w, kv_b, sr_w, sr_b, p_q, p_kv, p_xsr, M);

    // pooled path
    pool_ln_kernel<<<BZ * PL, 256>>>(p_xsr, norm_g, norm_b, p_xpl);
    split_kernel<<<(MP * CC / 4 + 255) / 256, 256>>>(p_xpl, p_xph, p_xpL, MP * CC / 4);
    gemm_bf16<<<dim3(8, 7), 256, SMEM_GEMM>>>(p_xph, p_xpL, kv_w, kv_b, p_kvp, MP, 512, 2);

    // CPB bias table
    tab_kernel<<<KTAB, 256>>>(rct, cpb1_w, cpb1_b, cpb2_w, cpb2_b, p_tab);

    // MMA attention (writes split bf16 output directly)
    attn_mma<<<dim3(NN / 64, HH, BZ), 256, SMEM_ATTN>>>(
        p_q, qe, temp, sls, p_kv, p_kvp, p_tab, rpi, rpb, ltok, lbias,
        p_ath, p_atl);

    // output projection
    gemm_bf16<<<dim3(4, 98), 256, SMEM_GEMM>>>(p_ath, p_atl, proj_w, proj_b, out, M, 256, 0);
}

// round 13
// speedup vs baseline: 2.5452x; 1.2546x over previous
#include <cuda_runtime.h>
#include <cuda_bf16.h>
#include <math.h>
#include <stdint.h>

// Problem constants
#define BZ 4
#define NN 3136
#define CC 256
#define HH 8
#define HD 32
#define PL 196
#define IMH 56
#define IMW 56
#define KTAB 2048

// ---------------- scratch (device globals; no allocation allowed) -------------
__device__ float g_q   [BZ * NN * CC];
__device__ float g_kv  [BZ * NN * 512];
__device__ float g_xsr [BZ * NN * CC];
__device__ float g_tab [KTAB * HH];
// bf16 hi/lo split buffers
__device__ __nv_bfloat16 g_xh  [BZ * NN * CC];
__device__ __nv_bfloat16 g_xl  [BZ * NN * CC];
__device__ __nv_bfloat16 g_xph [BZ * PL * CC];
__device__ __nv_bfloat16 g_xpL [BZ * PL * CC];
__device__ __nv_bfloat16 g_ath [BZ * NN * CC];
__device__ __nv_bfloat16 g_atl [BZ * NN * CC];
// prepared pooled K (smem-layout) and V^T, bf16 hi/lo
__device__ __align__(16) __nv_bfloat16 g_kph [BZ * HH * 224 * 40];
__device__ __align__(16) __nv_bfloat16 g_kpl [BZ * HH * 224 * 40];
__device__ __align__(16) __nv_bfloat16 g_vth [BZ * HH * 32 * 216];
__device__ __align__(16) __nv_bfloat16 g_vtl [BZ * HH * 32 * 216];

// ---------------- helpers ------------------------------------------------------
__device__ __forceinline__ uint32_t smem_u32(const void* p) {
    uint32_t a;
    asm("{ .reg .u64 t; cvta.to.shared.u64 t, %1; cvt.u32.u64 %0, t; }"
        : "=r"(a) : "l"(p));
    return a;
}
__device__ __forceinline__ void split4(float4 v, uint2& hi, uint2& lo) {
    float h0 = __bfloat162float(__float2bfloat16_rn(v.x));
    float h1 = __bfloat162float(__float2bfloat16_rn(v.y));
    float h2 = __bfloat162float(__float2bfloat16_rn(v.z));
    float h3 = __bfloat162float(__float2bfloat16_rn(v.w));
    __nv_bfloat162 ph0 = __floats2bfloat162_rn(h0, h1);
    __nv_bfloat162 ph1 = __floats2bfloat162_rn(h2, h3);
    __nv_bfloat162 pl0 = __floats2bfloat162_rn(v.x - h0, v.y - h1);
    __nv_bfloat162 pl1 = __floats2bfloat162_rn(v.z - h2, v.w - h3);
    hi.x = *(uint32_t*)&ph0; hi.y = *(uint32_t*)&ph1;
    lo.x = *(uint32_t*)&pl0; lo.y = *(uint32_t*)&pl1;
}
__device__ __forceinline__ void ldsm4(uint32_t* r, uint32_t addr) {
    asm volatile("ldmatrix.sync.aligned.m8n8.x4.shared.b16 {%0,%1,%2,%3}, [%4];"
                 : "=r"(r[0]), "=r"(r[1]), "=r"(r[2]), "=r"(r[3]) : "r"(addr));
}
__device__ __forceinline__ void mma_bf16(float* d, const uint32_t* a,
                                         uint32_t b0, uint32_t b1) {
    asm volatile(
        "mma.sync.aligned.m16n8k16.row.col.f32.bf16.bf16.f32 "
        "{%0,%1,%2,%3},{%4,%5,%6,%7},{%8,%9},{%0,%1,%2,%3};"
        : "+f"(d[0]), "+f"(d[1]), "+f"(d[2]), "+f"(d[3])
        : "r"(a[0]), "r"(a[1]), "r"(a[2]), "r"(a[3]), "r"(b0), "r"(b1));
}

// ---------------- split: fp32 -> bf16 hi/lo -----------------------------------
__global__ __launch_bounds__(256) void split_kernel(
    const float* __restrict__ src, __nv_bfloat16* __restrict__ hi,
    __nv_bfloat16* __restrict__ lo, int n4)
{
    int i = blockIdx.x * 256 + threadIdx.x;
    if (i >= n4) return;
    float4 v = ((const float4*)src)[i];
    uint2 h, l;
    split4(v, h, l);
    ((uint2*)hi)[i] = h;
    ((uint2*)lo)[i] = l;
}

// ---------------- bf16 3-pass GEMM mainloop (device) ---------------------------
#define A_H 0
#define A_L 16384
#define B_H 32768
#define B_L 65536
#define SMEM_GEMM 98304

__device__ __forceinline__ void gemm_mainloop(
    char* smem, const __nv_bfloat16* __restrict__ Ah,
    const __nv_bfloat16* __restrict__ Al, const float* __restrict__ W,
    int M, int m0, int n0, float acc[2][4][4])
{
    const uint32_t sb = smem_u32(smem);
    const int tid = threadIdx.x;
    const int lane = tid & 31, wid = tid >> 5;
    const int warpM = wid & 3, warpN = wid >> 2;

    #pragma unroll
    for (int it = 0; it < 16; it++) {
        int idx = tid + it * 256;
        int n = idx >> 6, c4 = idx & 63;
        float4 wv = *(const float4*)&W[(size_t)(n0 + n) * 256 + c4 * 4];
        uint2 hi, lo;
        split4(wv, hi, lo);
        uint32_t off = n * 512 + ((c4 >> 4) << 7) +
                       (((((c4 >> 1) & 7) ^ (n & 7))) << 4) + ((c4 & 1) << 3);
        *(uint2*)(smem + B_H + off) = hi;
        *(uint2*)(smem + B_L + off) = lo;
    }

    #pragma unroll
    for (int mt = 0; mt < 2; mt++)
        #pragma unroll
        for (int nt = 0; nt < 4; nt++)
            #pragma unroll
            for (int i = 0; i < 4; i++) acc[mt][nt][i] = 0.f;

    const uint4 z16 = make_uint4(0, 0, 0, 0);
    uint4 pah[4], pal[4];
    #pragma unroll
    for (int it = 0; it < 4; it++) {
        int idx = tid + it * 256;
        int row = idx >> 3, seg = idx & 7;
        int gr = m0 + row;
        pah[it] = (gr < M) ? *(const uint4*)&Ah[(size_t)gr * 256 + seg * 8] : z16;
        pal[it] = (gr < M) ? *(const uint4*)&Al[(size_t)gr * 256 + seg * 8] : z16;
    }

    const int a_row_in = ((lane >> 3) & 1) * 8 + (lane & 7);
    const int a_kseg   = (lane >> 4) & 1;
    const int b_row_in = ((lane >> 4) & 1) * 8 + (lane & 7);
    const int b_kseg   = (lane >> 3) & 1;

    for (int ch = 0; ch < 4; ch++) {
        __syncthreads();
        #pragma unroll
        for (int it = 0; it < 4; it++) {
            int idx = tid + it * 256;
            int row = idx >> 3, seg = idx & 7;
            uint32_t off = row * 128 + ((seg ^ (row & 7)) << 4);
            *(uint4*)(smem + A_H + off) = pah[it];
            *(uint4*)(smem + A_L + off) = pal[it];
        }
        __syncthreads();

        if (ch < 3) {
            #pragma unroll
            for (int it = 0; it < 4; it++) {
                int idx = tid + it * 256;
                int row = idx >> 3, seg = idx & 7;
                int gr = m0 + row;
                size_t gb = (size_t)gr * 256 + (ch + 1) * 64 + seg * 8;
                pah[it] = (gr < M) ? *(const uint4*)&Ah[gb] : z16;
                pal[it] = (gr < M) ? *(const uint4*)&Al[gb] : z16;
            }
        }

        #pragma unroll
        for (int s = 0; s < 4; s++) {
            uint32_t ah[2][4], al[2][4], bh[2][4], bl[2][4];
            #pragma unroll
            for (int mt = 0; mt < 2; mt++) {
                int r = warpM * 32 + mt * 16 + a_row_in;
                uint32_t off = r * 128 + (((s * 2 + a_kseg) ^ (r & 7)) << 4);
                ldsm4(ah[mt], sb + A_H + off);
                ldsm4(al[mt], sb + A_L + off);
            }
            #pragma unroll
            for (int np = 0; np < 2; np++) {
                int n = warpN * 32 + np * 16 + b_row_in;
                uint32_t off = n * 512 + ch * 128 +
                               (((s * 2 + b_kseg) ^ (n & 7)) << 4);
                ldsm4(bh[np], sb + B_H + off);
                ldsm4(bl[np], sb + B_L + off);
            }
            #pragma unroll
            for (int mt = 0; mt < 2; mt++)
                #pragma unroll
                for (int np = 0; np < 2; np++) {
                    float* dl = acc[mt][2 * np];
                    float* dh = acc[mt][2 * np + 1];
                    mma_bf16(dl, ah[mt], bh[np][0], bh[np][1]);
                    mma_bf16(dl, al[mt], bh[np][0], bh[np][1]);
                    mma_bf16(dl, ah[mt], bl[np][0], bl[np][1]);
                    mma_bf16(dh, ah[mt], bh[np][2], bh[np][3]);
                    mma_bf16(dh, al[mt], bh[np][2], bh[np][3]);
                    mma_bf16(dh, ah[mt], bl[np][2], bl[np][3]);
                }
        }
    }
}

// standard epilogue GEMM body
__device__ __forceinline__ void gemm_body(
    char* smem, const __nv_bfloat16* __restrict__ Ah,
    const __nv_bfloat16* __restrict__ Al, const float* __restrict__ W,
    const float* __restrict__ bias, float* __restrict__ C,
    int M, int N, int act, int m0, int n0)
{
    float acc[2][4][4];
    gemm_mainloop(smem, Ah, Al, W, M, m0, n0, acc);

    const int lane = threadIdx.x & 31, wid = threadIdx.x >> 5;
    const int gid = lane >> 2, tig = lane & 3;
    const int warpM = wid & 3, warpN = wid >> 2;

    const bool donorm = (act == 2) && (n0 + warpN * 32) < 256;
    #pragma unroll
    for (int mt = 0; mt < 2; mt++) {
        int r0 = m0 + warpM * 32 + mt * 16 + gid;
        int r1 = r0 + 8;
        float v0[4][2], v1[4][2];
        #pragma unroll
        for (int nt = 0; nt < 4; nt++) {
            int cb = n0 + warpN * 32 + nt * 8 + 2 * tig;
            float b0 = bias[cb], b1 = bias[cb + 1];
            v0[nt][0] = acc[mt][nt][0] + b0; v0[nt][1] = acc[mt][nt][1] + b1;
            v1[nt][0] = acc[mt][nt][2] + b0; v1[nt][1] = acc[mt][nt][3] + b1;
        }
        if (act == 1) {
            #pragma unroll
            for (int nt = 0; nt < 4; nt++)
                #pragma unroll
                for (int i = 0; i < 2; i++) {
                    v0[nt][i] = 0.5f * v0[nt][i] *
                                (1.f + erff(v0[nt][i] * 0.70710678118654752f));
                    v1[nt][i] = 0.5f * v1[nt][i] *
                                (1.f + erff(v1[nt][i] * 0.70710678118654752f));
                }
        } else if (donorm) {
            float ss0 = 0.f, ss1 = 0.f;
            #pragma unroll
            for (int nt = 0; nt < 4; nt++) {
                ss0 += v0[nt][0] * v0[nt][0] + v0[nt][1] * v0[nt][1];
                ss1 += v1[nt][0] * v1[nt][0] + v1[nt][1] * v1[nt][1];
            }
            ss0 += __shfl_xor_sync(0xffffffffu, ss0, 1);
            ss0 += __shfl_xor_sync(0xffffffffu, ss0, 2);
            ss1 += __shfl_xor_sync(0xffffffffu, ss1, 1);
            ss1 += __shfl_xor_sync(0xffffffffu, ss1, 2);
            float inv0 = 1.f / fmaxf(sqrtf(ss0), 1e-12f);
            float inv1 = 1.f / fmaxf(sqrtf(ss1), 1e-12f);
            #pragma unroll
            for (int nt = 0; nt < 4; nt++) {
                v0[nt][0] *= inv0; v0[nt][1] *= inv0;
                v1[nt][0] *= inv1; v1[nt][1] *= inv1;
            }
        }
        #pragma unroll
        for (int nt = 0; nt < 4; nt++) {
            int cb = n0 + warpN * 32 + nt * 8 + 2 * tig;
            if (r0 < M)
                *(float2*)&C[(size_t)r0 * N + cb] = make_float2(v0[nt][0], v0[nt][1]);
            if (r1 < M)
                *(float2*)&C[(size_t)r1 * N + cb] = make_float2(v1[nt][0], v1[nt][1]);
        }
    }
}

__global__ __launch_bounds__(256) void gemm_bf16(
    const __nv_bfloat16* __restrict__ Ah, const __nv_bfloat16* __restrict__ Al,
    const float* __restrict__ W, const float* __restrict__ bias,
    float* __restrict__ C, int M, int N, int act)
{
    extern __shared__ __align__(1024) char smem[];
    gemm_body(smem, Ah, Al, W, bias, C, M, N, act,
              blockIdx.y * 128, blockIdx.x * 64);
}

// fused q/kv/sr GEMM
__global__ __launch_bounds__(256) void gemm_qkvsr(
    const __nv_bfloat16* __restrict__ Ah, const __nv_bfloat16* __restrict__ Al,
    const float* __restrict__ q_w, const float* __restrict__ q_b,
    const float* __restrict__ kv_w, const float* __restrict__ kv_b,
    const float* __restrict__ sr_w, const float* __restrict__ sr_b,
    float* __restrict__ Cq, float* __restrict__ Ckv, float* __restrict__ Cxsr,
    int M)
{
    extern __shared__ __align__(1024) char smem[];
    const int bx = blockIdx.x;
    const float *W, *bias;
    float* C;
    int N, n0, act;
    if (bx < 4)       { W = q_w;  bias = q_b;  C = Cq;   N = 256; n0 = bx * 64;        act = 0; }
    else if (bx < 12) { W = kv_w; bias = kv_b; C = Ckv;  N = 512; n0 = (bx - 4) * 64;  act = 2; }
    else              { W = sr_w; bias = sr_b; C = Cxsr; N = 256; n0 = (bx - 12) * 64; act = 1; }
    gemm_body(smem, Ah, Al, W, bias, C, M, N, act, blockIdx.y * 128, n0);
}

// pooled-kv GEMM with fused prep: writes K (l2-normed) in smem-layout bf16 hi/lo
// and V transposed bf16 hi/lo. No fp32 output.
__global__ __launch_bounds__(256) void gemm_kvp_prep(
    const __nv_bfloat16* __restrict__ Ah, const __nv_bfloat16* __restrict__ Al,
    const float* __restrict__ kv_w, const float* __restrict__ kv_b,
    __nv_bfloat16* __restrict__ kph, __nv_bfloat16* __restrict__ kpl,
    __nv_bfloat16* __restrict__ vth, __nv_bfloat16* __restrict__ vtl,
    int M)
{
    extern __shared__ __align__(1024) char smem[];
    const int m0 = blockIdx.y * 128, n0 = blockIdx.x * 64;
    float acc[2][4][4];
    gemm_mainloop(smem, Ah, Al, kv_w, M, m0, n0, acc);

    const int lane = threadIdx.x & 31, wid = threadIdx.x >> 5;
    const int gid = lane >> 2, tig = lane & 3;
    const int warpM = wid & 3, warpN = wid >> 2;

    const int colbase = n0 + warpN * 32;     // 32-col head group base
    const bool isK = colbase < 256;
    const int h = (colbase & 255) >> 5;

    #pragma unroll
    for (int mt = 0; mt < 2; mt++) {
        int r0 = m0 + warpM * 32 + mt * 16 + gid;
        int r1 = r0 + 8;
        float v0[4][2], v1[4][2];
        #pragma unroll
        for (int nt = 0; nt < 4; nt++) {
            int cb = colbase + nt * 8 + 2 * tig;
            float b0 = kv_b[cb], b1 = kv_b[cb + 1];
            v0[nt][0] = acc[mt][nt][0] + b0; v0[nt][1] = acc[mt][nt][1] + b1;
            v1[nt][0] = acc[mt][nt][2] + b0; v1[nt][1] = acc[mt][nt][3] + b1;
        }
        if (isK) {
            float ss0 = 0.f, ss1 = 0.f;
            #pragma unroll
            for (int nt = 0; nt < 4; nt++) {
                ss0 += v0[nt][0] * v0[nt][0] + v0[nt][1] * v0[nt][1];
                ss1 += v1[nt][0] * v1[nt][0] + v1[nt][1] * v1[nt][1];
            }
            ss0 += __shfl_xor_sync(0xffffffffu, ss0, 1);
            ss0 += __shfl_xor_sync(0xffffffffu, ss0, 2);
            ss1 += __shfl_xor_sync(0xffffffffu, ss1, 1);
            ss1 += __shfl_xor_sync(0xffffffffu, ss1, 2);
            float inv0 = 1.f / fmaxf(sqrtf(ss0), 1e-12f);
            float inv1 = 1.f / fmaxf(sqrtf(ss1), 1e-12f);
            #pragma unroll
            for (int nt = 0; nt < 4; nt++) {
                v0[nt][0] *= inv0; v0[nt][1] *= inv0;
                v1[nt][0] *= inv1; v1[nt][1] *= inv1;
            }
        }
        // write rows r0, r1
        #pragma unroll
        for (int rsel = 0; rsel < 2; rsel++) {
            int r = rsel ? r1 : r0;
            if (r >= M) continue;
            int bb = r / PL, p = r - bb * PL;
            int bh = bb * HH + h;
            float (*vv)[2] = rsel ? v1 : v0;
            if (isK) {
                size_t base = (size_t)(bh * 224 + p) * 40;
                #pragma unroll
                for (int nt = 0; nt < 4; nt++) {
                    int d0 = nt * 8 + 2 * tig;
                    float a0 = vv[nt][0], a1 = vv[nt][1];
                    __nv_bfloat162 hb = __floats2bfloat162_rn(a0, a1);
                    float h0 = __bfloat162float(__low2bfloat16(hb));
                    float h1 = __bfloat162float(__high2bfloat16(hb));
                    __nv_bfloat162 lb = __floats2bfloat162_rn(a0 - h0, a1 - h1);
                    *(__nv_bfloat162*)&kph[base + d0] = hb;
                    *(__nv_bfloat162*)&kpl[base + d0] = lb;
                }
            } else {
                #pragma unroll
                for (int nt = 0; nt < 4; nt++)
                    #pragma unroll
                    for (int i = 0; i < 2; i++) {
                        int d = nt * 8 + 2 * tig + i;
                        float a = vv[nt][i];
                        __nv_bfloat16 hb = __float2bfloat16_rn(a);
                        size_t adr = (size_t)(bh * 32 + d) * 216 + p;
                        vth[adr] = hb;
                        vtl[adr] = __float2bfloat16_rn(a - __bfloat162float(hb));
                    }
            }
        }
    }
}

// ---------------- 4x4 average pool + layernorm over C (bf16 hi/lo output) -----
__global__ __launch_bounds__(256) void pool_ln_kernel(
    const float* __restrict__ xsr, const float* __restrict__ gam,
    const float* __restrict__ bet, __nv_bfloat16* __restrict__ xph,
    __nv_bfloat16* __restrict__ xpl)
{
    int bp = blockIdx.x;
    int b = bp / PL, p = bp % PL;
    int ph = p / 14, pw = p % 14;
    int c = threadIdx.x;

    float s = 0.f;
    #pragma unroll
    for (int i = 0; i < 4; i++)
        #pragma unroll
        for (int j = 0; j < 4; j++) {
            int n = (ph * 4 + i) * IMW + pw * 4 + j;
            s += xsr[((size_t)b * NN + n) * CC + c];
        }
    s *= (1.f / 16.f);

    __shared__ float r1[256], r2[256];
    r1[c] = s;
    r2[c] = s * s;
    __syncthreads();
    for (int st = 128; st > 0; st >>= 1) {
        if (c < st) { r1[c] += r1[c + st]; r2[c] += r2[c + st]; }
        __syncthreads();
    }
    float mean = r1[0] * (1.f / 256.f);
    float var  = r2[0] * (1.f / 256.f) - mean * mean;
    float invs = rsqrtf(var + 1e-5f);
    float val = (s - mean) * invs * gam[c] + bet[c];
    __nv_bfloat16 hb = __float2bfloat16_rn(val);
    xph[(size_t)bp * CC + c] = hb;
    xpl[(size_t)bp * CC + c] = __float2bfloat16_rn(val - __bfloat162float(hb));
}

// ---------------- CPB table ----------------------------------------------------
__global__ __launch_bounds__(256) void tab_kernel(
    const float* __restrict__ rct, const float* __restrict__ w1,
    const float* __restrict__ b1, const float* __restrict__ w2,
    const float* __restrict__ b2, float* __restrict__ tab)
{
    int t = blockIdx.x;
    __shared__ float sh[512];
    float c0 = rct[t * 2], c1 = rct[t * 2 + 1];
    for (int j = threadIdx.x; j < 512; j += 256)
        sh[j] = fmaxf(0.f, c0 * w1[j * 2] + c1 * w1[j * 2 + 1] + b1[j]);
    __syncthreads();
    int w = threadIdx.x >> 5, lane = threadIdx.x & 31;
    float s = 0.f;
    for (int j = lane; j < 512; j += 32) s += sh[j] * w2[w * 512 + j];
    #pragma unroll
    for (int o = 16; o > 0; o >>= 1) s += __shfl_xor_sync(0xffffffffu, s, o);
    if (lane == 0) tab[t * 8 + w] = s + b2[w];
}

// ---------------- MMA attention (512 threads) ----------------------------------
#define SP_OFF   0        // logits fp32 [64][228]; later probs bf16 hi@0, lo@+464B
#define SKH_OFF  58368    // K_pool hi bf16 [224][40]
#define SKL_OFF  76288
#define SVTH_OFF 94208    // V^T hi bf16 [32][216]
#define SVTL_OFF 108032
#define SQH_OFF  121856   // q_scaled hi bf16 [64][40]
#define SQL_OFF  126976
#define SQS_OFF  132096   // q_scaled fp32 [64][33] (reused as output accum)
#define SQN_OFF  140544   // q_norm fp32 [64][33]
#define SLOC_OFF 148992   // local weights [64][12]
#define SLOC2_OFF 152064  // raw local logits [64][12]
#define SLT_OFF  155136   // ltok head slice [32*9]
#define SRB_OFF  156288   // rpb[9] @0, lbias[9] @16
#define SMEM_ATTN 156416

__global__ __launch_bounds__(512) void attn_mma(
    const float* __restrict__ q, const float* __restrict__ qe,
    const float* __restrict__ temp, const float* __restrict__ sls,
    const float* __restrict__ kv,
    const __nv_bfloat16* __restrict__ kph, const __nv_bfloat16* __restrict__ kpl,
    const __nv_bfloat16* __restrict__ vth, const __nv_bfloat16* __restrict__ vtl,
    const float* __restrict__ tab, const int* __restrict__ rpi,
    const float* __restrict__ rpb, const float* __restrict__ ltok,
    const float* __restrict__ lbias,
    __nv_bfloat16* __restrict__ oh, __nv_bfloat16* __restrict__ ol)
{
    extern __shared__ __align__(1024) char smem[];
    const uint32_t sb = smem_u32(smem);
    float* sP    = (float*)(smem + SP_OFF);
    float* sQs   = (float*)(smem + SQS_OFF);
    float* sQn   = (float*)(smem + SQN_OFF);
    float* sLoc  = (float*)(smem + SLOC_OFF);
    float* sLoc2 = (float*)(smem + SLOC2_OFF);
    float* sLt   = (float*)(smem + SLT_OFF);
    float* sRb   = (float*)(smem + SRB_OFF);

    const int b = blockIdx.z, h = blockIdx.y;
    const int n0 = blockIdx.x * 64;
    const int tid = threadIdx.x, lane = tid & 31, wid = tid >> 5;
    const int gid = lane >> 2, tig = lane & 3;
    const int bh = b * HH + h;

    // ---- staging: straight uint4 copies of prepared K / V^T ----
    {
        const uint4* gkh = (const uint4*)(kph + (size_t)bh * 224 * 40);
        const uint4* gkl = (const uint4*)(kpl + (size_t)bh * 224 * 40);
        uint4* skh = (uint4*)(smem + SKH_OFF);
        uint4* skl = (uint4*)(smem + SKL_OFF);
        for (int i = tid; i < 1120; i += 512) { skh[i] = gkh[i]; skl[i] = gkl[i]; }
        const uint4* gvh = (const uint4*)(vth + (size_t)bh * 32 * 216);
        const uint4* gvl = (const uint4*)(vtl + (size_t)bh * 32 * 216);
        uint4* svh = (uint4*)(smem + SVTH_OFF);
        uint4* svl = (uint4*)(smem + SVTL_OFF);
        for (int i = tid; i < 864; i += 512) { svh[i] = gvh[i]; svl[i] = gvl[i]; }
        // ltok head slice (contiguous 288 floats), rpb/lbias
        for (int i = tid; i < 288; i += 512) sLt[i] = ltok[h * 288 + i];
        if (tid < 9) sRb[tid] = rpb[h * 9 + tid];
        else if (tid >= 32 && tid < 41) sRb[16 + tid - 32] = lbias[h * 9 + tid - 32];
    }
    // zero pads: K rows 196..223 (first 64B), V^T cols 196..207
    {
        const uint4 z = make_uint4(0, 0, 0, 0);
        for (int i = tid; i < 112; i += 512) {
            int row = 196 + (i >> 2), seg = i & 3;
            *(uint4*)(smem + SKH_OFF + row * 80 + seg * 16) = z;
            *(uint4*)(smem + SKL_OFF + row * 80 + seg * 16) = z;
        }
        for (int i = tid; i < 192; i += 512) {
            int d = i / 6, k = i % 6;
            *(uint32_t*)(smem + SVTH_OFF + d * 432 + 392 + k * 4) = 0;
            *(uint32_t*)(smem + SVTL_OFF + d * 432 + 392 + k * 4) = 0;
        }
    }
    // ---- stage q: norm + scale (16 warps x 4 rows) ----
    {
        float sp = log1pf(expf(temp[h]));
        float qev = qe[h * HD + lane];
        #pragma unroll
        for (int i = 0; i < 4; i++) {
            int row = wid * 4 + i;
            int n = n0 + row;
            float val = q[((size_t)(b * NN + n)) * CC + h * HD + lane];
            float ss = val * val;
            #pragma unroll
            for (int o = 16; o > 0; o >>= 1) ss += __shfl_xor_sync(0xffffffffu, ss, o);
            float inv = 1.f / fmaxf(sqrtf(ss), 1e-12f);
            float qnv = val * inv;
            float qsv = (qnv + qev) * sp * sls[n];
            sQs[row * 33 + lane] = qsv;
            sQn[row * 33 + lane] = qnv;
            __nv_bfloat16 hb = __float2bfloat16_rn(qsv);
            *(__nv_bfloat16*)(smem + SQH_OFF + row * 80 + lane * 2) = hb;
            *(__nv_bfloat16*)(smem + SQL_OFF + row * 80 + lane * 2) =
                __float2bfloat16_rn(qsv - __bfloat162float(hb));
        }
    }
    __syncthreads();

    const int warpM = wid & 3, warpN = (wid >> 2) & 1;
    const int a_row = ((lane >> 3) & 1) * 8 + (lane & 7);
    const int a_ks  = (lane >> 4) & 1;
    const int b_row = ((lane >> 4) & 1) * 8 + (lane & 7);
    const int b_ks  = (lane >> 3) & 1;

    // ---- phase 1: pooled logits = Qs @ K^T (warps 0-7) ----
    if (wid < 8) {
        float acc[7][2][4];
        #pragma unroll
        for (int nt = 0; nt < 7; nt++)
            #pragma unroll
            for (int np = 0; np < 2; np++)
                #pragma unroll
                for (int i = 0; i < 4; i++) acc[nt][np][i] = 0.f;

        #pragma unroll
        for (int s = 0; s < 2; s++) {
            uint32_t ah[4], al[4];
            {
                int r = warpM * 16 + a_row;
                uint32_t off = SQH_OFF + r * 80 + (s * 2 + a_ks) * 16;
                ldsm4(ah, sb + off);
                ldsm4(al, sb + off + (SQL_OFF - SQH_OFF));
            }
            #pragma unroll
            for (int nt = 0; nt < 7; nt++) {
                int nr = warpN * 112 + nt * 16 + b_row;
                uint32_t off = SKH_OFF + nr * 80 + (s * 2 + b_ks) * 16;
                uint32_t bhf[4], blf[4];
                ldsm4(bhf, sb + off);
                ldsm4(blf, sb + off + (SKL_OFF - SKH_OFF));
                #pragma unroll
                for (int np = 0; np < 2; np++) {
                    float* d = acc[nt][np];
                    mma_bf16(d, ah, bhf[np * 2], bhf[np * 2 + 1]);
                    mma_bf16(d, al, bhf[np * 2], bhf[np * 2 + 1]);
                    mma_bf16(d, ah, blf[np * 2], blf[np * 2 + 1]);
                }
            }
        }
        int r0 = warpM * 16 + gid;
        #pragma unroll
        for (int nt = 0; nt < 7; nt++)
            #pragma unroll
            for (int np = 0; np < 2; np++) {
                int colb = warpN * 112 + nt * 16 + np * 8 + 2 * tig;
                *(float2*)&sP[r0 * 228 + colb] =
                    make_float2(acc[nt][np][0], acc[nt][np][1]);
                *(float2*)&sP[(r0 + 8) * 228 + colb] =
                    make_float2(acc[nt][np][2], acc[nt][np][3]);
            }
    }
    __syncthreads();

    // ---- phase 1.5a: parallel CPB bias gather ----
    #pragma unroll 4
    for (int i = tid; i < 64 * PL; i += 512) {
        int row = i / PL;
        int j = i - row * PL;
        sP[row * 228 + j] += tab[rpi[(size_t)(n0 + row) * PL + j] * 8 + h];
    }
    // ---- phase 1.5b: parallel local logits + learnable-token dots ----
    for (int t5 = tid; t5 < 64 * 9; t5 += 512) {
        int row = t5 / 9, l = t5 - row * 9;
        int n = n0 + row;
        int rr = n / IMW, cc2 = n % IMW;
        int r2 = rr + l / 3 - 1, c3 = cc2 + l % 3 - 1;
        float aloc = -3.4e38f;
        const float* Qs = &sQs[row * 33];
        if (r2 >= 0 && r2 < IMH && c3 >= 0 && c3 < IMW) {
            int nb = r2 * IMW + c3;
            const float4* kr = (const float4*)(kv + ((size_t)(b * NN + nb)) * 512 + h * HD);
            float s2 = 0.f;
            #pragma unroll
            for (int d4 = 0; d4 < 8; d4++) {
                float4 t = kr[d4];
                s2 += Qs[d4*4+0]*t.x + Qs[d4*4+1]*t.y + Qs[d4*4+2]*t.z + Qs[d4*4+3]*t.w;
            }
            aloc = s2 + sRb[l];
        }
        sLoc2[row * 12 + l] = aloc;
        const float* Qn = &sQn[row * 33];
        float t2 = 0.f;
        #pragma unroll
        for (int d = 0; d < 32; d++) t2 += Qn[d] * sLt[d * 9 + l];
        sLoc[row * 12 + l] = t2 + sRb[16 + l];
    }
    __syncthreads();

    // ---- phase 2: softmax per row (16 warps x 4 rows) ----
    #pragma unroll
    for (int i = 0; i < 4; i++) {
        int row = wid * 4 + i;
        float* Pr = &sP[row * 228];

        float e[7];
        float mx = -3.4e38f;
        #pragma unroll
        for (int t = 0; t < 7; t++) {
            int j = lane + 32 * t;
            if (j < PL) { e[t] = Pr[j]; mx = fmaxf(mx, e[t]); }
            else e[t] = -3.4e38f;
        }
        float aloc = (lane < 9) ? sLoc2[row * 12 + lane] : -3.4e38f;
        mx = fmaxf(mx, aloc);
        #pragma unroll
        for (int o = 16; o > 0; o >>= 1)
            mx = fmaxf(mx, __shfl_xor_sync(0xffffffffu, mx, o));

        float sum = 0.f;
        #pragma unroll
        for (int t = 0; t < 7; t++) {
            int j = lane + 32 * t;
            if (j < PL) { e[t] = __expf(e[t] - mx); sum += e[t]; }
        }
        float el = 0.f;
        if (lane < 9) { el = __expf(aloc - mx); sum += el; }
        #pragma unroll
        for (int o = 16; o > 0; o >>= 1) sum += __shfl_xor_sync(0xffffffffu, sum, o);
        float inv = 1.f / sum;

        __nv_bfloat16* Ph = (__nv_bfloat16*)Pr;
        __nv_bfloat16* Pl2 = Ph + 232;
        #pragma unroll
        for (int t = 0; t < 7; t++) {
            int j = lane + 32 * t;
            if (j < PL) {
                float p = e[t] * inv;
                __nv_bfloat16 hb = __float2bfloat16_rn(p);
                Ph[j] = hb;
                Pl2[j] = __float2bfloat16_rn(p - __bfloat162float(hb));
            }
        }
        if (lane < 12) {
            Ph[PL + lane] = __float2bfloat16(0.f);
            Pl2[PL + lane] = __float2bfloat16(0.f);
        }
        if (lane < 9) sLoc[row * 12 + lane] += el * inv;
    }
    __syncthreads();

    // ---- phase 3: pooled output = P @ V (warps 0-7) ----
    if (wid < 8) {
        float acc[2][4];
        #pragma unroll
        for (int np = 0; np < 2; np++)
            #pragma unroll
            for (int i = 0; i < 4; i++) acc[np][i] = 0.f;

        #pragma unroll
        for (int kt = 0; kt < 13; kt++) {
            uint32_t ah[4], al[4], bhf[4], blf[4];
            int r = warpM * 16 + a_row;
            uint32_t offA = SP_OFF + r * 912 + (kt * 2 + a_ks) * 16;
            ldsm4(ah, sb + offA);
            ldsm4(al, sb + offA + 464);
            int nr = warpN * 16 + b_row;
            uint32_t offB = SVTH_OFF + nr * 432 + (kt * 2 + b_ks) * 16;
            ldsm4(bhf, sb + offB);
            ldsm4(blf, sb + offB + (SVTL_OFF - SVTH_OFF));
            #pragma unroll
            for (int np = 0; np < 2; np++) {
                float* d = acc[np];
                mma_bf16(d, ah, bhf[np * 2], bhf[np * 2 + 1]);
                mma_bf16(d, al, bhf[np * 2], bhf[np * 2 + 1]);
                mma_bf16(d, ah, blf[np * 2], blf[np * 2 + 1]);
            }
        }
        float* sO = sQs;
        int r0 = warpM * 16 + gid;
        #pragma unroll
        for (int np = 0; np < 2; np++) {
            int colb = warpN * 16 + np * 8 + 2 * tig;
            sO[r0 * 33 + colb]         = acc[np][0];
            sO[r0 * 33 + colb + 1]     = acc[np][1];
            sO[(r0+8) * 33 + colb]     = acc[np][2];
            sO[(r0+8) * 33 + colb + 1] = acc[np][3];
        }
    }
    __syncthreads();

    // ---- phase 4: add local-V contribution, split hi/lo, store ----
    #pragma unroll
    for (int i = 0; i < 4; i++) {
        int row = wid * 4 + i;
        int n = n0 + row;
        int rr = n / IMW, cc2 = n % IMW;
        float o = sQs[row * 33 + lane];
        #pragma unroll
        for (int l = 0; l < 9; l++) {
            int r2 = rr + l / 3 - 1, c3 = cc2 + l % 3 - 1;
            if (r2 >= 0 && r2 < IMH && c3 >= 0 && c3 < IMW) {
                int nb = r2 * IMW + c3;
                o += sLoc[row * 12 + l] *
                     kv[((size_t)(b * NN + nb)) * 512 + 256 + h * HD + lane];
            }
        }
        size_t oi = ((size_t)(b * NN) + n) * CC + h * HD + lane;
        __nv_bfloat16 hb = __float2bfloat16_rn(o);
        oh[oi] = hb;
        ol[oi] = __float2bfloat16_rn(o - __bfloat162float(hb));
    }
}

// -----------------------------------------------------------------------------
extern "C" void kernel_launch(void* const* d_in, const int* in_sizes, int n_in,
                              void* d_out, int out_size)
{
    const float* x      = (const float*)d_in[0];
    const int*   rpi    = (const int*)  d_in[3];
    const float* rct    = (const float*)d_in[4];
    const float* sls    = (const float*)d_in[5];
    const float* q_w    = (const float*)d_in[7];
    const float* q_b    = (const float*)d_in[8];
    const float* kv_w   = (const float*)d_in[9];
    const float* kv_b   = (const float*)d_in[10];
    const float* sr_w   = (const float*)d_in[11];
    const float* sr_b   = (const float*)d_in[12];
    const float* norm_g = (const float*)d_in[13];
    const float* norm_b = (const float*)d_in[14];
    const float* cpb1_w = (const float*)d_in[15];
    const float* cpb1_b = (const float*)d_in[16];
    const float* cpb2_w = (const float*)d_in[17];
    const float* cpb2_b = (const float*)d_in[18];
    const float* temp   = (const float*)d_in[19];
    const float* qe     = (const float*)d_in[20];
    const float* rpb    = (const float*)d_in[21];
    const float* ltok   = (const float*)d_in[22];
    const float* lbias  = (const float*)d_in[23];
    const float* proj_w = (const float*)d_in[24];
    const float* proj_b = (const float*)d_in[25];
    float* out = (float*)d_out;

    float *p_q, *p_kv, *p_xsr, *p_tab;
    __nv_bfloat16 *p_xh, *p_xl, *p_xph, *p_xpL, *p_ath, *p_atl;
    __nv_bfloat16 *p_kph, *p_kpl, *p_vth, *p_vtl;
    cudaGetSymbolAddress((void**)&p_q,   g_q);
    cudaGetSymbolAddress((void**)&p_kv,  g_kv);
    cudaGetSymbolAddress((void**)&p_xsr, g_xsr);
    cudaGetSymbolAddress((void**)&p_tab, g_tab);
    cudaGetSymbolAddress((void**)&p_xh,  g_xh);
    cudaGetSymbolAddress((void**)&p_xl,  g_xl);
    cudaGetSymbolAddress((void**)&p_xph, g_xph);
    cudaGetSymbolAddress((void**)&p_xpL, g_xpL);
    cudaGetSymbolAddress((void**)&p_ath, g_ath);
    cudaGetSymbolAddress((void**)&p_atl, g_atl);
    cudaGetSymbolAddress((void**)&p_kph, g_kph);
    cudaGetSymbolAddress((void**)&p_kpl, g_kpl);
    cudaGetSymbolAddress((void**)&p_vth, g_vth);
    cudaGetSymbolAddress((void**)&p_vtl, g_vtl);

    const int M = BZ * NN;  // 12544
    const int MP = BZ * PL; // 784

    cudaFuncSetAttribute(gemm_bf16, cudaFuncAttributeMaxDynamicSharedMemorySize, SMEM_GEMM);
    cudaFuncSetAttribute(gemm_qkvsr, cudaFuncAttributeMaxDynamicSharedMemorySize, SMEM_GEMM);
    cudaFuncSetAttribute(gemm_kvp_prep, cudaFuncAttributeMaxDynamicSharedMemorySize, SMEM_GEMM);
    cudaFuncSetAttribute(attn_mma, cudaFuncAttributeMaxDynamicSharedMemorySize, SMEM_ATTN);

    // 0: split x -> bf16 hi/lo
    split_kernel<<<(M * CC / 4 + 255) / 256, 256>>>(x, p_xh, p_xl, M * CC / 4);
    // 1: fused q + kv + sr GEMMs
    gemm_qkvsr<<<dim3(16, 98), 256, SMEM_GEMM>>>(
        p_xh, p_xl, q_w, q_b, kv_w, kv_b, sr_w, sr_b, p_q, p_kv, p_xsr, M);
    // 2: pool + layernorm (bf16 hi/lo out)
    pool_ln_kernel<<<BZ * PL, 256>>>(p_xsr, norm_g, norm_b, p_xph, p_xpL);
    // 3: CPB bias table
    tab_kernel<<<KTAB, 256>>>(rct, cpb1_w, cpb1_b, cpb2_w, cpb2_b, p_tab);
    // 4: pooled-kv GEMM with fused K/V^T bf16 prep
    gemm_kvp_prep<<<dim3(8, 7), 256, SMEM_GEMM>>>(
        p_xph, p_xpL, kv_w, kv_b, p_kph, p_kpl, p_vth, p_vtl, MP);
    // 5: MMA attention
    attn_mma<<<dim3(NN / 64, HH, BZ), 512, SMEM_ATTN>>>(
        p_q, qe, temp, sls, p_kv, p_kph, p_kpl, p_vth, p_vtl,
        p_tab, rpi, rpb, ltok, lbias, p_ath, p_atl);
    // 6: output projection
    gemm_bf16<<<dim3(4, 98), 256, SMEM_GEMM>>>(p_ath, p_atl, proj_w, proj_b, out, M, 256, 0);
}

// round 15
// speedup vs baseline: 2.7877x; 1.0953x over previous
#include <cuda_runtime.h>
#include <cuda_bf16.h>
#include <math.h>
#include <stdint.h>

// Problem constants
#define BZ 4
#define NN 3136
#define CC 256
#define HH 8
#define HD 32
#define PL 196
#define IMH 56
#define IMW 56
#define KTAB 2048

// ---------------- scratch (device globals; no allocation allowed) -------------
__device__ float g_q   [BZ * NN * CC];
__device__ float g_kv  [BZ * NN * 512];
__device__ float g_xsr [BZ * NN * CC];
__device__ float g_tabT[HH * KTAB];          // transposed CPB table [h][t]
// bf16 hi/lo split buffers
__device__ __nv_bfloat16 g_xh  [BZ * NN * CC];
__device__ __nv_bfloat16 g_xl  [BZ * NN * CC];
__device__ __nv_bfloat16 g_xph [BZ * PL * CC];
__device__ __nv_bfloat16 g_xpL [BZ * PL * CC];
__device__ __nv_bfloat16 g_ath [BZ * NN * CC];
__device__ __nv_bfloat16 g_atl [BZ * NN * CC];
// prepared pooled K (smem-layout) and V^T, bf16 hi/lo
__device__ __align__(16) __nv_bfloat16 g_kph [BZ * HH * 224 * 40];
__device__ __align__(16) __nv_bfloat16 g_kpl [BZ * HH * 224 * 40];
__device__ __align__(16) __nv_bfloat16 g_vth [BZ * HH * 32 * 216];
__device__ __align__(16) __nv_bfloat16 g_vtl [BZ * HH * 32 * 216];

// ---------------- helpers ------------------------------------------------------
__device__ __forceinline__ uint32_t smem_u32(const void* p) {
    uint32_t a;
    asm("{ .reg .u64 t; cvta.to.shared.u64 t, %1; cvt.u32.u64 %0, t; }"
        : "=r"(a) : "l"(p));
    return a;
}
__device__ __forceinline__ void split4(float4 v, uint2& hi, uint2& lo) {
    float h0 = __bfloat162float(__float2bfloat16_rn(v.x));
    float h1 = __bfloat162float(__float2bfloat16_rn(v.y));
    float h2 = __bfloat162float(__float2bfloat16_rn(v.z));
    float h3 = __bfloat162float(__float2bfloat16_rn(v.w));
    __nv_bfloat162 ph0 = __floats2bfloat162_rn(h0, h1);
    __nv_bfloat162 ph1 = __floats2bfloat162_rn(h2, h3);
    __nv_bfloat162 pl0 = __floats2bfloat162_rn(v.x - h0, v.y - h1);
    __nv_bfloat162 pl1 = __floats2bfloat162_rn(v.z - h2, v.w - h3);
    hi.x = *(uint32_t*)&ph0; hi.y = *(uint32_t*)&ph1;
    lo.x = *(uint32_t*)&pl0; lo.y = *(uint32_t*)&pl1;
}
__device__ __forceinline__ void ldsm4(uint32_t* r, uint32_t addr) {
    asm volatile("ldmatrix.sync.aligned.m8n8.x4.shared.b16 {%0,%1,%2,%3}, [%4];"
                 : "=r"(r[0]), "=r"(r[1]), "=r"(r[2]), "=r"(r[3]) : "r"(addr));
}
__device__ __forceinline__ void mma_bf16(float* d, const uint32_t* a,
                                         uint32_t b0, uint32_t b1) {
    asm volatile(
        "mma.sync.aligned.m16n8k16.row.col.f32.bf16.bf16.f32 "
        "{%0,%1,%2,%3},{%4,%5,%6,%7},{%8,%9},{%0,%1,%2,%3};"
        : "+f"(d[0]), "+f"(d[1]), "+f"(d[2]), "+f"(d[3])
        : "r"(a[0]), "r"(a[1]), "r"(a[2]), "r"(a[3]), "r"(b0), "r"(b1));
}

// ---------------- split: fp32 -> bf16 hi/lo -----------------------------------
__global__ __launch_bounds__(256) void split_kernel(
    const float* __restrict__ src, __nv_bfloat16* __restrict__ hi,
    __nv_bfloat16* __restrict__ lo, int n4)
{
    int i = blockIdx.x * 256 + threadIdx.x;
    if (i >= n4) return;
    float4 v = ((const float4*)src)[i];
    uint2 h, l;
    split4(v, h, l);
    ((uint2*)hi)[i] = h;
    ((uint2*)lo)[i] = l;
}

// ---------------- bf16 3-pass GEMM mainloop (device) ---------------------------
#define A_H 0
#define A_L 16384
#define B_H 32768
#define B_L 65536
#define SMEM_GEMM 98304

__device__ __forceinline__ void gemm_mainloop(
    char* smem, const __nv_bfloat16* __restrict__ Ah,
    const __nv_bfloat16* __restrict__ Al, const float* __restrict__ W,
    int M, int m0, int n0, float acc[2][4][4])
{
    const uint32_t sb = smem_u32(smem);
    const int tid = threadIdx.x;
    const int lane = tid & 31, wid = tid >> 5;
    const int warpM = wid & 3, warpN = wid >> 2;

    #pragma unroll
    for (int it = 0; it < 16; it++) {
        int idx = tid + it * 256;
        int n = idx >> 6, c4 = idx & 63;
        float4 wv = *(const float4*)&W[(size_t)(n0 + n) * 256 + c4 * 4];
        uint2 hi, lo;
        split4(wv, hi, lo);
        uint32_t off = n * 512 + ((c4 >> 4) << 7) +
                       (((((c4 >> 1) & 7) ^ (n & 7))) << 4) + ((c4 & 1) << 3);
        *(uint2*)(smem + B_H + off) = hi;
        *(uint2*)(smem + B_L + off) = lo;
    }

    #pragma unroll
    for (int mt = 0; mt < 2; mt++)
        #pragma unroll
        for (int nt = 0; nt < 4; nt++)
            #pragma unroll
            for (int i = 0; i < 4; i++) acc[mt][nt][i] = 0.f;

    const uint4 z16 = make_uint4(0, 0, 0, 0);
    uint4 pah[4], pal[4];
    #pragma unroll
    for (int it = 0; it < 4; it++) {
        int idx = tid + it * 256;
        int row = idx >> 3, seg = idx & 7;
        int gr = m0 + row;
        pah[it] = (gr < M) ? *(const uint4*)&Ah[(size_t)gr * 256 + seg * 8] : z16;
        pal[it] = (gr < M) ? *(const uint4*)&Al[(size_t)gr * 256 + seg * 8] : z16;
    }

    const int a_row_in = ((lane >> 3) & 1) * 8 + (lane & 7);
    const int a_kseg   = (lane >> 4) & 1;
    const int b_row_in = ((lane >> 4) & 1) * 8 + (lane & 7);
    const int b_kseg   = (lane >> 3) & 1;

    for (int ch = 0; ch < 4; ch++) {
        __syncthreads();
        #pragma unroll
        for (int it = 0; it < 4; it++) {
            int idx = tid + it * 256;
            int row = idx >> 3, seg = idx & 7;
            uint32_t off = row * 128 + ((seg ^ (row & 7)) << 4);
            *(uint4*)(smem + A_H + off) = pah[it];
            *(uint4*)(smem + A_L + off) = pal[it];
        }
        __syncthreads();

        if (ch < 3) {
            #pragma unroll
            for (int it = 0; it < 4; it++) {
                int idx = tid + it * 256;
                int row = idx >> 3, seg = idx & 7;
                int gr = m0 + row;
                size_t gb = (size_t)gr * 256 + (ch + 1) * 64 + seg * 8;
                pah[it] = (gr < M) ? *(const uint4*)&Ah[gb] : z16;
                pal[it] = (gr < M) ? *(const uint4*)&Al[gb] : z16;
            }
        }

        #pragma unroll
        for (int s = 0; s < 4; s++) {
            uint32_t ah[2][4], al[2][4], bh[2][4], bl[2][4];
            #pragma unroll
            for (int mt = 0; mt < 2; mt++) {
                int r = warpM * 32 + mt * 16 + a_row_in;
                uint32_t off = r * 128 + (((s * 2 + a_kseg) ^ (r & 7)) << 4);
                ldsm4(ah[mt], sb + A_H + off);
                ldsm4(al[mt], sb + A_L + off);
            }
            #pragma unroll
            for (int np = 0; np < 2; np++) {
                int n = warpN * 32 + np * 16 + b_row_in;
                uint32_t off = n * 512 + ch * 128 +
                               (((s * 2 + b_kseg) ^ (n & 7)) << 4);
                ldsm4(bh[np], sb + B_H + off);
                ldsm4(bl[np], sb + B_L + off);
            }
            #pragma unroll
            for (int mt = 0; mt < 2; mt++)
                #pragma unroll
                for (int np = 0; np < 2; np++) {
                    float* dl = acc[mt][2 * np];
                    float* dh = acc[mt][2 * np + 1];
                    mma_bf16(dl, ah[mt], bh[np][0], bh[np][1]);
                    mma_bf16(dl, al[mt], bh[np][0], bh[np][1]);
                    mma_bf16(dl, ah[mt], bl[np][0], bl[np][1]);
                    mma_bf16(dh, ah[mt], bh[np][2], bh[np][3]);
                    mma_bf16(dh, al[mt], bh[np][2], bh[np][3]);
                    mma_bf16(dh, ah[mt], bl[np][2], bl[np][3]);
                }
        }
    }
}

// standard epilogue GEMM body
__device__ __forceinline__ void gemm_body(
    char* smem, const __nv_bfloat16* __restrict__ Ah,
    const __nv_bfloat16* __restrict__ Al, const float* __restrict__ W,
    const float* __restrict__ bias, float* __restrict__ C,
    int M, int N, int act, int m0, int n0)
{
    float acc[2][4][4];
    gemm_mainloop(smem, Ah, Al, W, M, m0, n0, acc);

    const int lane = threadIdx.x & 31, wid = threadIdx.x >> 5;
    const int gid = lane >> 2, tig = lane & 3;
    const int warpM = wid & 3, warpN = wid >> 2;

    const bool donorm = (act == 2) && (n0 + warpN * 32) < 256;
    #pragma unroll
    for (int mt = 0; mt < 2; mt++) {
        int r0 = m0 + warpM * 32 + mt * 16 + gid;
        int r1 = r0 + 8;
        float v0[4][2], v1[4][2];
        #pragma unroll
        for (int nt = 0; nt < 4; nt++) {
            int cb = n0 + warpN * 32 + nt * 8 + 2 * tig;
            float b0 = bias[cb], b1 = bias[cb + 1];
            v0[nt][0] = acc[mt][nt][0] + b0; v0[nt][1] = acc[mt][nt][1] + b1;
            v1[nt][0] = acc[mt][nt][2] + b0; v1[nt][1] = acc[mt][nt][3] + b1;
        }
        if (act == 1) {
            #pragma unroll
            for (int nt = 0; nt < 4; nt++)
                #pragma unroll
                for (int i = 0; i < 2; i++) {
                    v0[nt][i] = 0.5f * v0[nt][i] *
                                (1.f + erff(v0[nt][i] * 0.70710678118654752f));
                    v1[nt][i] = 0.5f * v1[nt][i] *
                                (1.f + erff(v1[nt][i] * 0.70710678118654752f));
                }
        } else if (donorm) {
            float ss0 = 0.f, ss1 = 0.f;
            #pragma unroll
            for (int nt = 0; nt < 4; nt++) {
                ss0 += v0[nt][0] * v0[nt][0] + v0[nt][1] * v0[nt][1];
                ss1 += v1[nt][0] * v1[nt][0] + v1[nt][1] * v1[nt][1];
            }
            ss0 += __shfl_xor_sync(0xffffffffu, ss0, 1);
            ss0 += __shfl_xor_sync(0xffffffffu, ss0, 2);
            ss1 += __shfl_xor_sync(0xffffffffu, ss1, 1);
            ss1 += __shfl_xor_sync(0xffffffffu, ss1, 2);
            float inv0 = 1.f / fmaxf(sqrtf(ss0), 1e-12f);
            float inv1 = 1.f / fmaxf(sqrtf(ss1), 1e-12f);
            #pragma unroll
            for (int nt = 0; nt < 4; nt++) {
                v0[nt][0] *= inv0; v0[nt][1] *= inv0;
                v1[nt][0] *= inv1; v1[nt][1] *= inv1;
            }
        }
        #pragma unroll
        for (int nt = 0; nt < 4; nt++) {
            int cb = n0 + warpN * 32 + nt * 8 + 2 * tig;
            if (r0 < M)
                *(float2*)&C[(size_t)r0 * N + cb] = make_float2(v0[nt][0], v0[nt][1]);
            if (r1 < M)
                *(float2*)&C[(size_t)r1 * N + cb] = make_float2(v1[nt][0], v1[nt][1]);
        }
    }
}

__global__ __launch_bounds__(256) void gemm_bf16(
    const __nv_bfloat16* __restrict__ Ah, const __nv_bfloat16* __restrict__ Al,
    const float* __restrict__ W, const float* __restrict__ bias,
    float* __restrict__ C, int M, int N, int act)
{
    extern __shared__ __align__(1024) char smem[];
    gemm_body(smem, Ah, Al, W, bias, C, M, N, act,
              blockIdx.y * 128, blockIdx.x * 64);
}

// fused q/kv/sr GEMM
__global__ __launch_bounds__(256) void gemm_qkvsr(
    const __nv_bfloat16* __restrict__ Ah, const __nv_bfloat16* __restrict__ Al,
    const float* __restrict__ q_w, const float* __restrict__ q_b,
    const float* __restrict__ kv_w, const float* __restrict__ kv_b,
    const float* __restrict__ sr_w, const float* __restrict__ sr_b,
    float* __restrict__ Cq, float* __restrict__ Ckv, float* __restrict__ Cxsr,
    int M)
{
    extern __shared__ __align__(1024) char smem[];
    const int bx = blockIdx.x;
    const float *W, *bias;
    float* C;
    int N, n0, act;
    if (bx < 4)       { W = q_w;  bias = q_b;  C = Cq;   N = 256; n0 = bx * 64;        act = 0; }
    else if (bx < 12) { W = kv_w; bias = kv_b; C = Ckv;  N = 512; n0 = (bx - 4) * 64;  act = 2; }
    else              { W = sr_w; bias = sr_b; C = Cxsr; N = 256; n0 = (bx - 12) * 64; act = 1; }
    gemm_body(smem, Ah, Al, W, bias, C, M, N, act, blockIdx.y * 128, n0);
}

// pooled-kv GEMM with fused prep
__global__ __launch_bounds__(256) void gemm_kvp_prep(
    const __nv_bfloat16* __restrict__ Ah, const __nv_bfloat16* __restrict__ Al,
    const float* __restrict__ kv_w, const float* __restrict__ kv_b,
    __nv_bfloat16* __restrict__ kph, __nv_bfloat16* __restrict__ kpl,
    __nv_bfloat16* __restrict__ vth, __nv_bfloat16* __restrict__ vtl,
    int M)
{
    extern __shared__ __align__(1024) char smem[];
    const int m0 = blockIdx.y * 128, n0 = blockIdx.x * 64;
    float acc[2][4][4];
    gemm_mainloop(smem, Ah, Al, kv_w, M, m0, n0, acc);

    const int lane = threadIdx.x & 31, wid = threadIdx.x >> 5;
    const int gid = lane >> 2, tig = lane & 3;
    const int warpM = wid & 3, warpN = wid >> 2;

    const int colbase = n0 + warpN * 32;
    const bool isK = colbase < 256;
    const int h = (colbase & 255) >> 5;

    #pragma unroll
    for (int mt = 0; mt < 2; mt++) {
        int r0 = m0 + warpM * 32 + mt * 16 + gid;
        int r1 = r0 + 8;
        float v0[4][2], v1[4][2];
        #pragma unroll
        for (int nt = 0; nt < 4; nt++) {
            int cb = colbase + nt * 8 + 2 * tig;
            float b0 = kv_b[cb], b1 = kv_b[cb + 1];
            v0[nt][0] = acc[mt][nt][0] + b0; v0[nt][1] = acc[mt][nt][1] + b1;
            v1[nt][0] = acc[mt][nt][2] + b0; v1[nt][1] = acc[mt][nt][3] + b1;
        }
        if (isK) {
            float ss0 = 0.f, ss1 = 0.f;
            #pragma unroll
            for (int nt = 0; nt < 4; nt++) {
                ss0 += v0[nt][0] * v0[nt][0] + v0[nt][1] * v0[nt][1];
                ss1 += v1[nt][0] * v1[nt][0] + v1[nt][1] * v1[nt][1];
            }
            ss0 += __shfl_xor_sync(0xffffffffu, ss0, 1);
            ss0 += __shfl_xor_sync(0xffffffffu, ss0, 2);
            ss1 += __shfl_xor_sync(0xffffffffu, ss1, 1);
            ss1 += __shfl_xor_sync(0xffffffffu, ss1, 2);
            float inv0 = 1.f / fmaxf(sqrtf(ss0), 1e-12f);
            float inv1 = 1.f / fmaxf(sqrtf(ss1), 1e-12f);
            #pragma unroll
            for (int nt = 0; nt < 4; nt++) {
                v0[nt][0] *= inv0; v0[nt][1] *= inv0;
                v1[nt][0] *= inv1; v1[nt][1] *= inv1;
            }
        }
        #pragma unroll
        for (int rsel = 0; rsel < 2; rsel++) {
            int r = rsel ? r1 : r0;
            if (r >= M) continue;
            int bb = r / PL, p = r - bb * PL;
            int bh = bb * HH + h;
            float (*vv)[2] = rsel ? v1 : v0;
            if (isK) {
                size_t base = (size_t)(bh * 224 + p) * 40;
                #pragma unroll
                for (int nt = 0; nt < 4; nt++) {
                    int d0 = nt * 8 + 2 * tig;
                    float a0 = vv[nt][0], a1 = vv[nt][1];
                    __nv_bfloat162 hb = __floats2bfloat162_rn(a0, a1);
                    float h0 = __bfloat162float(__low2bfloat16(hb));
                    float h1 = __bfloat162float(__high2bfloat16(hb));
                    __nv_bfloat162 lb = __floats2bfloat162_rn(a0 - h0, a1 - h1);
                    *(__nv_bfloat162*)&kph[base + d0] = hb;
                    *(__nv_bfloat162*)&kpl[base + d0] = lb;
                }
            } else {
                #pragma unroll
                for (int nt = 0; nt < 4; nt++)
                    #pragma unroll
                    for (int i = 0; i < 2; i++) {
                        int d = nt * 8 + 2 * tig + i;
                        float a = vv[nt][i];
                        __nv_bfloat16 hb = __float2bfloat16_rn(a);
                        size_t adr = (size_t)(bh * 32 + d) * 216 + p;
                        vth[adr] = hb;
                        vtl[adr] = __float2bfloat16_rn(a - __bfloat162float(hb));
                    }
            }
        }
    }
}

// ---------------- 4x4 average pool + layernorm (bf16 hi/lo out) ----------------
__global__ __launch_bounds__(256) void pool_ln_kernel(
    const float* __restrict__ xsr, const float* __restrict__ gam,
    const float* __restrict__ bet, __nv_bfloat16* __restrict__ xph,
    __nv_bfloat16* __restrict__ xpl)
{
    int bp = blockIdx.x;
    int b = bp / PL, p = bp % PL;
    int ph = p / 14, pw = p % 14;
    int c = threadIdx.x;

    float s = 0.f;
    #pragma unroll
    for (int i = 0; i < 4; i++)
        #pragma unroll
        for (int j = 0; j < 4; j++) {
            int n = (ph * 4 + i) * IMW + pw * 4 + j;
            s += xsr[((size_t)b * NN + n) * CC + c];
        }
    s *= (1.f / 16.f);

    __shared__ float r1[256], r2[256];
    r1[c] = s;
    r2[c] = s * s;
    __syncthreads();
    for (int st = 128; st > 0; st >>= 1) {
        if (c < st) { r1[c] += r1[c + st]; r2[c] += r2[c + st]; }
        __syncthreads();
    }
    float mean = r1[0] * (1.f / 256.f);
    float var  = r2[0] * (1.f / 256.f) - mean * mean;
    float invs = rsqrtf(var + 1e-5f);
    float val = (s - mean) * invs * gam[c] + bet[c];
    __nv_bfloat16 hb = __float2bfloat16_rn(val);
    xph[(size_t)bp * CC + c] = hb;
    xpl[(size_t)bp * CC + c] = __float2bfloat16_rn(val - __bfloat162float(hb));
}

// ---------------- CPB table: 4 t per block, transposed output ------------------
__global__ __launch_bounds__(256) void tab_kernel(
    const float* __restrict__ rct, const float* __restrict__ w1,
    const float* __restrict__ b1, const float* __restrict__ w2,
    const float* __restrict__ b2, float* __restrict__ tabT)
{
    __shared__ float sh[4 * 512];
    const int tid = threadIdx.x;
    const int t0 = blockIdx.x * 4;

    #pragma unroll
    for (int u = 0; u < 8; u++) {
        int idx = tid + u * 256;
        int tl = idx >> 9, j = idx & 511;
        int t = t0 + tl;
        sh[idx] = fmaxf(0.f, rct[t * 2] * w1[j * 2] + rct[t * 2 + 1] * w1[j * 2 + 1] + b1[j]);
    }
    __syncthreads();

    const int wid = tid >> 5, lane = tid & 31;  // warp = head
    float w2r[16];
    #pragma unroll
    for (int i = 0; i < 16; i++) w2r[i] = w2[wid * 512 + lane + i * 32];
    float bb = b2[wid];
    #pragma unroll
    for (int tl = 0; tl < 4; tl++) {
        float s = 0.f;
        #pragma unroll
        for (int i = 0; i < 16; i++) s += sh[tl * 512 + lane + i * 32] * w2r[i];
        #pragma unroll
        for (int o = 16; o > 0; o >>= 1) s += __shfl_xor_sync(0xffffffffu, s, o);
        if (lane == 0) tabT[wid * KTAB + t0 + tl] = s + bb;
    }
}

// ---------------- MMA attention (512 threads) ----------------------------------
#define SP_OFF   0        // logits fp32 [64][228]; later probs bf16 hi@0, lo@+464B
#define SKH_OFF  58368    // K_pool hi bf16 [224][40]
#define SKL_OFF  76288
#define SVTH_OFF 94208    // V^T hi bf16 [32][216]
#define SVTL_OFF 108032
#define SQH_OFF  121856   // q_scaled hi bf16 [64][40]
#define SQL_OFF  126976
#define SQS_OFF  132096   // q_scaled fp32 [64][33] (reused as output accum)
#define SQN_OFF  140544   // q_norm fp32 [64][33]
#define SLOC_OFF 148992   // local weights [64][12]
#define SLOC2_OFF 152064  // raw local logits [64][12]
#define SLT_OFF  155136   // ltok head slice [32*9]
#define SRB_OFF  156288   // rpb[9] @0, lbias[9] @16
#define SKV_OFF  156416   // local K (then V) window [280][36] fp32
#define STAB_OFF 196736   // CPB column for this head [2048] fp32
#define SMEM_ATTN 204928

__global__ __launch_bounds__(512) void attn_mma(
    const float* __restrict__ q, const float* __restrict__ qe,
    const float* __restrict__ temp, const float* __restrict__ sls,
    const float* __restrict__ kv,
    const __nv_bfloat16* __restrict__ kph, const __nv_bfloat16* __restrict__ kpl,
    const __nv_bfloat16* __restrict__ vth, const __nv_bfloat16* __restrict__ vtl,
    const float* __restrict__ tabT, const int* __restrict__ rpi,
    const float* __restrict__ rpb, const float* __restrict__ ltok,
    const float* __restrict__ lbias,
    __nv_bfloat16* __restrict__ oh, __nv_bfloat16* __restrict__ ol)
{
    extern __shared__ __align__(1024) char smem[];
    const uint32_t sb = smem_u32(smem);
    float* sP    = (float*)(smem + SP_OFF);
    float* sQs   = (float*)(smem + SQS_OFF);
    float* sQn   = (float*)(smem + SQN_OFF);
    float* sLoc  = (float*)(smem + SLOC_OFF);
    float* sLoc2 = (float*)(smem + SLOC2_OFF);
    float* sLt   = (float*)(smem + SLT_OFF);
    float* sRb   = (float*)(smem + SRB_OFF);
    float* sKV   = (float*)(smem + SKV_OFF);
    float* sTab  = (float*)(smem + STAB_OFF);

    const int b = blockIdx.z, h = blockIdx.y;
    const int n0 = blockIdx.x * 64;
    const int tid = threadIdx.x, lane = tid & 31, wid = tid >> 5;
    const int gid = lane >> 2, tig = lane & 3;
    const int bh = b * HH + h;
    const int rstart = n0 / IMW - 1;

    // ---- staging: prepared K / V^T copies ----
    {
        const uint4* gkh = (const uint4*)(kph + (size_t)bh * 224 * 40);
        const uint4* gkl = (const uint4*)(kpl + (size_t)bh * 224 * 40);
        uint4* skh = (uint4*)(smem + SKH_OFF);
        uint4* skl = (uint4*)(smem + SKL_OFF);
        for (int i = tid; i < 1120; i += 512) { skh[i] = gkh[i]; skl[i] = gkl[i]; }
        const uint4* gvh = (const uint4*)(vth + (size_t)bh * 32 * 216);
        const uint4* gvl = (const uint4*)(vtl + (size_t)bh * 32 * 216);
        uint4* svh = (uint4*)(smem + SVTH_OFF);
        uint4* svl = (uint4*)(smem + SVTL_OFF);
        for (int i = tid; i < 864; i += 512) { svh[i] = gvh[i]; svl[i] = gvl[i]; }
        for (int i = tid; i < 288; i += 512) sLt[i] = ltok[h * 288 + i];
        if (tid < 9) sRb[tid] = rpb[h * 9 + tid];
        else if (tid >= 32 && tid < 41) sRb[16 + tid - 32] = lbias[h * 9 + tid - 32];
        // CPB column for this head (coalesced from transposed table)
        for (int i = tid; i < KTAB; i += 512) sTab[i] = tabT[h * KTAB + i];
    }
    // zero pads: K rows 196..223, V^T cols 196..207
    {
        const uint4 z = make_uint4(0, 0, 0, 0);
        for (int i = tid; i < 112; i += 512) {
            int row = 196 + (i >> 2), seg = i & 3;
            *(uint4*)(smem + SKH_OFF + row * 80 + seg * 16) = z;
            *(uint4*)(smem + SKL_OFF + row * 80 + seg * 16) = z;
        }
        for (int i = tid; i < 192; i += 512) {
            int d = i / 6, k = i % 6;
            *(uint32_t*)(smem + SVTH_OFF + d * 432 + 392 + k * 4) = 0;
            *(uint32_t*)(smem + SVTL_OFF + d * 432 + 392 + k * 4) = 0;
        }
    }
    // ---- stage local K window: 5 image rows x 56 cols x 32 d, stride 36 ----
    for (int i = tid; i < 280 * 8; i += 512) {
        int pos = i >> 3, seg = i & 7;
        int rr2 = rstart + pos / IMW;
        float4 v = make_float4(0.f, 0.f, 0.f, 0.f);
        if (rr2 >= 0 && rr2 < IMH) {
            int nb = rr2 * IMW + pos % IMW;
            v = *(const float4*)&kv[((size_t)(b * NN + nb)) * 512 + h * HD + seg * 4];
        }
        *(float4*)&sKV[pos * 36 + seg * 4] = v;
    }
    // ---- stage q: norm + scale ----
    {
        float sp = log1pf(expf(temp[h]));
        float qev = qe[h * HD + lane];
        #pragma unroll
        for (int i = 0; i < 4; i++) {
            int row = wid * 4 + i;
            int n = n0 + row;
            float val = q[((size_t)(b * NN + n)) * CC + h * HD + lane];
            float ss = val * val;
            #pragma unroll
            for (int o = 16; o > 0; o >>= 1) ss += __shfl_xor_sync(0xffffffffu, ss, o);
            float inv = 1.f / fmaxf(sqrtf(ss), 1e-12f);
            float qnv = val * inv;
            float qsv = (qnv + qev) * sp * sls[n];
            sQs[row * 33 + lane] = qsv;
            sQn[row * 33 + lane] = qnv;
            __nv_bfloat16 hb = __float2bfloat16_rn(qsv);
            *(__nv_bfloat16*)(smem + SQH_OFF + row * 80 + lane * 2) = hb;
            *(__nv_bfloat16*)(smem + SQL_OFF + row * 80 + lane * 2) =
                __float2bfloat16_rn(qsv - __bfloat162float(hb));
        }
    }
    __syncthreads();

    const int warpM = wid & 3, warpN = (wid >> 2) & 1;
    const int a_row = ((lane >> 3) & 1) * 8 + (lane & 7);
    const int a_ks  = (lane >> 4) & 1;
    const int b_row = ((lane >> 4) & 1) * 8 + (lane & 7);
    const int b_ks  = (lane >> 3) & 1;

    // ---- phase 1: pooled logits = Qs @ K^T (warps 0-7) ----
    if (wid < 8) {
        float acc[7][2][4];
        #pragma unroll
        for (int nt = 0; nt < 7; nt++)
            #pragma unroll
            for (int np = 0; np < 2; np++)
                #pragma unroll
                for (int i = 0; i < 4; i++) acc[nt][np][i] = 0.f;

        #pragma unroll
        for (int s = 0; s < 2; s++) {
            uint32_t ah[4], al[4];
            {
                int r = warpM * 16 + a_row;
                uint32_t off = SQH_OFF + r * 80 + (s * 2 + a_ks) * 16;
                ldsm4(ah, sb + off);
                ldsm4(al, sb + off + (SQL_OFF - SQH_OFF));
            }
            #pragma unroll
            for (int nt = 0; nt < 7; nt++) {
                int nr = warpN * 112 + nt * 16 + b_row;
                uint32_t off = SKH_OFF + nr * 80 + (s * 2 + b_ks) * 16;
                uint32_t bhf[4], blf[4];
                ldsm4(bhf, sb + off);
                ldsm4(blf, sb + off + (SKL_OFF - SKH_OFF));
                #pragma unroll
                for (int np = 0; np < 2; np++) {
                    float* d = acc[nt][np];
                    mma_bf16(d, ah, bhf[np * 2], bhf[np * 2 + 1]);
                    mma_bf16(d, al, bhf[np * 2], bhf[np * 2 + 1]);
                    mma_bf16(d, ah, blf[np * 2], blf[np * 2 + 1]);
                }
            }
        }
        int r0 = warpM * 16 + gid;
        #pragma unroll
        for (int nt = 0; nt < 7; nt++)
            #pragma unroll
            for (int np = 0; np < 2; np++) {
                int colb = warpN * 112 + nt * 16 + np * 8 + 2 * tig;
                *(float2*)&sP[r0 * 228 + colb] =
                    make_float2(acc[nt][np][0], acc[nt][np][1]);
                *(float2*)&sP[(r0 + 8) * 228 + colb] =
                    make_float2(acc[nt][np][2], acc[nt][np][3]);
            }
    }
    __syncthreads();

    // ---- phase 1.5a: CPB bias gather from smem ----
    #pragma unroll 4
    for (int i = tid; i < 64 * PL; i += 512) {
        int row = i / PL;
        int j = i - row * PL;
        sP[row * 228 + j] += sTab[rpi[(size_t)(n0 + row) * PL + j]];
    }
    // ---- phase 1.5b: local logits + learnable-token dots (K from smem) ----
    for (int t5 = tid; t5 < 64 * 9; t5 += 512) {
        int row = t5 / 9, l = t5 - row * 9;
        int n = n0 + row;
        int rr = n / IMW, cc2 = n % IMW;
        int r2 = rr + l / 3 - 1, c3 = cc2 + l % 3 - 1;
        float aloc = -3.4e38f;
        const float* Qs = &sQs[row * 33];
        if (r2 >= 0 && r2 < IMH && c3 >= 0 && c3 < IMW) {
            const float* kr = &sKV[((r2 - rstart) * IMW + c3) * 36];
            float s2 = 0.f;
            #pragma unroll
            for (int d4 = 0; d4 < 8; d4++) {
                float4 t = *(const float4*)&kr[d4 * 4];
                s2 += Qs[d4*4+0]*t.x + Qs[d4*4+1]*t.y + Qs[d4*4+2]*t.z + Qs[d4*4+3]*t.w;
            }
            aloc = s2 + sRb[l];
        }
        sLoc2[row * 12 + l] = aloc;
        const float* Qn = &sQn[row * 33];
        float t2 = 0.f;
        #pragma unroll
        for (int d = 0; d < 32; d++) t2 += Qn[d] * sLt[d * 9 + l];
        sLoc[row * 12 + l] = t2 + sRb[16 + l];
    }
    __syncthreads();

    // ---- stage local V window (overwrites K window) ----
    for (int i = tid; i < 280 * 8; i += 512) {
        int pos = i >> 3, seg = i & 7;
        int rr2 = rstart + pos / IMW;
        float4 v = make_float4(0.f, 0.f, 0.f, 0.f);
        if (rr2 >= 0 && rr2 < IMH) {
            int nb = rr2 * IMW + pos % IMW;
            v = *(const float4*)&kv[((size_t)(b * NN + nb)) * 512 + 256 + h * HD + seg * 4];
        }
        *(float4*)&sKV[pos * 36 + seg * 4] = v;
    }

    // ---- phase 2: softmax per row (16 warps x 4 rows) ----
    #pragma unroll
    for (int i = 0; i < 4; i++) {
        int row = wid * 4 + i;
        float* Pr = &sP[row * 228];

        float e[7];
        float mx = -3.4e38f;
        #pragma unroll
        for (int t = 0; t < 7; t++) {
            int j = lane + 32 * t;
            if (j < PL) { e[t] = Pr[j]; mx = fmaxf(mx, e[t]); }
            else e[t] = -3.4e38f;
        }
        float aloc = (lane < 9) ? sLoc2[row * 12 + lane] : -3.4e38f;
        mx = fmaxf(mx, aloc);
        #pragma unroll
        for (int o = 16; o > 0; o >>= 1)
            mx = fmaxf(mx, __shfl_xor_sync(0xffffffffu, mx, o));

        float sum = 0.f;
        #pragma unroll
        for (int t = 0; t < 7; t++) {
            int j = lane + 32 * t;
            if (j < PL) { e[t] = __expf(e[t] - mx); sum += e[t]; }
        }
        float el = 0.f;
        if (lane < 9) { el = __expf(aloc - mx); sum += el; }
        #pragma unroll
        for (int o = 16; o > 0; o >>= 1) sum += __shfl_xor_sync(0xffffffffu, sum, o);
        float inv = 1.f / sum;

        __nv_bfloat16* Ph = (__nv_bfloat16*)Pr;
        __nv_bfloat16* Pl2 = Ph + 232;
        #pragma unroll
        for (int t = 0; t < 7; t++) {
            int j = lane + 32 * t;
            if (j < PL) {
                float p = e[t] * inv;
                __nv_bfloat16 hb = __float2bfloat16_rn(p);
                Ph[j] = hb;
                Pl2[j] = __float2bfloat16_rn(p - __bfloat162float(hb));
            }
        }
        if (lane < 12) {
            Ph[PL + lane] = __float2bfloat16(0.f);
            Pl2[PL + lane] = __float2bfloat16(0.f);
        }
        if (lane < 9) sLoc[row * 12 + lane] += el * inv;
    }
    __syncthreads();

    // ---- phase 3: pooled output = P @ V (warps 0-7) ----
    if (wid < 8) {
        float acc[2][4];
        #pragma unroll
        for (int np = 0; np < 2; np++)
            #pragma unroll
            for (int i = 0; i < 4; i++) acc[np][i] = 0.f;

        #pragma unroll
        for (int kt = 0; kt < 13; kt++) {
            uint32_t ah[4], al[4], bhf[4], blf[4];
            int r = warpM * 16 + a_row;
            uint32_t offA = SP_OFF + r * 912 + (kt * 2 + a_ks) * 16;
            ldsm4(ah, sb + offA);
            ldsm4(al, sb + offA + 464);
            int nr = warpN * 16 + b_row;
            uint32_t offB = SVTH_OFF + nr * 432 + (kt * 2 + b_ks) * 16;
            ldsm4(bhf, sb + offB);
            ldsm4(blf, sb + offB + (SVTL_OFF - SVTH_OFF));
            #pragma unroll
            for (int np = 0; np < 2; np++) {
                float* d = acc[np];
                mma_bf16(d, ah, bhf[np * 2], bhf[np * 2 + 1]);
                mma_bf16(d, al, bhf[np * 2], bhf[np * 2 + 1]);
                mma_bf16(d, ah, blf[np * 2], blf[np * 2 + 1]);
            }
        }
        float* sO = sQs;
        int r0 = warpM * 16 + gid;
        #pragma unroll
        for (int np = 0; np < 2; np++) {
            int colb = warpN * 16 + np * 8 + 2 * tig;
            sO[r0 * 33 + colb]         = acc[np][0];
            sO[r0 * 33 + colb + 1]     = acc[np][1];
            sO[(r0+8) * 33 + colb]     = acc[np][2];
            sO[(r0+8) * 33 + colb + 1] = acc[np][3];
        }
    }
    __syncthreads();

    // ---- phase 4: add local-V (from smem), split hi/lo, store ----
    #pragma unroll
    for (int i = 0; i < 4; i++) {
        int row = wid * 4 + i;
        int n = n0 + row;
        int rr = n / IMW, cc2 = n % IMW;
        float o = sQs[row * 33 + lane];
        #pragma unroll
        for (int l = 0; l < 9; l++) {
            int r2 = rr + l / 3 - 1, c3 = cc2 + l % 3 - 1;
            if (r2 >= 0 && r2 < IMH && c3 >= 0 && c3 < IMW) {
                o += sLoc[row * 12 + l] *
                     sKV[((r2 - rstart) * IMW + c3) * 36 + lane];
            }
        }
        size_t oi = ((size_t)(b * NN) + n) * CC + h * HD + lane;
        __nv_bfloat16 hb = __float2bfloat16_rn(o);
        oh[oi] = hb;
        ol[oi] = __float2bfloat16_rn(o - __bfloat162float(hb));
    }
}

// -----------------------------------------------------------------------------
extern "C" void kernel_launch(void* const* d_in, const int* in_sizes, int n_in,
                              void* d_out, int out_size)
{
    const float* x      = (const float*)d_in[0];
    const int*   rpi    = (const int*)  d_in[3];
    const float* rct    = (const float*)d_in[4];
    const float* sls    = (const float*)d_in[5];
    const float* q_w    = (const float*)d_in[7];
    const float* q_b    = (const float*)d_in[8];
    const float* kv_w   = (const float*)d_in[9];
    const float* kv_b   = (const float*)d_in[10];
    const float* sr_w   = (const float*)d_in[11];
    const float* sr_b   = (const float*)d_in[12];
    const float* norm_g = (const float*)d_in[13];
    const float* norm_b = (const float*)d_in[14];
    const float* cpb1_w = (const float*)d_in[15];
    const float* cpb1_b = (const float*)d_in[16];
    const float* cpb2_w = (const float*)d_in[17];
    const float* cpb2_b = (const float*)d_in[18];
    const float* temp   = (const float*)d_in[19];
    const float* qe     = (const float*)d_in[20];
    const float* rpb    = (const float*)d_in[21];
    const float* ltok   = (const float*)d_in[22];
    const float* lbias  = (const float*)d_in[23];
    const float* proj_w = (const float*)d_in[24];
    const float* proj_b = (const float*)d_in[25];
    float* out = (float*)d_out;

    float *p_q, *p_kv, *p_xsr, *p_tabT;
    __nv_bfloat16 *p_xh, *p_xl, *p_xph, *p_xpL, *p_ath, *p_atl;
    __nv_bfloat16 *p_kph, *p_kpl, *p_vth, *p_vtl;
    cudaGetSymbolAddress((void**)&p_q,    g_q);
    cudaGetSymbolAddress((void**)&p_kv,   g_kv);
    cudaGetSymbolAddress((void**)&p_xsr,  g_xsr);
    cudaGetSymbolAddress((void**)&p_tabT, g_tabT);
    cudaGetSymbolAddress((void**)&p_xh,   g_xh);
    cudaGetSymbolAddress((void**)&p_xl,   g_xl);
    cudaGetSymbolAddress((void**)&p_xph,  g_xph);
    cudaGetSymbolAddress((void**)&p_xpL,  g_xpL);
    cudaGetSymbolAddress((void**)&p_ath,  g_ath);
    cudaGetSymbolAddress((void**)&p_atl,  g_atl);
    cudaGetSymbolAddress((void**)&p_kph,  g_kph);
    cudaGetSymbolAddress((void**)&p_kpl,  g_kpl);
    cudaGetSymbolAddress((void**)&p_vth,  g_vth);
    cudaGetSymbolAddress((void**)&p_vtl,  g_vtl);

    const int M = BZ * NN;  // 12544
    const int MP = BZ * PL; // 784

    cudaFuncSetAttribute(gemm_bf16, cudaFuncAttributeMaxDynamicSharedMemorySize, SMEM_GEMM);
    cudaFuncSetAttribute(gemm_qkvsr, cudaFuncAttributeMaxDynamicSharedMemorySize, SMEM_GEMM);
    cudaFuncSetAttribute(gemm_kvp_prep, cudaFuncAttributeMaxDynamicSharedMemorySize, SMEM_GEMM);
    cudaFuncSetAttribute(attn_mma, cudaFuncAttributeMaxDynamicSharedMemorySize, SMEM_ATTN);

    // 0: split x -> bf16 hi/lo
    split_kernel<<<(M * CC / 4 + 255) / 256, 256>>>(x, p_xh, p_xl, M * CC / 4);
    // 1: fused q + kv + sr GEMMs
    gemm_qkvsr<<<dim3(16, 98), 256, SMEM_GEMM>>>(
        p_xh, p_xl, q_w, q_b, kv_w, kv_b, sr_w, sr_b, p_q, p_kv, p_xsr, M);
    // 2: pool + layernorm (bf16 hi/lo out)
    pool_ln_kernel<<<BZ * PL, 256>>>(p_xsr, norm_g, norm_b, p_xph, p_xpL);
    // 3: CPB bias table (transposed out)
    tab_kernel<<<KTAB / 4, 256>>>(rct, cpb1_w, cpb1_b, cpb2_w, cpb2_b, p_tabT);
    // 4: pooled-kv GEMM with fused K/V^T bf16 prep
    gemm_kvp_prep<<<dim3(8, 7), 256, SMEM_GEMM>>>(
        p_xph, p_xpL, kv_w, kv_b, p_kph, p_kpl, p_vth, p_vtl, MP);
    // 5: MMA attention
    attn_mma<<<dim3(NN / 64, HH, BZ), 512, SMEM_ATTN>>>(
        p_q, qe, temp, sls, p_kv, p_kph, p_kpl, p_vth, p_vtl,
        p_tabT, rpi, rpb, ltok, lbias, p_ath, p_atl);
    // 6: output projection
    gemm_bf16<<<dim3(4, 98), 256, SMEM_GEMM>>>(p_ath, p_atl, proj_w, proj_b, out, M, 256, 0);
}